// round 1
// baseline (speedup 1.0000x reference)
#include <cuda_runtime.h>

#define NB 8
#define NC 64
#define NHD 8
#define SH 128
#define SW 128
#define HW (SH*SW)
#define KT 21

// ---------------- scratch (device globals; no allocations) ----------------
__device__ float g_Wh[KT*NC*NC];      // combined+BN-folded weights, layout [t][co][ci]
__device__ float g_Ww[KT*NC*NC];
__device__ float g_rbh[NC*SH];        // per-(cout,row) bias for h-conv
__device__ float g_rbw[NC*SW];        // per-(cout,col) bias for w-conv
__device__ float g_sch[NB*NC*HW];
__device__ float g_scw[NB*NC*HW];
__device__ float g_hqkv[NB*192*HW];
__device__ float g_wqkv[NB*192*HW];
__device__ float g_Pw[NB*NHD*SW*SW];
__device__ float g_Ph[NB*NHD*SW*SW];
__device__ float g_wo[NB*NC*HW];
__device__ float g_ho[NB*NC*HW];

// ---------------- prep: combine 3 strip kernels, fold BN, row biases ------
__global__ void prep_kernel(int side,
    const float* __restrict__ w7,  const float* __restrict__ b7,
    const float* __restrict__ w11, const float* __restrict__ b11,
    const float* __restrict__ w21, const float* __restrict__ b21,
    const float* __restrict__ bng, const float* __restrict__ bnb,
    const float* __restrict__ bnm, const float* __restrict__ bnv)
{
    float* Wout  = side ? g_Ww  : g_Wh;
    float* rbout = side ? g_rbw : g_rbh;
    int co = blockIdx.x;
    int tid = threadIdx.x;
    __shared__ float Wraw[NC*KT];
    __shared__ float Pfx[NC*(KT+1)];

    for (int idx = tid; idx < NC*KT; idx += blockDim.x){
        int ci = idx / KT, t = idx % KT;
        float v = w21[(co*NC+ci)*21 + t];
        if (t >= 5 && t < 16) v += w11[(co*NC+ci)*11 + (t-5)];
        if (t >= 7 && t < 14) v += w7 [(co*NC+ci)*7  + (t-7)];
        Wraw[idx] = v;
        float a = bng[ci] * rsqrtf(bnv[ci] + 1e-5f);
        Wout[t*NC*NC + co*NC + ci] = v * a;
    }
    __syncthreads();
    if (tid < NC){
        int ci = tid;
        float a = bng[ci] * rsqrtf(bnv[ci] + 1e-5f);
        float c = bnb[ci] - bnm[ci] * a;
        float s = 0.f;
        Pfx[ci*(KT+1)] = 0.f;
        for (int t = 0; t < KT; t++){
            s += Wraw[ci*KT + t] * c;
            Pfx[ci*(KT+1) + t + 1] = s;
        }
    }
    __syncthreads();
    float cb = b7[co] + b11[co] + b21[co];
    for (int h = tid; h < SH; h += blockDim.x){
        int t0 = 10 - h;  if (t0 < 0) t0 = 0;
        int t1 = 137 - h; if (t1 > KT-1) t1 = KT-1;
        float s = cb;
        for (int ci = 0; ci < NC; ci++)
            s += Pfx[ci*(KT+1) + t1 + 1] - Pfx[ci*(KT+1) + t0];
        rbout[co*SH + h] = s;
    }
}

// ---------------- 21-tap conv along H (64->64 channels) -------------------
// block = one (b, h) output row: C[64 co][128 w], K-loop over (t, ci)
__global__ void conv_h_kernel(const float* __restrict__ x)
{
    extern __shared__ float sm[];
    float* As = sm;             // 64x64 weights for current tap
    float* Xs = sm + NC*NC;     // 64x128 input row
    int h = blockIdx.x, b = blockIdx.y;
    int tid = threadIdx.x;
    int ty = tid >> 4, tx = tid & 15;
    float acc[8][8];
    #pragma unroll
    for (int r = 0; r < 8; r++)
        #pragma unroll
        for (int j = 0; j < 8; j++) acc[r][j] = 0.f;
    const float* xb = x + b*NC*HW;

    #pragma unroll 1
    for (int t = 0; t < KT; t++){
        int hin = h + t - 10;
        if ((unsigned)hin >= SH) continue;   // uniform: zero contribution
        #pragma unroll
        for (int i = 0; i < 32; i++) As[tid + i*128] = g_Wh[t*NC*NC + tid + i*128];
        const float* xr = xb + hin*SW;
        #pragma unroll 8
        for (int i = 0; i < 64; i++){
            int idx = tid + i*128;
            Xs[idx] = xr[(idx >> 7)*HW + (idx & 127)];
        }
        __syncthreads();
        #pragma unroll 2
        for (int ci = 0; ci < NC; ci++){
            float a[8], xv[8];
            #pragma unroll
            for (int r = 0; r < 8; r++) a[r] = As[(ty*8+r)*NC + ci];
            #pragma unroll
            for (int j = 0; j < 8; j++) xv[j] = Xs[ci*SW + tx + 16*j];
            #pragma unroll
            for (int r = 0; r < 8; r++)
                #pragma unroll
                for (int j = 0; j < 8; j++)
                    acc[r][j] = fmaf(a[r], xv[j], acc[r][j]);
        }
        __syncthreads();
    }
    float* outb = g_sch + b*NC*HW + h*SW;
    #pragma unroll
    for (int r = 0; r < 8; r++){
        int co = ty*8 + r;
        float rb = g_rbh[co*SH + h];
        #pragma unroll
        for (int j = 0; j < 8; j++)
            outb[co*HW + tx + 16*j] = acc[r][j] + rb;
    }
}

// ---------------- 21-tap conv along W -------------------------------------
__global__ void conv_w_kernel(const float* __restrict__ x)
{
    extern __shared__ float sm[];
    float* As = sm;             // 64x64
    float* Xs = sm + NC*NC;     // 64 x 148 (padded row)
    int h = blockIdx.x, b = blockIdx.y;
    int tid = threadIdx.x;
    int ty = tid >> 4, tx = tid & 15;
    float acc[8][8];
    #pragma unroll
    for (int r = 0; r < 8; r++)
        #pragma unroll
        for (int j = 0; j < 8; j++) acc[r][j] = 0.f;

    for (int i = tid; i < NC*148; i += 128) Xs[i] = 0.f;
    __syncthreads();
    const float* xr = x + b*NC*HW + h*SW;
    #pragma unroll 8
    for (int i = 0; i < 64; i++){
        int idx = tid + i*128;
        Xs[(idx >> 7)*148 + 10 + (idx & 127)] = xr[(idx >> 7)*HW + (idx & 127)];
    }
    __syncthreads();

    #pragma unroll 1
    for (int t = 0; t < KT; t++){
        #pragma unroll
        for (int i = 0; i < 32; i++) As[tid + i*128] = g_Ww[t*NC*NC + tid + i*128];
        __syncthreads();
        #pragma unroll 2
        for (int ci = 0; ci < NC; ci++){
            float a[8], xv[8];
            #pragma unroll
            for (int r = 0; r < 8; r++) a[r] = As[(ty*8+r)*NC + ci];
            #pragma unroll
            for (int j = 0; j < 8; j++) xv[j] = Xs[ci*148 + (tx + 16*j) + t];
            #pragma unroll
            for (int r = 0; r < 8; r++)
                #pragma unroll
                for (int j = 0; j < 8; j++)
                    acc[r][j] = fmaf(a[r], xv[j], acc[r][j]);
        }
        __syncthreads();
    }
    float* outb = g_scw + b*NC*HW + h*SW;
    #pragma unroll
    for (int r = 0; r < 8; r++){
        int co = ty*8 + r;
        #pragma unroll
        for (int j = 0; j < 8; j++){
            int w = tx + 16*j;
            outb[co*HW + w] = acc[r][j] + g_rbw[co*SW + w];
        }
    }
}

// ---------------- 1x1 qkv projection 64 -> 192 ----------------------------
__global__ void pw_kernel(int which, const float* __restrict__ w,
                          const float* __restrict__ bias)
{
    extern __shared__ float sm[];
    float* Ws = sm;            // 64x64 slab of weights (one o-group)
    float* Xs = sm + 4096;     // 64x128 pixels
    const float* sc = which ? g_scw : g_sch;
    float* out = which ? g_wqkv : g_hqkv;
    int pt = blockIdx.x, b = blockIdx.y, og = blockIdx.z;
    int px0 = pt * 128;
    int tid = threadIdx.x, ty = tid >> 4, tx = tid & 15;

    #pragma unroll
    for (int i = 0; i < 32; i++) Ws[tid + i*128] = w[og*4096 + tid + i*128];
    #pragma unroll 8
    for (int i = 0; i < 64; i++){
        int idx = tid + i*128;
        Xs[idx] = sc[(b*NC + (idx >> 7))*HW + px0 + (idx & 127)];
    }
    __syncthreads();
    float acc[8][8];
    #pragma unroll
    for (int r = 0; r < 8; r++)
        #pragma unroll
        for (int j = 0; j < 8; j++) acc[r][j] = 0.f;
    #pragma unroll 2
    for (int ci = 0; ci < NC; ci++){
        float a[8], xv[8];
        #pragma unroll
        for (int r = 0; r < 8; r++) a[r] = Ws[(ty*8+r)*NC + ci];
        #pragma unroll
        for (int j = 0; j < 8; j++) xv[j] = Xs[ci*128 + tx + 16*j];
        #pragma unroll
        for (int r = 0; r < 8; r++)
            #pragma unroll
            for (int j = 0; j < 8; j++)
                acc[r][j] = fmaf(a[r], xv[j], acc[r][j]);
    }
    #pragma unroll
    for (int r = 0; r < 8; r++){
        int o = og*64 + ty*8 + r;
        float bv = bias[o];
        #pragma unroll
        for (int j = 0; j < 8; j++)
            out[(b*192 + o)*HW + px0 + tx + 16*j] = acc[r][j] + bv;
    }
}

// ---------------- P = q^T @ v   (128x128, K=1024) per (b,nh) --------------
__global__ void gemm_p_kernel(int which)
{
    __shared__ __align__(16) float As[16*128];
    __shared__ __align__(16) float Bs[16*128];
    const float* A  = which ? g_wqkv : g_hqkv;   // q-side
    const float* Bm = which ? g_hqkv : g_wqkv;   // v-side
    float* P = which ? g_Ph : g_Pw;
    int pair = blockIdx.x;
    int b = pair >> 3, nh = pair & 7;
    int tid = threadIdx.x, ty = tid >> 4, tx = tid & 15;
    float acc[8][8];
    #pragma unroll
    for (int r = 0; r < 8; r++)
        #pragma unroll
        for (int j = 0; j < 8; j++) acc[r][j] = 0.f;
    // q block (d=0..7) and v block (d=16..23) are channel-contiguous:
    // the (DH x W) matrices are simply contiguous 1024x128 arrays.
    const float* abase = A  + (b*192 + nh*24 + 0 )*HW;
    const float* bbase = Bm + (b*192 + nh*24 + 16)*HW;

    #pragma unroll 1
    for (int k0 = 0; k0 < 1024; k0 += 16){
        const float* ap = abase + k0*SW;
        const float* bp = bbase + k0*SW;
        #pragma unroll
        for (int i = 0; i < 8; i++){
            As[tid + i*256] = ap[tid + i*256];
            Bs[tid + i*256] = bp[tid + i*256];
        }
        __syncthreads();
        #pragma unroll
        for (int k = 0; k < 16; k++){
            float4 a0 = *(const float4*)&As[k*128 + ty*8];
            float4 a1 = *(const float4*)&As[k*128 + ty*8 + 4];
            float4 b0 = *(const float4*)&Bs[k*128 + tx*8];
            float4 b1 = *(const float4*)&Bs[k*128 + tx*8 + 4];
            float a[8] = {a0.x,a0.y,a0.z,a0.w,a1.x,a1.y,a1.z,a1.w};
            float bb[8] = {b0.x,b0.y,b0.z,b0.w,b1.x,b1.y,b1.z,b1.w};
            #pragma unroll
            for (int r = 0; r < 8; r++)
                #pragma unroll
                for (int j = 0; j < 8; j++)
                    acc[r][j] = fmaf(a[r], bb[j], acc[r][j]);
        }
        __syncthreads();
    }
    float* pp = P + pair*16384;
    #pragma unroll
    for (int r = 0; r < 8; r++)
        #pragma unroll
        for (int j = 0; j < 8; j++)
            pp[(ty*8+r)*128 + tx*8 + j] = acc[r][j];
}

// ---------------- o = scale * k @ P  (1024x128, K=128) per (b,nh) ---------
__global__ void gemm_o_kernel(int which)
{
    __shared__ __align__(16) float As[16*132];  // padded stride (transposed k-chunk)
    __shared__ __align__(16) float Bs[16*128];
    const float* Kt = which ? g_hqkv : g_wqkv;  // k-side (offset +8)
    const float* P  = which ? g_Ph : g_Pw;
    float* out = which ? g_ho : g_wo;
    int jt = blockIdx.x, pair = blockIdx.y;     // jt = d (0..7), 128 rows each
    int b = pair >> 3, nh = pair & 7;
    int tid = threadIdx.x, ty = tid >> 4, tx = tid & 15;
    const float* kb = Kt + (b*192 + nh*24 + 8 + jt)*HW;
    const float* pb = P + pair*16384;
    float acc[8][8];
    #pragma unroll
    for (int r = 0; r < 8; r++)
        #pragma unroll
        for (int j = 0; j < 8; j++) acc[r][j] = 0.f;

    #pragma unroll 1
    for (int k0 = 0; k0 < 128; k0 += 16){
        #pragma unroll
        for (int i = 0; i < 8; i++){
            int idx = tid + i*256;
            int j = idx >> 4, k = idx & 15;
            As[k*132 + j] = kb[j*128 + k0 + k];   // transpose on store
        }
        #pragma unroll
        for (int i = 0; i < 8; i++){
            int idx = tid + i*256;
            Bs[idx] = pb[k0*128 + idx];
        }
        __syncthreads();
        #pragma unroll
        for (int k = 0; k < 16; k++){
            float4 a0 = *(const float4*)&As[k*132 + ty*8];
            float4 a1 = *(const float4*)&As[k*132 + ty*8 + 4];
            float4 b0 = *(const float4*)&Bs[k*128 + tx*8];
            float4 b1 = *(const float4*)&Bs[k*128 + tx*8 + 4];
            float a[8] = {a0.x,a0.y,a0.z,a0.w,a1.x,a1.y,a1.z,a1.w};
            float bb[8] = {b0.x,b0.y,b0.z,b0.w,b1.x,b1.y,b1.z,b1.w};
            #pragma unroll
            for (int r = 0; r < 8; r++)
                #pragma unroll
                for (int j = 0; j < 8; j++)
                    acc[r][j] = fmaf(a[r], bb[j], acc[r][j]);
        }
        __syncthreads();
    }
    const float scale = 0.707106781186547524f;   // D * H^-0.5
    float* ob = out + ((b*NC + nh*8 + jt)*SH)*SW;  // (b, c=nh*8+d, h, w)
    #pragma unroll
    for (int r = 0; r < 8; r++){
        int row = ty*8 + r;                       // h
        #pragma unroll
        for (int j = 0; j < 8; j++)
            ob[row*SW + tx*8 + j] = acc[r][j] * scale;
    }
}

// ---------------- epilogue: out-projections + sigmoid gate ----------------
__global__ void epi_kernel(const float* __restrict__ x,
    const float* __restrict__ wow, const float* __restrict__ wob,
    const float* __restrict__ how, const float* __restrict__ hob,
    float* __restrict__ out)
{
    extern __shared__ float sm[];
    float* Ws = sm;             // wout 64x64
    float* Hs = sm + 4096;      // hout 64x64
    float* Xw = sm + 8192;      // 16x128 chunk of w_o
    float* Xh = sm + 8192 + 2048;
    int pt = blockIdx.x, b = blockIdx.y;
    int px0 = pt * 128;
    int tid = threadIdx.x, ty = tid >> 4, tx = tid & 15;

    #pragma unroll
    for (int i = 0; i < 32; i++){
        Ws[tid + i*128] = wow[tid + i*128];
        Hs[tid + i*128] = how[tid + i*128];
    }
    float acc[8][8];
    #pragma unroll
    for (int r = 0; r < 8; r++)
        #pragma unroll
        for (int j = 0; j < 8; j++) acc[r][j] = 0.f;

    #pragma unroll 1
    for (int kc = 0; kc < 4; kc++){
        #pragma unroll
        for (int i = 0; i < 16; i++){
            int idx = tid + i*128;
            int ci = idx >> 7, p = idx & 127;
            Xw[idx] = g_wo[(b*NC + kc*16 + ci)*HW + px0 + p];
            Xh[idx] = g_ho[(b*NC + kc*16 + ci)*HW + px0 + p];
        }
        __syncthreads();
        #pragma unroll 2
        for (int c16 = 0; c16 < 16; c16++){
            int ci = kc*16 + c16;
            float aw[8], ah[8], xw[8], xh[8];
            #pragma unroll
            for (int r = 0; r < 8; r++){
                aw[r] = Ws[(ty*8+r)*NC + ci];
                ah[r] = Hs[(ty*8+r)*NC + ci];
            }
            #pragma unroll
            for (int j = 0; j < 8; j++){
                xw[j] = Xw[c16*128 + tx + 16*j];
                xh[j] = Xh[c16*128 + tx + 16*j];
            }
            #pragma unroll
            for (int r = 0; r < 8; r++)
                #pragma unroll
                for (int j = 0; j < 8; j++){
                    acc[r][j] = fmaf(aw[r], xw[j], acc[r][j]);
                    acc[r][j] = fmaf(ah[r], xh[j], acc[r][j]);
                }
        }
        __syncthreads();
    }
    #pragma unroll
    for (int r = 0; r < 8; r++){
        int c = ty*8 + r;
        float bv = wob[c] + hob[c];
        #pragma unroll
        for (int j = 0; j < 8; j++){
            int px = px0 + tx + 16*j;
            float s = acc[r][j] + bv;
            float xv = x[(b*NC + c)*HW + px];
            out[(b*NC + c)*HW + px] = xv * (1.f / (1.f + expf(-s)));
        }
    }
}

// ---------------- launch ---------------------------------------------------
extern "C" void kernel_launch(void* const* d_in, const int* in_sizes, int n_in,
                              void* d_out, int out_size)
{
    const float* x = (const float*)d_in[0];
    // index maps for the two plausible input orderings
    int i1w[3], i1b[3], i2w[3], i2b[3];
    if (in_sizes[11] == 45056){ // reference-signature order
        i1w[0]=9;  i1w[1]=11; i1w[2]=13;  i1b[0]=10; i1b[1]=12; i1b[2]=14;
        i2w[0]=15; i2w[1]=17; i2w[2]=19;  i2b[0]=16; i2b[1]=18; i2b[2]=20;
    } else {                    // setup_inputs dict order
        i1w[0]=9;  i1w[1]=13; i1w[2]=17;  i1b[0]=10; i1b[1]=14; i1b[2]=18;
        i2w[0]=11; i2w[1]=15; i2w[2]=19;  i2b[0]=12; i2b[1]=16; i2b[2]=20;
    }
    const float* bn1g=(const float*)d_in[1]; const float* bn1b=(const float*)d_in[2];
    const float* bn1m=(const float*)d_in[3]; const float* bn1v=(const float*)d_in[4];
    const float* bn2g=(const float*)d_in[5]; const float* bn2b=(const float*)d_in[6];
    const float* bn2m=(const float*)d_in[7]; const float* bn2v=(const float*)d_in[8];
    const float* hqkvw=(const float*)d_in[21]; const float* hqkvb=(const float*)d_in[22];
    const float* wqkvw=(const float*)d_in[23]; const float* wqkvb=(const float*)d_in[24];
    const float* houtw=(const float*)d_in[25]; const float* houtb=(const float*)d_in[26];
    const float* woutw=(const float*)d_in[27]; const float* woutb=(const float*)d_in[28];

    cudaFuncSetAttribute(conv_h_kernel, cudaFuncAttributeMaxDynamicSharedMemorySize, 64*1024);
    cudaFuncSetAttribute(conv_w_kernel, cudaFuncAttributeMaxDynamicSharedMemorySize, 64*1024);
    cudaFuncSetAttribute(pw_kernel,     cudaFuncAttributeMaxDynamicSharedMemorySize, 64*1024);
    cudaFuncSetAttribute(epi_kernel,    cudaFuncAttributeMaxDynamicSharedMemorySize, 64*1024);

    prep_kernel<<<NC, 128>>>(0,
        (const float*)d_in[i1w[0]], (const float*)d_in[i1b[0]],
        (const float*)d_in[i1w[1]], (const float*)d_in[i1b[1]],
        (const float*)d_in[i1w[2]], (const float*)d_in[i1b[2]],
        bn1g, bn1b, bn1m, bn1v);
    prep_kernel<<<NC, 128>>>(1,
        (const float*)d_in[i2w[0]], (const float*)d_in[i2b[0]],
        (const float*)d_in[i2w[1]], (const float*)d_in[i2b[1]],
        (const float*)d_in[i2w[2]], (const float*)d_in[i2b[2]],
        bn2g, bn2b, bn2m, bn2v);

    conv_h_kernel<<<dim3(SH, NB), 128, 49152>>>(x);
    conv_w_kernel<<<dim3(SH, NB), 128, 54272>>>(x);

    pw_kernel<<<dim3(128, NB, 3), 128, 49152>>>(0, hqkvw, hqkvb);
    pw_kernel<<<dim3(128, NB, 3), 128, 49152>>>(1, wqkvw, wqkvb);

    gemm_p_kernel<<<64, 256>>>(0);   // P_w = hq^T @ wv
    gemm_p_kernel<<<64, 256>>>(1);   // P_h = wq^T @ hv
    gemm_o_kernel<<<dim3(8, 64), 256>>>(0);  // w_o = scale * wk @ P_w
    gemm_o_kernel<<<dim3(8, 64), 256>>>(1);  // h_o = scale * hk @ P_h

    epi_kernel<<<dim3(128, NB), 128, 49152>>>(x, woutw, woutb, houtw, houtb,
                                              (float*)d_out);
}

// round 3
// speedup vs baseline: 1.3833x; 1.3833x over previous
#include <cuda_runtime.h>

#define NB 8
#define NC 64
#define SH 128
#define SW 128
#define HW (SH*SW)
#define KT 21

// ---------------- scratch (device globals; no allocations) ----------------
__device__ __align__(16) float g_Wh[KT*NC*NC];      // combined+BN-folded weights [t][ci][co]
__device__ __align__(16) float g_Ww[KT*NC*NC];
__device__ __align__(16) float g_rbh[NC*SH];        // per-(cout,row) bias for h-conv
__device__ __align__(16) float g_rbw[NC*SW];        // per-(cout,col) bias for w-conv
__device__ __align__(16) float g_sch[NB*NC*HW];
__device__ __align__(16) float g_scw[NB*NC*HW];
__device__ __align__(16) float g_hqkv[NB*192*HW];
__device__ __align__(16) float g_wqkv[NB*192*HW];
__device__ __align__(16) float g_Pp[2*64*4*SW*SW];  // partial P: [which][pair][ksplit][128][128]
__device__ __align__(16) float g_wo[NB*NC*HW];
__device__ __align__(16) float g_ho[NB*NC*HW];

// ---------------- prep: combine 3 strip kernels, fold BN, row biases ------
__global__ void prep_kernel(int side,
    const float* __restrict__ w7,  const float* __restrict__ b7,
    const float* __restrict__ w11, const float* __restrict__ b11,
    const float* __restrict__ w21, const float* __restrict__ b21,
    const float* __restrict__ bng, const float* __restrict__ bnb,
    const float* __restrict__ bnm, const float* __restrict__ bnv)
{
    float* Wout  = side ? g_Ww  : g_Wh;
    float* rbout = side ? g_rbw : g_rbh;
    int co = blockIdx.x;
    int tid = threadIdx.x;
    __shared__ float Wraw[NC*KT];
    __shared__ float Pfx[NC*(KT+1)];

    for (int idx = tid; idx < NC*KT; idx += blockDim.x){
        int ci = idx / KT, t = idx % KT;
        float v = w21[(co*NC+ci)*21 + t];
        if (t >= 5 && t < 16) v += w11[(co*NC+ci)*11 + (t-5)];
        if (t >= 7 && t < 14) v += w7 [(co*NC+ci)*7  + (t-7)];
        Wraw[idx] = v;
        float a = bng[ci] * rsqrtf(bnv[ci] + 1e-5f);
        Wout[t*NC*NC + ci*NC + co] = v * a;   // [t][ci][co]
    }
    __syncthreads();
    if (tid < NC){
        int ci = tid;
        float a = bng[ci] * rsqrtf(bnv[ci] + 1e-5f);
        float c = bnb[ci] - bnm[ci] * a;
        float s = 0.f;
        Pfx[ci*(KT+1)] = 0.f;
        for (int t = 0; t < KT; t++){
            s += Wraw[ci*KT + t] * c;
            Pfx[ci*(KT+1) + t + 1] = s;
        }
    }
    __syncthreads();
    float cb = b7[co] + b11[co] + b21[co];
    for (int h = tid; h < SH; h += blockDim.x){
        int t0 = 10 - h;  if (t0 < 0) t0 = 0;
        int t1 = 137 - h; if (t1 > KT-1) t1 = KT-1;
        float s = cb;
        for (int ci = 0; ci < NC; ci++)
            s += Pfx[ci*(KT+1) + t1 + 1] - Pfx[ci*(KT+1) + t0];
        rbout[co*SH + h] = s;
    }
}

// ---------------- 21-tap conv along H: 2 output rows per block ------------
// smem: As[64ci][64co] (16KB) + 2 rolling row buffers [64ci][128w] (32KB each)
__global__ __launch_bounds__(256) void conv_h_kernel(const float* __restrict__ x)
{
    extern __shared__ float sm[];
    float* As = sm;                      // 4096 words
    // row slot s at sm + 4096 + s*8192
    int h0 = blockIdx.x * 2, b = blockIdx.y;
    int tid = threadIdx.x;
    int wy = tid >> 5;                   // co group (8 co)
    int l  = tid & 31;
    int rsel = l >> 4;                   // row within pair
    int c4w  = l & 15;                   // float4 col group
    const float* xb = x + b*NC*HW;

    float acc[8][8];
    #pragma unroll
    for (int r = 0; r < 8; r++)
        #pragma unroll
        for (int j = 0; j < 8; j++) acc[r][j] = 0.f;

    // initial loads: rows h0-10, h0-9 ; weights tap 0
    #pragma unroll
    for (int rr = 0; rr < 2; rr++){
        int r = h0 - 10 + rr;
        float4* dst = (float4*)(sm + 4096 + (r & 1)*8192);
        if ((unsigned)r < 128u){
            #pragma unroll
            for (int i = 0; i < 8; i++){
                int idx = tid + i*256;
                int ci = idx >> 5, w4 = idx & 31;
                dst[idx] = *(const float4*)(xb + ci*HW + r*SW + w4*4);
            }
        } else {
            float4 z = {0.f,0.f,0.f,0.f};
            #pragma unroll
            for (int i = 0; i < 8; i++) dst[tid + i*256] = z;
        }
    }
    {
        const float4* src = (const float4*)g_Wh;
        #pragma unroll
        for (int i = 0; i < 4; i++) ((float4*)As)[tid + i*256] = src[tid + i*256];
    }
    __syncthreads();

    #pragma unroll 1
    for (int t = 0; t < KT; t++){
        const float4* Xp = (const float4*)(sm + 4096 + ((t + rsel) & 1)*8192);
        const float4* Aq = (const float4*)As;
        #pragma unroll 4
        for (int ci = 0; ci < NC; ci++){
            float4 a0 = Aq[ci*16 + wy*2];
            float4 a1 = Aq[ci*16 + wy*2 + 1];
            float4 x0 = Xp[ci*32 + c4w];
            float4 x1 = Xp[ci*32 + c4w + 16];
            float a[8] = {a0.x,a0.y,a0.z,a0.w,a1.x,a1.y,a1.z,a1.w};
            float xv[8] = {x0.x,x0.y,x0.z,x0.w,x1.x,x1.y,x1.z,x1.w};
            #pragma unroll
            for (int r = 0; r < 8; r++)
                #pragma unroll
                for (int j = 0; j < 8; j++)
                    acc[r][j] = fmaf(a[r], xv[j], acc[r][j]);
        }
        __syncthreads();
        if (t < KT-1){
            int r = h0 + t - 8;          // next needed row
            float4* dst = (float4*)(sm + 4096 + (r & 1)*8192);
            if ((unsigned)r < 128u){
                #pragma unroll
                for (int i = 0; i < 8; i++){
                    int idx = tid + i*256;
                    int ci = idx >> 5, w4 = idx & 31;
                    dst[idx] = *(const float4*)(xb + ci*HW + r*SW + w4*4);
                }
            } else {
                float4 z = {0.f,0.f,0.f,0.f};
                #pragma unroll
                for (int i = 0; i < 8; i++) dst[tid + i*256] = z;
            }
            const float4* src = (const float4*)(g_Wh + (t+1)*4096);
            #pragma unroll
            for (int i = 0; i < 4; i++) ((float4*)As)[tid + i*256] = src[tid + i*256];
        }
        __syncthreads();
    }

    int h = h0 + rsel;
    #pragma unroll
    for (int r = 0; r < 8; r++){
        int co = wy*8 + r;
        float rb = g_rbh[co*SH + h];
        float* ob = g_sch + (b*NC + co)*HW + h*SW;
        float4 v0 = {acc[r][0]+rb, acc[r][1]+rb, acc[r][2]+rb, acc[r][3]+rb};
        float4 v1 = {acc[r][4]+rb, acc[r][5]+rb, acc[r][6]+rb, acc[r][7]+rb};
        *(float4*)(ob + c4w*4)      = v0;
        *(float4*)(ob + c4w*4 + 64) = v1;
    }
}

// ---------------- 21-tap conv along W: 2 rows per block, X resident -------
// smem: As 16KB + Xs[64ci][2row][176] (88KB).
// Row center stored at word offset 12 (16B aligned). Output pixel p, tap t
// reads index 12 + p + t - 10 = 2 + wl + 16*jj + t. Pads zero-filled.
#define WSTR 176
__global__ __launch_bounds__(256) void conv_w_kernel(const float* __restrict__ x)
{
    extern __shared__ float sm[];
    float* As = sm;                      // 4096 words
    float* Xs = sm + 4096;               // 64*352 = 22528 words
    int h0 = blockIdx.x * 2, b = blockIdx.y;
    int tid = threadIdx.x;
    int wy = tid >> 5;
    int l  = tid & 31;
    int rsel = l >> 4;
    int wl = l & 15;                     // pixel lane: px = wl + 16*jj
    const float* xb = x + b*NC*HW;

    // zero entire buffer (covers both pads), then fill center at +12 (16B aligned)
    {
        float4 z = {0.f,0.f,0.f,0.f};
        for (int i = tid; i < 5632; i += 256) ((float4*)Xs)[i] = z;
    }
    __syncthreads();
    #pragma unroll
    for (int i = 0; i < 16; i++){
        int idx = tid + i*256;
        int ci = idx >> 6, rem = idx & 63;
        int row = rem >> 5, w4 = rem & 31;
        *(float4*)(Xs + ci*(2*WSTR) + row*WSTR + 12 + w4*4) =
            *(const float4*)(xb + ci*HW + (h0+row)*SW + w4*4);
    }
    {
        const float4* src = (const float4*)g_Ww;
        #pragma unroll
        for (int i = 0; i < 4; i++) ((float4*)As)[tid + i*256] = src[tid + i*256];
    }
    __syncthreads();

    float acc[8][8];
    #pragma unroll
    for (int r = 0; r < 8; r++)
        #pragma unroll
        for (int j = 0; j < 8; j++) acc[r][j] = 0.f;

    #pragma unroll 1
    for (int t = 0; t < KT; t++){
        const float* xp = Xs + rsel*WSTR + 2 + wl + t;   // = center(12) + px + t - 10
        const float4* Aq = (const float4*)As;
        #pragma unroll 4
        for (int ci = 0; ci < NC; ci++){
            float4 a0 = Aq[ci*16 + wy*2];
            float4 a1 = Aq[ci*16 + wy*2 + 1];
            float a[8] = {a0.x,a0.y,a0.z,a0.w,a1.x,a1.y,a1.z,a1.w};
            const float* xc = xp + ci*(2*WSTR);
            float xv[8];
            #pragma unroll
            for (int jj = 0; jj < 8; jj++) xv[jj] = xc[16*jj];
            #pragma unroll
            for (int r = 0; r < 8; r++)
                #pragma unroll
                for (int jj = 0; jj < 8; jj++)
                    acc[r][jj] = fmaf(a[r], xv[jj], acc[r][jj]);
        }
        __syncthreads();
        if (t < KT-1){
            const float4* src = (const float4*)(g_Ww + (t+1)*4096);
            #pragma unroll
            for (int i = 0; i < 4; i++) ((float4*)As)[tid + i*256] = src[tid + i*256];
        }
        __syncthreads();
    }

    // stage outputs into Xs ([co][row][128]) to enable float4 global stores
    #pragma unroll
    for (int r = 0; r < 8; r++){
        int co = wy*8 + r;
        float* ot = Xs + co*256 + rsel*128 + wl;
        #pragma unroll
        for (int jj = 0; jj < 8; jj++) ot[16*jj] = acc[r][jj];
    }
    __syncthreads();
    for (int i = 0; i < 16; i++){
        int idx4 = tid + i*256;
        int co = idx4 >> 6;
        int row = (idx4 >> 5) & 1;
        int w4 = idx4 & 31;
        float4 v = ((float4*)Xs)[idx4];
        float4 bb = *(const float4*)(g_rbw + co*SW + w4*4);
        v.x += bb.x; v.y += bb.y; v.z += bb.z; v.w += bb.w;
        *(float4*)(g_scw + (b*NC + co)*HW + (h0+row)*SW + w4*4) = v;
    }
}

// ---------------- 1x1 qkv projection 64 -> 192 ----------------------------
__global__ __launch_bounds__(128) void pw_kernel(int which, const float* __restrict__ w,
                          const float* __restrict__ bias)
{
    extern __shared__ float sm[];
    float* Ws = sm;            // [ci][o pad 68] = 4352 words
    float* Xs = sm + 4352;     // [ci][128] = 8192 words
    const float* sc = which ? g_scw : g_sch;
    float* out = which ? g_wqkv : g_hqkv;
    int pt = blockIdx.x, b = blockIdx.y, og = blockIdx.z;
    int px0 = pt * 128;
    int tid = threadIdx.x, ty = tid >> 4, tx = tid & 15;

    #pragma unroll
    for (int i = 0; i < 32; i++){
        int idx = tid + i*128;
        int o = idx >> 6, ci = idx & 63;
        Ws[ci*68 + o] = w[og*4096 + idx];
    }
    {
        #pragma unroll
        for (int i = 0; i < 16; i++){
            int idx4 = tid + i*128;
            int ci = idx4 >> 5, p4 = idx4 & 31;
            ((float4*)Xs)[idx4] = *(const float4*)(sc + (b*NC + ci)*HW + px0 + p4*4);
        }
    }
    __syncthreads();
    float acc[8][8];
    #pragma unroll
    for (int r = 0; r < 8; r++)
        #pragma unroll
        for (int j = 0; j < 8; j++) acc[r][j] = 0.f;
    const float4* Xq = (const float4*)Xs;
    #pragma unroll 4
    for (int ci = 0; ci < NC; ci++){
        float4 a0 = *(const float4*)(Ws + ci*68 + ty*8);
        float4 a1 = *(const float4*)(Ws + ci*68 + ty*8 + 4);
        float4 x0 = Xq[ci*32 + tx];
        float4 x1 = Xq[ci*32 + tx + 16];
        float a[8] = {a0.x,a0.y,a0.z,a0.w,a1.x,a1.y,a1.z,a1.w};
        float xv[8] = {x0.x,x0.y,x0.z,x0.w,x1.x,x1.y,x1.z,x1.w};
        #pragma unroll
        for (int r = 0; r < 8; r++)
            #pragma unroll
            for (int j = 0; j < 8; j++)
                acc[r][j] = fmaf(a[r], xv[j], acc[r][j]);
    }
    #pragma unroll
    for (int r = 0; r < 8; r++){
        int o = og*64 + ty*8 + r;
        float bv = bias[o];
        float* ob = out + (b*192 + o)*HW + px0;
        float4 v0 = {acc[r][0]+bv, acc[r][1]+bv, acc[r][2]+bv, acc[r][3]+bv};
        float4 v1 = {acc[r][4]+bv, acc[r][5]+bv, acc[r][6]+bv, acc[r][7]+bv};
        *(float4*)(ob + tx*4)      = v0;
        *(float4*)(ob + tx*4 + 64) = v1;
    }
}

// ---------------- P partials: both branches, K split 4 --------------------
__global__ __launch_bounds__(256) void gemm_p_kernel()
{
    __shared__ __align__(16) float As[16*128];
    __shared__ __align__(16) float Bs[16*128];
    int pair = blockIdx.x, ks = blockIdx.y, which = blockIdx.z;
    int b = pair >> 3, nh = pair & 7;
    const float* A  = which ? g_wqkv : g_hqkv;   // q-side
    const float* Bm = which ? g_hqkv : g_wqkv;   // v-side
    int tid = threadIdx.x, ty = tid >> 4, tx = tid & 15;
    float acc[8][8];
    #pragma unroll
    for (int r = 0; r < 8; r++)
        #pragma unroll
        for (int j = 0; j < 8; j++) acc[r][j] = 0.f;
    const float* abase = A  + (b*192 + nh*24 + 0 )*HW + ks*256*SW;
    const float* bbase = Bm + (b*192 + nh*24 + 16)*HW + ks*256*SW;

    #pragma unroll 1
    for (int k0 = 0; k0 < 256; k0 += 16){
        const float4* ap = (const float4*)(abase + k0*SW);
        const float4* bp = (const float4*)(bbase + k0*SW);
        #pragma unroll
        for (int i = 0; i < 2; i++){
            ((float4*)As)[tid + i*256] = ap[tid + i*256];
            ((float4*)Bs)[tid + i*256] = bp[tid + i*256];
        }
        __syncthreads();
        const float4* Aq = (const float4*)As;
        const float4* Bq = (const float4*)Bs;
        #pragma unroll
        for (int k = 0; k < 16; k++){
            float4 a0 = Aq[k*32 + ty];
            float4 a1 = Aq[k*32 + ty + 16];
            float4 b0 = Bq[k*32 + tx];
            float4 b1 = Bq[k*32 + tx + 16];
            float a[8] = {a0.x,a0.y,a0.z,a0.w,a1.x,a1.y,a1.z,a1.w};
            float bb[8] = {b0.x,b0.y,b0.z,b0.w,b1.x,b1.y,b1.z,b1.w};
            #pragma unroll
            for (int r = 0; r < 8; r++)
                #pragma unroll
                for (int j = 0; j < 8; j++)
                    acc[r][j] = fmaf(a[r], bb[j], acc[r][j]);
        }
        __syncthreads();
    }
    float* pp = g_Pp + ((which*64 + pair)*4 + ks)*16384;
    #pragma unroll
    for (int r = 0; r < 8; r++){
        int row = ty*4 + (r & 3) + (r >= 4 ? 64 : 0);
        float4 v0 = {acc[r][0], acc[r][1], acc[r][2], acc[r][3]};
        float4 v1 = {acc[r][4], acc[r][5], acc[r][6], acc[r][7]};
        *(float4*)(pp + row*128 + tx*4)      = v0;
        *(float4*)(pp + row*128 + tx*4 + 64) = v1;
    }
}

// ---------------- o = scale * k @ (sum of P partials) ---------------------
__global__ __launch_bounds__(256) void gemm_o_kernel()
{
    __shared__ __align__(16) float As[16*132];
    __shared__ __align__(16) float Bs[16*128];
    int jt = blockIdx.x, pair = blockIdx.y, which = blockIdx.z;
    int b = pair >> 3, nh = pair & 7;
    const float* Kt = which ? g_hqkv : g_wqkv;
    float* out = which ? g_ho : g_wo;
    int tid = threadIdx.x, ty = tid >> 4, tx = tid & 15;
    const float* kb = Kt + (b*192 + nh*24 + 8 + jt)*HW;
    const float* pb = g_Pp + (which*64 + pair)*4*16384;
    float acc[8][8];
    #pragma unroll
    for (int r = 0; r < 8; r++)
        #pragma unroll
        for (int j = 0; j < 8; j++) acc[r][j] = 0.f;

    #pragma unroll 1
    for (int k0 = 0; k0 < 128; k0 += 16){
        #pragma unroll
        for (int i = 0; i < 8; i++){
            int idx = tid + i*256;
            int j = idx >> 4, k = idx & 15;
            As[k*132 + j] = kb[j*128 + k0 + k];   // transpose on store
        }
        #pragma unroll
        for (int i = 0; i < 2; i++){
            int idx4 = tid + i*256;
            float4 p0 = ((const float4*)(pb             ))[k0*32 + idx4];
            float4 p1 = ((const float4*)(pb + 16384     ))[k0*32 + idx4];
            float4 p2 = ((const float4*)(pb + 2*16384   ))[k0*32 + idx4];
            float4 p3 = ((const float4*)(pb + 3*16384   ))[k0*32 + idx4];
            float4 s = {p0.x+p1.x+p2.x+p3.x, p0.y+p1.y+p2.y+p3.y,
                        p0.z+p1.z+p2.z+p3.z, p0.w+p1.w+p2.w+p3.w};
            ((float4*)Bs)[idx4] = s;
        }
        __syncthreads();
        const float4* Bq = (const float4*)Bs;
        #pragma unroll
        for (int k = 0; k < 16; k++){
            float4 a0 = *(const float4*)(As + k*132 + ty*4);
            float4 a1 = *(const float4*)(As + k*132 + ty*4 + 64);
            float4 b0 = Bq[k*32 + tx];
            float4 b1 = Bq[k*32 + tx + 16];
            float a[8] = {a0.x,a0.y,a0.z,a0.w,a1.x,a1.y,a1.z,a1.w};
            float bb[8] = {b0.x,b0.y,b0.z,b0.w,b1.x,b1.y,b1.z,b1.w};
            #pragma unroll
            for (int r = 0; r < 8; r++)
                #pragma unroll
                for (int j = 0; j < 8; j++)
                    acc[r][j] = fmaf(a[r], bb[j], acc[r][j]);
        }
        __syncthreads();
    }
    const float scale = 0.707106781186547524f;   // D * H^-0.5
    float* ob = out + (b*NC + nh*8 + jt)*HW;
    #pragma unroll
    for (int r = 0; r < 8; r++){
        int row = ty*4 + (r & 3) + (r >= 4 ? 64 : 0);   // h index
        float4 v0 = {acc[r][0]*scale, acc[r][1]*scale, acc[r][2]*scale, acc[r][3]*scale};
        float4 v1 = {acc[r][4]*scale, acc[r][5]*scale, acc[r][6]*scale, acc[r][7]*scale};
        *(float4*)(ob + row*SW + tx*4)      = v0;
        *(float4*)(ob + row*SW + tx*4 + 64) = v1;
    }
}

// ---------------- epilogue: out-projections + sigmoid gate ----------------
__global__ __launch_bounds__(128) void epi_kernel(const float* __restrict__ x,
    const float* __restrict__ wow, const float* __restrict__ wob,
    const float* __restrict__ how, const float* __restrict__ hob,
    float* __restrict__ out)
{
    extern __shared__ float sm[];
    float* Ws = sm;              // [ci][o pad 68]
    float* Hs = sm + 4352;
    float* Xw = sm + 8704;       // [16][128]
    float* Xh = sm + 8704 + 2048;
    int pt = blockIdx.x, b = blockIdx.y;
    int px0 = pt * 128;
    int tid = threadIdx.x, ty = tid >> 4, tx = tid & 15;

    #pragma unroll
    for (int i = 0; i < 32; i++){
        int idx = tid + i*128;
        int o = idx >> 6, ci = idx & 63;
        Ws[ci*68 + o] = wow[idx];
        Hs[ci*68 + o] = how[idx];
    }
    float acc[8][8];
    #pragma unroll
    for (int r = 0; r < 8; r++)
        #pragma unroll
        for (int j = 0; j < 8; j++) acc[r][j] = 0.f;

    #pragma unroll 1
    for (int kc = 0; kc < 4; kc++){
        if (kc) __syncthreads();
        #pragma unroll
        for (int i = 0; i < 4; i++){
            int idx4 = tid + i*128;
            int ci = idx4 >> 5, p4 = idx4 & 31;
            ((float4*)Xw)[idx4] = *(const float4*)(g_wo + (b*NC + kc*16 + ci)*HW + px0 + p4*4);
            ((float4*)Xh)[idx4] = *(const float4*)(g_ho + (b*NC + kc*16 + ci)*HW + px0 + p4*4);
        }
        __syncthreads();
        const float4* Xwq = (const float4*)Xw;
        const float4* Xhq = (const float4*)Xh;
        #pragma unroll 2
        for (int c16 = 0; c16 < 16; c16++){
            int ci = kc*16 + c16;
            float4 aw0 = *(const float4*)(Ws + ci*68 + ty*8);
            float4 aw1 = *(const float4*)(Ws + ci*68 + ty*8 + 4);
            float4 ah0 = *(const float4*)(Hs + ci*68 + ty*8);
            float4 ah1 = *(const float4*)(Hs + ci*68 + ty*8 + 4);
            float4 xw0 = Xwq[c16*32 + tx];
            float4 xw1 = Xwq[c16*32 + tx + 16];
            float4 xh0 = Xhq[c16*32 + tx];
            float4 xh1 = Xhq[c16*32 + tx + 16];
            float aw[8] = {aw0.x,aw0.y,aw0.z,aw0.w,aw1.x,aw1.y,aw1.z,aw1.w};
            float ah[8] = {ah0.x,ah0.y,ah0.z,ah0.w,ah1.x,ah1.y,ah1.z,ah1.w};
            float xwv[8] = {xw0.x,xw0.y,xw0.z,xw0.w,xw1.x,xw1.y,xw1.z,xw1.w};
            float xhv[8] = {xh0.x,xh0.y,xh0.z,xh0.w,xh1.x,xh1.y,xh1.z,xh1.w};
            #pragma unroll
            for (int r = 0; r < 8; r++)
                #pragma unroll
                for (int j = 0; j < 8; j++){
                    acc[r][j] = fmaf(aw[r], xwv[j], acc[r][j]);
                    acc[r][j] = fmaf(ah[r], xhv[j], acc[r][j]);
                }
        }
    }
    #pragma unroll
    for (int r = 0; r < 8; r++){
        int c = ty*8 + r;
        float bv = wob[c] + hob[c];
        const float* xb = x + (b*NC + c)*HW + px0;
        float* ob = out + (b*NC + c)*HW + px0;
        #pragma unroll
        for (int half = 0; half < 2; half++){
            float4 xv = *(const float4*)(xb + tx*4 + half*64);
            float vs[4];
            #pragma unroll
            for (int j = 0; j < 4; j++){
                float s = acc[r][half*4 + j] + bv;
                vs[j] = (&xv.x)[j] * (1.f / (1.f + expf(-s)));
            }
            float4 v = {vs[0], vs[1], vs[2], vs[3]};
            *(float4*)(ob + tx*4 + half*64) = v;
        }
    }
}

// ---------------- launch ---------------------------------------------------
extern "C" void kernel_launch(void* const* d_in, const int* in_sizes, int n_in,
                              void* d_out, int out_size)
{
    const float* x = (const float*)d_in[0];
    int i1w[3], i1b[3], i2w[3], i2b[3];
    if (in_sizes[11] == 45056){ // reference-signature order
        i1w[0]=9;  i1w[1]=11; i1w[2]=13;  i1b[0]=10; i1b[1]=12; i1b[2]=14;
        i2w[0]=15; i2w[1]=17; i2w[2]=19;  i2b[0]=16; i2b[1]=18; i2b[2]=20;
    } else {                    // setup_inputs dict order
        i1w[0]=9;  i1w[1]=13; i1w[2]=17;  i1b[0]=10; i1b[1]=14; i1b[2]=18;
        i2w[0]=11; i2w[1]=15; i2w[2]=19;  i2b[0]=12; i2b[1]=16; i2b[2]=20;
    }
    const float* bn1g=(const float*)d_in[1]; const float* bn1b=(const float*)d_in[2];
    const float* bn1m=(const float*)d_in[3]; const float* bn1v=(const float*)d_in[4];
    const float* bn2g=(const float*)d_in[5]; const float* bn2b=(const float*)d_in[6];
    const float* bn2m=(const float*)d_in[7]; const float* bn2v=(const float*)d_in[8];
    const float* hqkvw=(const float*)d_in[21]; const float* hqkvb=(const float*)d_in[22];
    const float* wqkvw=(const float*)d_in[23]; const float* wqkvb=(const float*)d_in[24];
    const float* houtw=(const float*)d_in[25]; const float* houtb=(const float*)d_in[26];
    const float* woutw=(const float*)d_in[27]; const float* woutb=(const float*)d_in[28];

    cudaFuncSetAttribute(conv_h_kernel, cudaFuncAttributeMaxDynamicSharedMemorySize, 100*1024);
    cudaFuncSetAttribute(conv_w_kernel, cudaFuncAttributeMaxDynamicSharedMemorySize, 120*1024);
    cudaFuncSetAttribute(pw_kernel,     cudaFuncAttributeMaxDynamicSharedMemorySize, 64*1024);
    cudaFuncSetAttribute(epi_kernel,    cudaFuncAttributeMaxDynamicSharedMemorySize, 64*1024);

    prep_kernel<<<NC, 128>>>(0,
        (const float*)d_in[i1w[0]], (const float*)d_in[i1b[0]],
        (const float*)d_in[i1w[1]], (const float*)d_in[i1b[1]],
        (const float*)d_in[i1w[2]], (const float*)d_in[i1b[2]],
        bn1g, bn1b, bn1m, bn1v);
    prep_kernel<<<NC, 128>>>(1,
        (const float*)d_in[i2w[0]], (const float*)d_in[i2b[0]],
        (const float*)d_in[i2w[1]], (const float*)d_in[i2b[1]],
        (const float*)d_in[i2w[2]], (const float*)d_in[i2b[2]],
        bn2g, bn2b, bn2m, bn2v);

    conv_h_kernel<<<dim3(64, NB), 256, (4096 + 2*8192)*4>>>(x);
    conv_w_kernel<<<dim3(64, NB), 256, (4096 + 64*2*WSTR)*4>>>(x);

    pw_kernel<<<dim3(128, NB, 3), 128, (4352 + 8192)*4>>>(0, hqkvw, hqkvb);
    pw_kernel<<<dim3(128, NB, 3), 128, (4352 + 8192)*4>>>(1, wqkvw, wqkvb);

    gemm_p_kernel<<<dim3(64, 4, 2), 256>>>();
    gemm_o_kernel<<<dim3(8, 64, 2), 256>>>();

    epi_kernel<<<dim3(128, NB), 128, (8704 + 4096)*4>>>(x, woutw, woutb, houtw, houtb,
                                                        (float*)d_out);
}

// round 4
// speedup vs baseline: 2.6901x; 1.9447x over previous
#include <cuda_runtime.h>

#define NB 8
#define NC 64
#define SH 128
#define SW 128
#define HW (SH*SW)
#define KT 21

// ---------------- scratch (device globals; no allocations) ----------------
__device__ __align__(16) float g_Wh[KT*NC*NC];      // combined+BN-folded tf32 weights [t][ci][co]
__device__ __align__(16) float g_Ww[KT*NC*NC];
__device__ __align__(16) float g_rbh[NC*SH];        // per-(cout,row) bias for h-conv (fp32 exact)
__device__ __align__(16) float g_rbw[NC*SW];
__device__ __align__(16) float g_sch[NB*NC*HW];
__device__ __align__(16) float g_scw[NB*NC*HW];
__device__ __align__(16) float g_hqkv[NB*192*HW];
__device__ __align__(16) float g_wqkv[NB*192*HW];
__device__ __align__(16) float g_Pp[2*64*4*SW*SW];
__device__ __align__(16) float g_wo[NB*NC*HW];
__device__ __align__(16) float g_ho[NB*NC*HW];

// ---------------- tf32 mma helpers ----------------------------------------
__device__ __forceinline__ unsigned f2tf32(float x){
    unsigned r; asm("cvt.rna.tf32.f32 %0, %1;" : "=r"(r) : "f"(x)); return r;
}
__device__ __forceinline__ float4 tf4(float4 v){
    float4 o;
    o.x = __uint_as_float(f2tf32(v.x));
    o.y = __uint_as_float(f2tf32(v.y));
    o.z = __uint_as_float(f2tf32(v.z));
    o.w = __uint_as_float(f2tf32(v.w));
    return o;
}
__device__ __forceinline__ void mma_tf32(float* d, const unsigned* a, const unsigned* b){
    asm volatile("mma.sync.aligned.m16n8k8.row.col.f32.tf32.tf32.f32 "
        "{%0,%1,%2,%3}, {%4,%5,%6,%7}, {%8,%9}, {%0,%1,%2,%3};\n"
        : "+f"(d[0]), "+f"(d[1]), "+f"(d[2]), "+f"(d[3])
        : "r"(a[0]), "r"(a[1]), "r"(a[2]), "r"(a[3]), "r"(b[0]), "r"(b[1]));
}

// ---------------- prep: combine 3 strip kernels, fold BN, row biases ------
__global__ void prep_kernel(int side,
    const float* __restrict__ w7,  const float* __restrict__ b7,
    const float* __restrict__ w11, const float* __restrict__ b11,
    const float* __restrict__ w21, const float* __restrict__ b21,
    const float* __restrict__ bng, const float* __restrict__ bnb,
    const float* __restrict__ bnm, const float* __restrict__ bnv)
{
    float* Wout  = side ? g_Ww  : g_Wh;
    float* rbout = side ? g_rbw : g_rbh;
    int co = blockIdx.x;
    int tid = threadIdx.x;
    __shared__ float Wraw[NC*KT];
    __shared__ float Pfx[NC*(KT+1)];

    for (int idx = tid; idx < NC*KT; idx += blockDim.x){
        int ci = idx / KT, t = idx % KT;
        float v = w21[(co*NC+ci)*21 + t];
        if (t >= 5 && t < 16) v += w11[(co*NC+ci)*11 + (t-5)];
        if (t >= 7 && t < 14) v += w7 [(co*NC+ci)*7  + (t-7)];
        Wraw[idx] = v;
        float a = bng[ci] * rsqrtf(bnv[ci] + 1e-5f);
        Wout[t*NC*NC + ci*NC + co] = __uint_as_float(f2tf32(v * a));  // [t][ci][co], tf32
    }
    __syncthreads();
    if (tid < NC){
        int ci = tid;
        float a = bng[ci] * rsqrtf(bnv[ci] + 1e-5f);
        float c = bnb[ci] - bnm[ci] * a;
        float s = 0.f;
        Pfx[ci*(KT+1)] = 0.f;
        for (int t = 0; t < KT; t++){
            s += Wraw[ci*KT + t] * c;
            Pfx[ci*(KT+1) + t + 1] = s;
        }
    }
    __syncthreads();
    float cb = b7[co] + b11[co] + b21[co];
    for (int h = tid; h < SH; h += blockDim.x){
        int t0 = 10 - h;  if (t0 < 0) t0 = 0;
        int t1 = 137 - h; if (t1 > KT-1) t1 = KT-1;
        float s = cb;
        for (int ci = 0; ci < NC; ci++)
            s += Pfx[ci*(KT+1) + t1 + 1] - Pfx[ci*(KT+1) + t0];
        rbout[co*SH + h] = s;
    }
}

// ======================= conv_h via tf32 mma ===============================
// Block: 2 output rows (h0, h0+1), C[64co][256px]. 8 warps: r=wid>>2, pxq=(wid&3)*32.
// Warp tile 64co x 32px: m-tiles i=0..3 (16co), n-tiles j=0..3 (8px).
// smem: Xs 3 slots [64ci][136] rolling rows; As double [64ci][72].
#define XH_STR 136
#define XH_SLOT (NC*XH_STR)          // 8704
#define AS_STR 72
#define AS_SLAB (NC*AS_STR)          // 4608
__global__ __launch_bounds__(256, 1) void conv_h_kernel(const float* __restrict__ x)
{
    extern __shared__ float sm[];
    float* Xs = sm;                          // 3*8704 = 26112
    float* As = sm + 3*XH_SLOT;              // 2*4608
    int h0 = blockIdx.x * 2, b = blockIdx.y;
    int tid = threadIdx.x;
    int wid = tid >> 5, lid = tid & 31;
    int gid = lid >> 2, tig = lid & 3;
    int r = wid >> 2, pxq = (wid & 3) * 32;
    const float* xb = x + b*NC*HW;

    // initial rows h0-10 -> slot0, h0-9 -> slot1 (tf32-rounded)
    #pragma unroll
    for (int rr = 0; rr < 2; rr++){
        int row = h0 - 10 + rr;
        float* dst = Xs + rr*XH_SLOT;
        if ((unsigned)row < 128u){
            #pragma unroll
            for (int i = 0; i < 8; i++){
                int idx4 = tid + i*256;
                int ci = idx4 >> 5, w4 = idx4 & 31;
                float4 v = *(const float4*)(xb + ci*HW + row*SW + w4*4);
                *(float4*)(dst + ci*XH_STR + w4*4) = tf4(v);
            }
        } else {
            float4 z = {0.f,0.f,0.f,0.f};
            #pragma unroll
            for (int i = 0; i < 8; i++){
                int idx4 = tid + i*256;
                int ci = idx4 >> 5, w4 = idx4 & 31;
                *(float4*)(dst + ci*XH_STR + w4*4) = z;
            }
        }
    }
    float4 wreg[4];
    {
        const float4* ws = (const float4*)g_Wh;
        #pragma unroll
        for (int i = 0; i < 4; i++) wreg[i] = ws[tid + i*256];
    }

    float d[4][4][4];
    #pragma unroll
    for (int i = 0; i < 4; i++)
        #pragma unroll
        for (int j = 0; j < 4; j++)
            #pragma unroll
            for (int k = 0; k < 4; k++) d[i][j][k] = 0.f;

    #pragma unroll 1
    for (int t = 0; t < KT; t++){
        float* Ab = As + (t & 1)*AS_SLAB;
        #pragma unroll
        for (int i = 0; i < 4; i++){
            int idx4 = tid + i*256;
            int ci = idx4 >> 4, co4 = idx4 & 15;
            *(float4*)(Ab + ci*AS_STR + co4*4) = wreg[i];
        }
        if (t < KT-1){
            const float4* ws = (const float4*)(g_Wh + (t+1)*4096);
            #pragma unroll
            for (int i = 0; i < 4; i++) wreg[i] = ws[tid + i*256];
        }
        // prefetch next needed row h0+t-8 into regs
        float4 xr[8];
        int nrow = h0 + t - 8;
        if (t < KT-1){
            if ((unsigned)nrow < 128u){
                #pragma unroll
                for (int i = 0; i < 8; i++){
                    int idx4 = tid + i*256;
                    int ci = idx4 >> 5, w4 = idx4 & 31;
                    xr[i] = *(const float4*)(xb + ci*HW + nrow*SW + w4*4);
                }
            } else {
                float4 z = {0.f,0.f,0.f,0.f};
                #pragma unroll
                for (int i = 0; i < 8; i++) xr[i] = z;
            }
        }
        __syncthreads();
        // compute tap t: warp reads slot (t+r)%3
        const unsigned* Au = (const unsigned*)Ab;
        const unsigned* xu = (const unsigned*)(Xs + ((t + r) % 3)*XH_SLOT) + pxq + gid;
        #pragma unroll 2
        for (int c8 = 0; c8 < 8; c8++){
            int ci0 = c8*8;
            unsigned af[4][4];
            #pragma unroll
            for (int i = 0; i < 4; i++){
                int r0 = (ci0+tig)*AS_STR + i*16 + gid;
                int r1 = (ci0+tig+4)*AS_STR + i*16 + gid;
                af[i][0] = Au[r0]; af[i][1] = Au[r0+8];
                af[i][2] = Au[r1]; af[i][3] = Au[r1+8];
            }
            unsigned bf[4][2];
            #pragma unroll
            for (int j = 0; j < 4; j++){
                bf[j][0] = xu[(ci0+tig)*XH_STR + j*8];
                bf[j][1] = xu[(ci0+tig+4)*XH_STR + j*8];
            }
            #pragma unroll
            for (int i = 0; i < 4; i++)
                #pragma unroll
                for (int j = 0; j < 4; j++)
                    mma_tf32(d[i][j], af[i], bf[j]);
        }
        // store prefetched row into slot (t+2)%3 (not read this tap)
        if (t < KT-1){
            float* ds = Xs + ((t + 2) % 3)*XH_SLOT;
            #pragma unroll
            for (int i = 0; i < 8; i++){
                int idx4 = tid + i*256;
                int ci = idx4 >> 5, w4 = idx4 & 31;
                *(float4*)(ds + ci*XH_STR + w4*4) = tf4(xr[i]);
            }
        }
    }
    // epilogue: stage C[co][col] (col = r*128+px) into smem, then coalesced store
    __syncthreads();
    float* S = Xs;                          // 64*264 = 16896 <= 26112
    #pragma unroll
    for (int i = 0; i < 4; i++)
        #pragma unroll
        for (int j = 0; j < 4; j++){
            int co = i*16 + gid;
            int col = r*128 + pxq + j*8 + tig*2;
            *(float2*)&S[co*264 + col]     = make_float2(d[i][j][0], d[i][j][1]);
            *(float2*)&S[(co+8)*264 + col] = make_float2(d[i][j][2], d[i][j][3]);
        }
    __syncthreads();
    #pragma unroll
    for (int i = 0; i < 16; i++){
        int idx4 = tid + i*256;
        int co = idx4 >> 6, rem = idx4 & 63;
        int row = rem >> 5, w4 = rem & 31;
        float4 v = *(float4*)&S[co*264 + row*128 + w4*4];
        float rb = g_rbh[co*SH + h0 + row];
        v.x += rb; v.y += rb; v.z += rb; v.w += rb;
        *(float4*)(g_sch + (b*NC + co)*HW + (h0+row)*SW + w4*4) = v;
    }
}

// ======================= conv_w via tf32 mma ===============================
// Block: 2 rows, X resident [64ci][360] (center at +12, row r at +r*176).
#define XW_STR 360
__global__ __launch_bounds__(256, 1) void conv_w_kernel(const float* __restrict__ x)
{
    extern __shared__ float sm[];
    float* Xs = sm;                          // 64*360 = 23040
    float* As = sm + NC*XW_STR;              // 2*4608
    int h0 = blockIdx.x * 2, b = blockIdx.y;
    int tid = threadIdx.x;
    int wid = tid >> 5, lid = tid & 31;
    int gid = lid >> 2, tig = lid & 3;
    int r = wid >> 2, pxq = (wid & 3) * 32;
    const float* xb = x + b*NC*HW;

    {   // zero pads then fill center (tf32-rounded)
        float4 z = {0.f,0.f,0.f,0.f};
        for (int i = tid; i < NC*XW_STR/4; i += 256) ((float4*)Xs)[i] = z;
    }
    __syncthreads();
    #pragma unroll
    for (int i = 0; i < 16; i++){
        int idx4 = tid + i*256;
        int ci = idx4 >> 6, rem = idx4 & 63;
        int row = rem >> 5, w4 = rem & 31;
        float4 v = *(const float4*)(xb + ci*HW + (h0+row)*SW + w4*4);
        *(float4*)(Xs + ci*XW_STR + row*176 + 12 + w4*4) = tf4(v);
    }
    float4 wreg[4];
    {
        const float4* ws = (const float4*)g_Ww;
        #pragma unroll
        for (int i = 0; i < 4; i++) wreg[i] = ws[tid + i*256];
    }

    float d[4][4][4];
    #pragma unroll
    for (int i = 0; i < 4; i++)
        #pragma unroll
        for (int j = 0; j < 4; j++)
            #pragma unroll
            for (int k = 0; k < 4; k++) d[i][j][k] = 0.f;

    #pragma unroll 1
    for (int t = 0; t < KT; t++){
        float* Ab = As + (t & 1)*AS_SLAB;
        #pragma unroll
        for (int i = 0; i < 4; i++){
            int idx4 = tid + i*256;
            int ci = idx4 >> 4, co4 = idx4 & 15;
            *(float4*)(Ab + ci*AS_STR + co4*4) = wreg[i];
        }
        if (t < KT-1){
            const float4* ws = (const float4*)(g_Ww + (t+1)*4096);
            #pragma unroll
            for (int i = 0; i < 4; i++) wreg[i] = ws[tid + i*256];
        }
        __syncthreads();
        const unsigned* Au = (const unsigned*)Ab;
        const unsigned* xu = (const unsigned*)Xs + r*176 + 12 + pxq + gid + t - 10;
        #pragma unroll 2
        for (int c8 = 0; c8 < 8; c8++){
            int ci0 = c8*8;
            unsigned af[4][4];
            #pragma unroll
            for (int i = 0; i < 4; i++){
                int r0 = (ci0+tig)*AS_STR + i*16 + gid;
                int r1 = (ci0+tig+4)*AS_STR + i*16 + gid;
                af[i][0] = Au[r0]; af[i][1] = Au[r0+8];
                af[i][2] = Au[r1]; af[i][3] = Au[r1+8];
            }
            unsigned bf[4][2];
            #pragma unroll
            for (int j = 0; j < 4; j++){
                bf[j][0] = xu[(ci0+tig)*XW_STR + j*8];
                bf[j][1] = xu[(ci0+tig+4)*XW_STR + j*8];
            }
            #pragma unroll
            for (int i = 0; i < 4; i++)
                #pragma unroll
                for (int j = 0; j < 4; j++)
                    mma_tf32(d[i][j], af[i], bf[j]);
        }
    }
    // epilogue
    __syncthreads();
    float* S = Xs;                           // 64*264 = 16896 <= 23040
    #pragma unroll
    for (int i = 0; i < 4; i++)
        #pragma unroll
        for (int j = 0; j < 4; j++){
            int co = i*16 + gid;
            int col = r*128 + pxq + j*8 + tig*2;
            *(float2*)&S[co*264 + col]     = make_float2(d[i][j][0], d[i][j][1]);
            *(float2*)&S[(co+8)*264 + col] = make_float2(d[i][j][2], d[i][j][3]);
        }
    __syncthreads();
    #pragma unroll
    for (int i = 0; i < 16; i++){
        int idx4 = tid + i*256;
        int co = idx4 >> 6, rem = idx4 & 63;
        int row = rem >> 5, w4 = rem & 31;
        float4 v = *(float4*)&S[co*264 + row*128 + w4*4];
        float4 bb = *(const float4*)(g_rbw + co*SW + w4*4);
        v.x += bb.x; v.y += bb.y; v.z += bb.z; v.w += bb.w;
        *(float4*)(g_scw + (b*NC + co)*HW + (h0+row)*SW + w4*4) = v;
    }
}

// ---------------- 1x1 qkv projection 64 -> 192 ----------------------------
__global__ __launch_bounds__(128) void pw_kernel(int which, const float* __restrict__ w,
                          const float* __restrict__ bias)
{
    extern __shared__ float sm[];
    float* Ws = sm;            // [ci][o pad 68] = 4352 words
    float* Xs = sm + 4352;     // [ci][128] = 8192 words
    const float* sc = which ? g_scw : g_sch;
    float* out = which ? g_wqkv : g_hqkv;
    int pt = blockIdx.x, b = blockIdx.y, og = blockIdx.z;
    int px0 = pt * 128;
    int tid = threadIdx.x, ty = tid >> 4, tx = tid & 15;

    #pragma unroll
    for (int i = 0; i < 32; i++){
        int idx = tid + i*128;
        int o = idx >> 6, ci = idx & 63;
        Ws[ci*68 + o] = w[og*4096 + idx];
    }
    {
        #pragma unroll
        for (int i = 0; i < 16; i++){
            int idx4 = tid + i*128;
            int ci = idx4 >> 5, p4 = idx4 & 31;
            ((float4*)Xs)[idx4] = *(const float4*)(sc + (b*NC + ci)*HW + px0 + p4*4);
        }
    }
    __syncthreads();
    float acc[8][8];
    #pragma unroll
    for (int r = 0; r < 8; r++)
        #pragma unroll
        for (int j = 0; j < 8; j++) acc[r][j] = 0.f;
    const float4* Xq = (const float4*)Xs;
    #pragma unroll 4
    for (int ci = 0; ci < NC; ci++){
        float4 a0 = *(const float4*)(Ws + ci*68 + ty*8);
        float4 a1 = *(const float4*)(Ws + ci*68 + ty*8 + 4);
        float4 x0 = Xq[ci*32 + tx];
        float4 x1 = Xq[ci*32 + tx + 16];
        float a[8] = {a0.x,a0.y,a0.z,a0.w,a1.x,a1.y,a1.z,a1.w};
        float xv[8] = {x0.x,x0.y,x0.z,x0.w,x1.x,x1.y,x1.z,x1.w};
        #pragma unroll
        for (int r = 0; r < 8; r++)
            #pragma unroll
            for (int j = 0; j < 8; j++)
                acc[r][j] = fmaf(a[r], xv[j], acc[r][j]);
    }
    #pragma unroll
    for (int r = 0; r < 8; r++){
        int o = og*64 + ty*8 + r;
        float bv = bias[o];
        float* ob = out + (b*192 + o)*HW + px0;
        float4 v0 = {acc[r][0]+bv, acc[r][1]+bv, acc[r][2]+bv, acc[r][3]+bv};
        float4 v1 = {acc[r][4]+bv, acc[r][5]+bv, acc[r][6]+bv, acc[r][7]+bv};
        *(float4*)(ob + tx*4)      = v0;
        *(float4*)(ob + tx*4 + 64) = v1;
    }
}

// ---------------- P partials: both branches, K split 4 --------------------
__global__ __launch_bounds__(256) void gemm_p_kernel()
{
    __shared__ __align__(16) float As[16*128];
    __shared__ __align__(16) float Bs[16*128];
    int pair = blockIdx.x, ks = blockIdx.y, which = blockIdx.z;
    int b = pair >> 3, nh = pair & 7;
    const float* A  = which ? g_wqkv : g_hqkv;   // q-side
    const float* Bm = which ? g_hqkv : g_wqkv;   // v-side
    int tid = threadIdx.x, ty = tid >> 4, tx = tid & 15;
    float acc[8][8];
    #pragma unroll
    for (int r = 0; r < 8; r++)
        #pragma unroll
        for (int j = 0; j < 8; j++) acc[r][j] = 0.f;
    const float* abase = A  + (b*192 + nh*24 + 0 )*HW + ks*256*SW;
    const float* bbase = Bm + (b*192 + nh*24 + 16)*HW + ks*256*SW;

    #pragma unroll 1
    for (int k0 = 0; k0 < 256; k0 += 16){
        const float4* ap = (const float4*)(abase + k0*SW);
        const float4* bp = (const float4*)(bbase + k0*SW);
        #pragma unroll
        for (int i = 0; i < 2; i++){
            ((float4*)As)[tid + i*256] = ap[tid + i*256];
            ((float4*)Bs)[tid + i*256] = bp[tid + i*256];
        }
        __syncthreads();
        const float4* Aq = (const float4*)As;
        const float4* Bq = (const float4*)Bs;
        #pragma unroll
        for (int k = 0; k < 16; k++){
            float4 a0 = Aq[k*32 + ty];
            float4 a1 = Aq[k*32 + ty + 16];
            float4 b0 = Bq[k*32 + tx];
            float4 b1 = Bq[k*32 + tx + 16];
            float a[8] = {a0.x,a0.y,a0.z,a0.w,a1.x,a1.y,a1.z,a1.w};
            float bb[8] = {b0.x,b0.y,b0.z,b0.w,b1.x,b1.y,b1.z,b1.w};
            #pragma unroll
            for (int r = 0; r < 8; r++)
                #pragma unroll
                for (int j = 0; j < 8; j++)
                    acc[r][j] = fmaf(a[r], bb[j], acc[r][j]);
        }
        __syncthreads();
    }
    float* pp = g_Pp + ((which*64 + pair)*4 + ks)*16384;
    #pragma unroll
    for (int r = 0; r < 8; r++){
        int row = ty*4 + (r & 3) + (r >= 4 ? 64 : 0);
        float4 v0 = {acc[r][0], acc[r][1], acc[r][2], acc[r][3]};
        float4 v1 = {acc[r][4], acc[r][5], acc[r][6], acc[r][7]};
        *(float4*)(pp + row*128 + tx*4)      = v0;
        *(float4*)(pp + row*128 + tx*4 + 64) = v1;
    }
}

// ---------------- o = scale * k @ (sum of P partials) ---------------------
__global__ __launch_bounds__(256) void gemm_o_kernel()
{
    __shared__ __align__(16) float As[16*132];
    __shared__ __align__(16) float Bs[16*128];
    int jt = blockIdx.x, pair = blockIdx.y, which = blockIdx.z;
    int b = pair >> 3, nh = pair & 7;
    const float* Kt = which ? g_hqkv : g_wqkv;
    float* out = which ? g_ho : g_wo;
    int tid = threadIdx.x, ty = tid >> 4, tx = tid & 15;
    const float* kb = Kt + (b*192 + nh*24 + 8 + jt)*HW;
    const float* pb = g_Pp + (which*64 + pair)*4*16384;
    float acc[8][8];
    #pragma unroll
    for (int r = 0; r < 8; r++)
        #pragma unroll
        for (int j = 0; j < 8; j++) acc[r][j] = 0.f;

    #pragma unroll 1
    for (int k0 = 0; k0 < 128; k0 += 16){
        #pragma unroll
        for (int i = 0; i < 8; i++){
            int idx = tid + i*256;
            int j = idx >> 4, k = idx & 15;
            As[k*132 + j] = kb[j*128 + k0 + k];   // transpose on store
        }
        #pragma unroll
        for (int i = 0; i < 2; i++){
            int idx4 = tid + i*256;
            float4 p0 = ((const float4*)(pb             ))[k0*32 + idx4];
            float4 p1 = ((const float4*)(pb + 16384     ))[k0*32 + idx4];
            float4 p2 = ((const float4*)(pb + 2*16384   ))[k0*32 + idx4];
            float4 p3 = ((const float4*)(pb + 3*16384   ))[k0*32 + idx4];
            float4 s = {p0.x+p1.x+p2.x+p3.x, p0.y+p1.y+p2.y+p3.y,
                        p0.z+p1.z+p2.z+p3.z, p0.w+p1.w+p2.w+p3.w};
            ((float4*)Bs)[idx4] = s;
        }
        __syncthreads();
        const float4* Bq = (const float4*)Bs;
        #pragma unroll
        for (int k = 0; k < 16; k++){
            float4 a0 = *(const float4*)(As + k*132 + ty*4);
            float4 a1 = *(const float4*)(As + k*132 + ty*4 + 64);
            float4 b0 = Bq[k*32 + tx];
            float4 b1 = Bq[k*32 + tx + 16];
            float a[8] = {a0.x,a0.y,a0.z,a0.w,a1.x,a1.y,a1.z,a1.w};
            float bb[8] = {b0.x,b0.y,b0.z,b0.w,b1.x,b1.y,b1.z,b1.w};
            #pragma unroll
            for (int r = 0; r < 8; r++)
                #pragma unroll
                for (int j = 0; j < 8; j++)
                    acc[r][j] = fmaf(a[r], bb[j], acc[r][j]);
        }
        __syncthreads();
    }
    const float scale = 0.707106781186547524f;   // D * H^-0.5
    float* ob = out + (b*NC + nh*8 + jt)*HW;
    #pragma unroll
    for (int r = 0; r < 8; r++){
        int row = ty*4 + (r & 3) + (r >= 4 ? 64 : 0);   // h index
        float4 v0 = {acc[r][0]*scale, acc[r][1]*scale, acc[r][2]*scale, acc[r][3]*scale};
        float4 v1 = {acc[r][4]*scale, acc[r][5]*scale, acc[r][6]*scale, acc[r][7]*scale};
        *(float4*)(ob + row*SW + tx*4)      = v0;
        *(float4*)(ob + row*SW + tx*4 + 64) = v1;
    }
}

// ---------------- epilogue: out-projections + sigmoid gate ----------------
__global__ __launch_bounds__(128) void epi_kernel(const float* __restrict__ x,
    const float* __restrict__ wow, const float* __restrict__ wob,
    const float* __restrict__ how, const float* __restrict__ hob,
    float* __restrict__ out)
{
    extern __shared__ float sm[];
    float* Ws = sm;              // [ci][o pad 68]
    float* Hs = sm + 4352;
    float* Xw = sm + 8704;       // [16][128]
    float* Xh = sm + 8704 + 2048;
    int pt = blockIdx.x, b = blockIdx.y;
    int px0 = pt * 128;
    int tid = threadIdx.x, ty = tid >> 4, tx = tid & 15;

    #pragma unroll
    for (int i = 0; i < 32; i++){
        int idx = tid + i*128;
        int o = idx >> 6, ci = idx & 63;
        Ws[ci*68 + o] = wow[idx];
        Hs[ci*68 + o] = how[idx];
    }
    float acc[8][8];
    #pragma unroll
    for (int r = 0; r < 8; r++)
        #pragma unroll
        for (int j = 0; j < 8; j++) acc[r][j] = 0.f;

    #pragma unroll 1
    for (int kc = 0; kc < 4; kc++){
        if (kc) __syncthreads();
        #pragma unroll
        for (int i = 0; i < 4; i++){
            int idx4 = tid + i*128;
            int ci = idx4 >> 5, p4 = idx4 & 31;
            ((float4*)Xw)[idx4] = *(const float4*)(g_wo + (b*NC + kc*16 + ci)*HW + px0 + p4*4);
            ((float4*)Xh)[idx4] = *(const float4*)(g_ho + (b*NC + kc*16 + ci)*HW + px0 + p4*4);
        }
        __syncthreads();
        const float4* Xwq = (const float4*)Xw;
        const float4* Xhq = (const float4*)Xh;
        #pragma unroll 2
        for (int c16 = 0; c16 < 16; c16++){
            int ci = kc*16 + c16;
            float4 aw0 = *(const float4*)(Ws + ci*68 + ty*8);
            float4 aw1 = *(const float4*)(Ws + ci*68 + ty*8 + 4);
            float4 ah0 = *(const float4*)(Hs + ci*68 + ty*8);
            float4 ah1 = *(const float4*)(Hs + ci*68 + ty*8 + 4);
            float4 xw0 = Xwq[c16*32 + tx];
            float4 xw1 = Xwq[c16*32 + tx + 16];
            float4 xh0 = Xhq[c16*32 + tx];
            float4 xh1 = Xhq[c16*32 + tx + 16];
            float aw[8] = {aw0.x,aw0.y,aw0.z,aw0.w,aw1.x,aw1.y,aw1.z,aw1.w};
            float ah[8] = {ah0.x,ah0.y,ah0.z,ah0.w,ah1.x,ah1.y,ah1.z,ah1.w};
            float xwv[8] = {xw0.x,xw0.y,xw0.z,xw0.w,xw1.x,xw1.y,xw1.z,xw1.w};
            float xhv[8] = {xh0.x,xh0.y,xh0.z,xh0.w,xh1.x,xh1.y,xh1.z,xh1.w};
            #pragma unroll
            for (int r = 0; r < 8; r++)
                #pragma unroll
                for (int j = 0; j < 8; j++){
                    acc[r][j] = fmaf(aw[r], xwv[j], acc[r][j]);
                    acc[r][j] = fmaf(ah[r], xhv[j], acc[r][j]);
                }
        }
    }
    #pragma unroll
    for (int r = 0; r < 8; r++){
        int c = ty*8 + r;
        float bv = wob[c] + hob[c];
        const float* xb = x + (b*NC + c)*HW + px0;
        float* ob = out + (b*NC + c)*HW + px0;
        #pragma unroll
        for (int half = 0; half < 2; half++){
            float4 xv = *(const float4*)(xb + tx*4 + half*64);
            float vs[4];
            #pragma unroll
            for (int j = 0; j < 4; j++){
                float s = acc[r][half*4 + j] + bv;
                vs[j] = (&xv.x)[j] * (1.f / (1.f + expf(-s)));
            }
            float4 v = {vs[0], vs[1], vs[2], vs[3]};
            *(float4*)(ob + tx*4 + half*64) = v;
        }
    }
}

// ---------------- launch ---------------------------------------------------
extern "C" void kernel_launch(void* const* d_in, const int* in_sizes, int n_in,
                              void* d_out, int out_size)
{
    const float* x = (const float*)d_in[0];
    int i1w[3], i1b[3], i2w[3], i2b[3];
    if (in_sizes[11] == 45056){ // reference-signature order
        i1w[0]=9;  i1w[1]=11; i1w[2]=13;  i1b[0]=10; i1b[1]=12; i1b[2]=14;
        i2w[0]=15; i2w[1]=17; i2w[2]=19;  i2b[0]=16; i2b[1]=18; i2b[2]=20;
    } else {                    // setup_inputs dict order
        i1w[0]=9;  i1w[1]=13; i1w[2]=17;  i1b[0]=10; i1b[1]=14; i1b[2]=18;
        i2w[0]=11; i2w[1]=15; i2w[2]=19;  i2b[0]=12; i2b[1]=16; i2b[2]=20;
    }
    const float* bn1g=(const float*)d_in[1]; const float* bn1b=(const float*)d_in[2];
    const float* bn1m=(const float*)d_in[3]; const float* bn1v=(const float*)d_in[4];
    const float* bn2g=(const float*)d_in[5]; const float* bn2b=(const float*)d_in[6];
    const float* bn2m=(const float*)d_in[7]; const float* bn2v=(const float*)d_in[8];
    const float* hqkvw=(const float*)d_in[21]; const float* hqkvb=(const float*)d_in[22];
    const float* wqkvw=(const float*)d_in[23]; const float* wqkvb=(const float*)d_in[24];
    const float* houtw=(const float*)d_in[25]; const float* houtb=(const float*)d_in[26];
    const float* woutw=(const float*)d_in[27]; const float* woutb=(const float*)d_in[28];

    int sm_h = (3*XH_SLOT + 2*AS_SLAB) * 4;   // 141312 B
    int sm_w = (NC*XW_STR + 2*AS_SLAB) * 4;   // 129024 B
    cudaFuncSetAttribute(conv_h_kernel, cudaFuncAttributeMaxDynamicSharedMemorySize, sm_h);
    cudaFuncSetAttribute(conv_w_kernel, cudaFuncAttributeMaxDynamicSharedMemorySize, sm_w);
    cudaFuncSetAttribute(pw_kernel,     cudaFuncAttributeMaxDynamicSharedMemorySize, 64*1024);
    cudaFuncSetAttribute(epi_kernel,    cudaFuncAttributeMaxDynamicSharedMemorySize, 64*1024);

    prep_kernel<<<NC, 128>>>(0,
        (const float*)d_in[i1w[0]], (const float*)d_in[i1b[0]],
        (const float*)d_in[i1w[1]], (const float*)d_in[i1b[1]],
        (const float*)d_in[i1w[2]], (const float*)d_in[i1b[2]],
        bn1g, bn1b, bn1m, bn1v);
    prep_kernel<<<NC, 128>>>(1,
        (const float*)d_in[i2w[0]], (const float*)d_in[i2b[0]],
        (const float*)d_in[i2w[1]], (const float*)d_in[i2b[1]],
        (const float*)d_in[i2w[2]], (const float*)d_in[i2b[2]],
        bn2g, bn2b, bn2m, bn2v);

    conv_h_kernel<<<dim3(64, NB), 256, sm_h>>>(x);
    conv_w_kernel<<<dim3(64, NB), 256, sm_w>>>(x);

    pw_kernel<<<dim3(128, NB, 3), 128, (4352 + 8192)*4>>>(0, hqkvw, hqkvb);
    pw_kernel<<<dim3(128, NB, 3), 128, (4352 + 8192)*4>>>(1, wqkvw, wqkvb);

    gemm_p_kernel<<<dim3(64, 4, 2), 256>>>();
    gemm_o_kernel<<<dim3(8, 64, 2), 256>>>();

    epi_kernel<<<dim3(128, NB), 128, (8704 + 4096)*4>>>(x, woutw, woutb, houtw, houtb,
                                                        (float*)d_out);
}

// round 5
// speedup vs baseline: 2.7973x; 1.0398x over previous
#include <cuda_runtime.h>

#define NB 8
#define NC 64
#define SH 128
#define SW 128
#define HW (SH*SW)
#define KT 21

typedef unsigned long long u64;

// ---------------- scratch (device globals; no allocations) ----------------
__device__ __align__(16) float g_Wh[KT*NC*NC];      // combined+BN-folded tf32 weights [t][ci][co]
__device__ __align__(16) float g_Ww[KT*NC*NC];
__device__ __align__(16) float g_rbh[NC*SH];
__device__ __align__(16) float g_rbw[NC*SW];
__device__ __align__(16) float g_sch[NB*NC*HW];
__device__ __align__(16) float g_scw[NB*NC*HW];
__device__ __align__(16) float g_hqkv[NB*192*HW];
__device__ __align__(16) float g_wqkv[NB*192*HW];
__device__ __align__(16) float g_Pp[2*64*4*SW*SW];
__device__ __align__(16) float g_wo[NB*NC*HW];
__device__ __align__(16) float g_ho[NB*NC*HW];

// ---------------- tf32 mma helpers ----------------------------------------
__device__ __forceinline__ unsigned f2tf32(float x){
    unsigned r; asm("cvt.rna.tf32.f32 %0, %1;" : "=r"(r) : "f"(x)); return r;
}
__device__ __forceinline__ float4 tf4(float4 v){
    float4 o;
    o.x = __uint_as_float(f2tf32(v.x));
    o.y = __uint_as_float(f2tf32(v.y));
    o.z = __uint_as_float(f2tf32(v.z));
    o.w = __uint_as_float(f2tf32(v.w));
    return o;
}
__device__ __forceinline__ void mma_tf32(float* d, const unsigned* a, const unsigned* b){
    asm volatile("mma.sync.aligned.m16n8k8.row.col.f32.tf32.tf32.f32 "
        "{%0,%1,%2,%3}, {%4,%5,%6,%7}, {%8,%9}, {%0,%1,%2,%3};\n"
        : "+f"(d[0]), "+f"(d[1]), "+f"(d[2]), "+f"(d[3])
        : "r"(a[0]), "r"(a[1]), "r"(a[2]), "r"(a[3]), "r"(b[0]), "r"(b[1]));
}

// ---------------- f32x2 packed fma helpers (exact fp32 math) ---------------
__device__ __forceinline__ u64 pack2(float x, float y){
    u64 r; asm("mov.b64 %0, {%1,%2};" : "=l"(r) : "f"(x), "f"(y)); return r;
}
__device__ __forceinline__ void ffma2(u64& d, u64 a, u64 b){
    asm("fma.rn.f32x2 %0, %1, %2, %0;" : "+l"(d) : "l"(a), "l"(b));
}
__device__ __forceinline__ float2 unpack2(u64 d){
    float2 f; asm("mov.b64 {%0,%1}, %2;" : "=f"(f.x), "=f"(f.y) : "l"(d)); return f;
}

// ---------------- prep: combine 3 strip kernels, fold BN, row biases ------
__global__ void prep_kernel(int side,
    const float* __restrict__ w7,  const float* __restrict__ b7,
    const float* __restrict__ w11, const float* __restrict__ b11,
    const float* __restrict__ w21, const float* __restrict__ b21,
    const float* __restrict__ bng, const float* __restrict__ bnb,
    const float* __restrict__ bnm, const float* __restrict__ bnv)
{
    float* Wout  = side ? g_Ww  : g_Wh;
    float* rbout = side ? g_rbw : g_rbh;
    int co = blockIdx.x;
    int tid = threadIdx.x;
    __shared__ float Wraw[NC*KT];
    __shared__ float Pfx[NC*(KT+1)];

    for (int idx = tid; idx < NC*KT; idx += blockDim.x){
        int ci = idx / KT, t = idx % KT;
        float v = w21[(co*NC+ci)*21 + t];
        if (t >= 5 && t < 16) v += w11[(co*NC+ci)*11 + (t-5)];
        if (t >= 7 && t < 14) v += w7 [(co*NC+ci)*7  + (t-7)];
        Wraw[idx] = v;
        float a = bng[ci] * rsqrtf(bnv[ci] + 1e-5f);
        Wout[t*NC*NC + ci*NC + co] = __uint_as_float(f2tf32(v * a));
    }
    __syncthreads();
    if (tid < NC){
        int ci = tid;
        float a = bng[ci] * rsqrtf(bnv[ci] + 1e-5f);
        float c = bnb[ci] - bnm[ci] * a;
        float s = 0.f;
        Pfx[ci*(KT+1)] = 0.f;
        for (int t = 0; t < KT; t++){
            s += Wraw[ci*KT + t] * c;
            Pfx[ci*(KT+1) + t + 1] = s;
        }
    }
    __syncthreads();
    float cb = b7[co] + b11[co] + b21[co];
    for (int h = tid; h < SH; h += blockDim.x){
        int t0 = 10 - h;  if (t0 < 0) t0 = 0;
        int t1 = 137 - h; if (t1 > KT-1) t1 = KT-1;
        float s = cb;
        for (int ci = 0; ci < NC; ci++)
            s += Pfx[ci*(KT+1) + t1 + 1] - Pfx[ci*(KT+1) + t0];
        rbout[co*SH + h] = s;
    }
}

// ======================= conv_h via tf32 mma (2 CTA/SM) ====================
// 2-slot rolling row buffer + single-buffered A; 2 syncs/tap.
#define XH_STR 136
#define XH_SLOT (NC*XH_STR)          // 8704
#define AS_STR 72
#define AS_SLAB (NC*AS_STR)          // 4608
__global__ __launch_bounds__(256, 2) void conv_h_kernel(const float* __restrict__ x)
{
    extern __shared__ float sm[];
    float* Xs = sm;                          // 2*8704
    float* As = sm + 2*XH_SLOT;              // 4608  -> total 22016 w = 88KB
    int h0 = blockIdx.x * 2, b = blockIdx.y;
    int tid = threadIdx.x;
    int wid = tid >> 5, lid = tid & 31;
    int gid = lid >> 2, tig = lid & 3;
    int r = wid >> 2, pxq = (wid & 3) * 32;
    const float* xb = x + b*NC*HW;

    // initial rows h0-10 -> slot0, h0-9 -> slot1 (h0 even => parity matches)
    #pragma unroll
    for (int rr = 0; rr < 2; rr++){
        int row = h0 - 10 + rr;
        float* dst = Xs + rr*XH_SLOT;
        if ((unsigned)row < 128u){
            #pragma unroll
            for (int i = 0; i < 8; i++){
                int idx4 = tid + i*256;
                int ci = idx4 >> 5, w4 = idx4 & 31;
                float4 v = *(const float4*)(xb + ci*HW + row*SW + w4*4);
                *(float4*)(dst + ci*XH_STR + w4*4) = tf4(v);
            }
        } else {
            float4 z = {0.f,0.f,0.f,0.f};
            #pragma unroll
            for (int i = 0; i < 8; i++){
                int idx4 = tid + i*256;
                int ci = idx4 >> 5, w4 = idx4 & 31;
                *(float4*)(dst + ci*XH_STR + w4*4) = z;
            }
        }
    }
    {   // A(t=0)
        const float4* ws = (const float4*)g_Wh;
        #pragma unroll
        for (int i = 0; i < 4; i++){
            int idx4 = tid + i*256;
            int ci = idx4 >> 4, co4 = idx4 & 15;
            *(float4*)(As + ci*AS_STR + co4*4) = ws[idx4];
        }
    }
    __syncthreads();

    float d[4][4][4];
    #pragma unroll
    for (int i = 0; i < 4; i++)
        #pragma unroll
        for (int j = 0; j < 4; j++)
            #pragma unroll
            for (int k = 0; k < 4; k++) d[i][j][k] = 0.f;

    #pragma unroll 1
    for (int t = 0; t < KT; t++){
        const unsigned* Au = (const unsigned*)As;
        const unsigned* xu = (const unsigned*)(Xs + ((t + r) & 1)*XH_SLOT) + pxq + gid;
        #pragma unroll 2
        for (int c8 = 0; c8 < 8; c8++){
            int ci0 = c8*8;
            unsigned af[4][4];
            #pragma unroll
            for (int i = 0; i < 4; i++){
                int r0 = (ci0+tig)*AS_STR + i*16 + gid;
                int r1 = (ci0+tig+4)*AS_STR + i*16 + gid;
                af[i][0] = Au[r0]; af[i][1] = Au[r0+8];
                af[i][2] = Au[r1]; af[i][3] = Au[r1+8];
            }
            unsigned bf[4][2];
            #pragma unroll
            for (int j = 0; j < 4; j++){
                bf[j][0] = xu[(ci0+tig)*XH_STR + j*8];
                bf[j][1] = xu[(ci0+tig+4)*XH_STR + j*8];
            }
            #pragma unroll
            for (int i = 0; i < 4; i++)
                #pragma unroll
                for (int j = 0; j < 4; j++)
                    mma_tf32(d[i][j], af[i], bf[j]);
        }
        if (t < KT-1){
            __syncthreads();
            // new row h0+t-8 -> slot t&1 (its old row is now dead)
            int nrow = h0 + t - 8;
            float* ds = Xs + (t & 1)*XH_SLOT;
            if ((unsigned)nrow < 128u){
                #pragma unroll
                for (int i = 0; i < 8; i++){
                    int idx4 = tid + i*256;
                    int ci = idx4 >> 5, w4 = idx4 & 31;
                    float4 v = *(const float4*)(xb + ci*HW + nrow*SW + w4*4);
                    *(float4*)(ds + ci*XH_STR + w4*4) = tf4(v);
                }
            } else {
                float4 z = {0.f,0.f,0.f,0.f};
                #pragma unroll
                for (int i = 0; i < 8; i++){
                    int idx4 = tid + i*256;
                    int ci = idx4 >> 5, w4 = idx4 & 31;
                    *(float4*)(ds + ci*XH_STR + w4*4) = z;
                }
            }
            const float4* ws = (const float4*)(g_Wh + (t+1)*4096);
            #pragma unroll
            for (int i = 0; i < 4; i++){
                int idx4 = tid + i*256;
                int ci = idx4 >> 4, co4 = idx4 & 15;
                *(float4*)(As + ci*AS_STR + co4*4) = ws[idx4];
            }
            __syncthreads();
        }
    }
    // epilogue
    __syncthreads();
    float* S = Xs;                          // 64*264 = 16896 <= 17408
    #pragma unroll
    for (int i = 0; i < 4; i++)
        #pragma unroll
        for (int j = 0; j < 4; j++){
            int co = i*16 + gid;
            int col = r*128 + pxq + j*8 + tig*2;
            *(float2*)&S[co*264 + col]     = make_float2(d[i][j][0], d[i][j][1]);
            *(float2*)&S[(co+8)*264 + col] = make_float2(d[i][j][2], d[i][j][3]);
        }
    __syncthreads();
    #pragma unroll
    for (int i = 0; i < 16; i++){
        int idx4 = tid + i*256;
        int co = idx4 >> 6, rem = idx4 & 63;
        int row = rem >> 5, w4 = rem & 31;
        float4 v = *(float4*)&S[co*264 + row*128 + w4*4];
        float rb = g_rbh[co*SH + h0 + row];
        v.x += rb; v.y += rb; v.z += rb; v.w += rb;
        *(float4*)(g_sch + (b*NC + co)*HW + (h0+row)*SW + w4*4) = v;
    }
}

// ======================= conv_w via tf32 mma (2 CTA/SM) ====================
// X resident [64ci][328] (row r at +r*164, center +12); single-buffered A.
#define XW_CI 328
#define XW_ROW 164
__global__ __launch_bounds__(256, 2) void conv_w_kernel(const float* __restrict__ x)
{
    extern __shared__ float sm[];
    float* Xs = sm;                          // 64*328 = 20992
    float* As = sm + NC*XW_CI;               // 4608 -> total 25600 w = 102.4KB
    int h0 = blockIdx.x * 2, b = blockIdx.y;
    int tid = threadIdx.x;
    int wid = tid >> 5, lid = tid & 31;
    int gid = lid >> 2, tig = lid & 3;
    int r = wid >> 2, pxq = (wid & 3) * 32;
    const float* xb = x + b*NC*HW;

    {   // zero pads then fill center (tf32-rounded)
        float4 z = {0.f,0.f,0.f,0.f};
        for (int i = tid; i < NC*XW_CI/4; i += 256) ((float4*)Xs)[i] = z;
    }
    __syncthreads();
    #pragma unroll
    for (int i = 0; i < 16; i++){
        int idx4 = tid + i*256;
        int ci = idx4 >> 6, rem = idx4 & 63;
        int row = rem >> 5, w4 = rem & 31;
        float4 v = *(const float4*)(xb + ci*HW + (h0+row)*SW + w4*4);
        *(float4*)(Xs + ci*XW_CI + row*XW_ROW + 12 + w4*4) = tf4(v);
    }
    {   // A(t=0)
        const float4* ws = (const float4*)g_Ww;
        #pragma unroll
        for (int i = 0; i < 4; i++){
            int idx4 = tid + i*256;
            int ci = idx4 >> 4, co4 = idx4 & 15;
            *(float4*)(As + ci*AS_STR + co4*4) = ws[idx4];
        }
    }
    __syncthreads();

    float d[4][4][4];
    #pragma unroll
    for (int i = 0; i < 4; i++)
        #pragma unroll
        for (int j = 0; j < 4; j++)
            #pragma unroll
            for (int k = 0; k < 4; k++) d[i][j][k] = 0.f;

    #pragma unroll 1
    for (int t = 0; t < KT; t++){
        const unsigned* Au = (const unsigned*)As;
        const unsigned* xu = (const unsigned*)Xs + r*XW_ROW + 12 + pxq + gid + t - 10;
        #pragma unroll 2
        for (int c8 = 0; c8 < 8; c8++){
            int ci0 = c8*8;
            unsigned af[4][4];
            #pragma unroll
            for (int i = 0; i < 4; i++){
                int r0 = (ci0+tig)*AS_STR + i*16 + gid;
                int r1 = (ci0+tig+4)*AS_STR + i*16 + gid;
                af[i][0] = Au[r0]; af[i][1] = Au[r0+8];
                af[i][2] = Au[r1]; af[i][3] = Au[r1+8];
            }
            unsigned bf[4][2];
            #pragma unroll
            for (int j = 0; j < 4; j++){
                bf[j][0] = xu[(ci0+tig)*XW_CI + j*8];
                bf[j][1] = xu[(ci0+tig+4)*XW_CI + j*8];
            }
            #pragma unroll
            for (int i = 0; i < 4; i++)
                #pragma unroll
                for (int j = 0; j < 4; j++)
                    mma_tf32(d[i][j], af[i], bf[j]);
        }
        if (t < KT-1){
            __syncthreads();
            const float4* ws = (const float4*)(g_Ww + (t+1)*4096);
            #pragma unroll
            for (int i = 0; i < 4; i++){
                int idx4 = tid + i*256;
                int ci = idx4 >> 4, co4 = idx4 & 15;
                *(float4*)(As + ci*AS_STR + co4*4) = ws[idx4];
            }
            __syncthreads();
        }
    }
    // epilogue
    __syncthreads();
    float* S = Xs;                           // 64*264 = 16896 <= 20992
    #pragma unroll
    for (int i = 0; i < 4; i++)
        #pragma unroll
        for (int j = 0; j < 4; j++){
            int co = i*16 + gid;
            int col = r*128 + pxq + j*8 + tig*2;
            *(float2*)&S[co*264 + col]     = make_float2(d[i][j][0], d[i][j][1]);
            *(float2*)&S[(co+8)*264 + col] = make_float2(d[i][j][2], d[i][j][3]);
        }
    __syncthreads();
    #pragma unroll
    for (int i = 0; i < 16; i++){
        int idx4 = tid + i*256;
        int co = idx4 >> 6, rem = idx4 & 63;
        int row = rem >> 5, w4 = rem & 31;
        float4 v = *(float4*)&S[co*264 + row*128 + w4*4];
        float4 bb = *(const float4*)(g_rbw + co*SW + w4*4);
        v.x += bb.x; v.y += bb.y; v.z += bb.z; v.w += bb.w;
        *(float4*)(g_scw + (b*NC + co)*HW + (h0+row)*SW + w4*4) = v;
    }
}

// ---------------- 1x1 qkv projection 64 -> 192 (f32x2) ---------------------
__global__ __launch_bounds__(128) void pw_kernel(int which, const float* __restrict__ w,
                          const float* __restrict__ bias)
{
    extern __shared__ float sm[];
    float* Ws = sm;            // [ci][o pad 68]
    float* Xs = sm + 4352;     // [ci][128]
    const float* sc = which ? g_scw : g_sch;
    float* out = which ? g_wqkv : g_hqkv;
    int pt = blockIdx.x, b = blockIdx.y, og = blockIdx.z;
    int px0 = pt * 128;
    int tid = threadIdx.x, ty = tid >> 4, tx = tid & 15;

    #pragma unroll
    for (int i = 0; i < 32; i++){
        int idx = tid + i*128;
        int o = idx >> 6, ci = idx & 63;
        Ws[ci*68 + o] = w[og*4096 + idx];
    }
    #pragma unroll
    for (int i = 0; i < 16; i++){
        int idx4 = tid + i*128;
        int ci = idx4 >> 5, p4 = idx4 & 31;
        ((float4*)Xs)[idx4] = *(const float4*)(sc + (b*NC + ci)*HW + px0 + p4*4);
    }
    __syncthreads();
    u64 acc2[8][4];
    #pragma unroll
    for (int r = 0; r < 8; r++)
        #pragma unroll
        for (int j = 0; j < 4; j++) acc2[r][j] = 0ull;
    const float4* Xq = (const float4*)Xs;
    #pragma unroll 4
    for (int ci = 0; ci < NC; ci++){
        float4 a0 = *(const float4*)(Ws + ci*68 + ty*8);
        float4 a1 = *(const float4*)(Ws + ci*68 + ty*8 + 4);
        float4 x0 = Xq[ci*32 + tx];
        float4 x1 = Xq[ci*32 + tx + 16];
        u64 da[8] = {pack2(a0.x,a0.x), pack2(a0.y,a0.y), pack2(a0.z,a0.z), pack2(a0.w,a0.w),
                     pack2(a1.x,a1.x), pack2(a1.y,a1.y), pack2(a1.z,a1.z), pack2(a1.w,a1.w)};
        u64 xd[4] = {pack2(x0.x,x0.y), pack2(x0.z,x0.w), pack2(x1.x,x1.y), pack2(x1.z,x1.w)};
        #pragma unroll
        for (int r = 0; r < 8; r++)
            #pragma unroll
            for (int j = 0; j < 4; j++)
                ffma2(acc2[r][j], da[r], xd[j]);
    }
    #pragma unroll
    for (int r = 0; r < 8; r++){
        int o = og*64 + ty*8 + r;
        float bv = bias[o];
        float* ob = out + (b*192 + o)*HW + px0;
        float2 p0 = unpack2(acc2[r][0]), p1 = unpack2(acc2[r][1]);
        float2 p2 = unpack2(acc2[r][2]), p3 = unpack2(acc2[r][3]);
        float4 v0 = {p0.x+bv, p0.y+bv, p1.x+bv, p1.y+bv};
        float4 v1 = {p2.x+bv, p2.y+bv, p3.x+bv, p3.y+bv};
        *(float4*)(ob + tx*4)      = v0;
        *(float4*)(ob + tx*4 + 64) = v1;
    }
}

// ---------------- P partials: both branches, K split 4 (f32x2) -------------
__global__ __launch_bounds__(256) void gemm_p_kernel()
{
    __shared__ __align__(16) float As[16*128];
    __shared__ __align__(16) float Bs[16*128];
    int pair = blockIdx.x, ks = blockIdx.y, which = blockIdx.z;
    int b = pair >> 3, nh = pair & 7;
    const float* A  = which ? g_wqkv : g_hqkv;
    const float* Bm = which ? g_hqkv : g_wqkv;
    int tid = threadIdx.x, ty = tid >> 4, tx = tid & 15;
    u64 acc2[8][4];
    #pragma unroll
    for (int r = 0; r < 8; r++)
        #pragma unroll
        for (int j = 0; j < 4; j++) acc2[r][j] = 0ull;
    const float* abase = A  + (b*192 + nh*24 + 0 )*HW + ks*256*SW;
    const float* bbase = Bm + (b*192 + nh*24 + 16)*HW + ks*256*SW;

    #pragma unroll 1
    for (int k0 = 0; k0 < 256; k0 += 16){
        const float4* ap = (const float4*)(abase + k0*SW);
        const float4* bp = (const float4*)(bbase + k0*SW);
        #pragma unroll
        for (int i = 0; i < 2; i++){
            ((float4*)As)[tid + i*256] = ap[tid + i*256];
            ((float4*)Bs)[tid + i*256] = bp[tid + i*256];
        }
        __syncthreads();
        const float4* Aq = (const float4*)As;
        const float4* Bq = (const float4*)Bs;
        #pragma unroll
        for (int k = 0; k < 16; k++){
            float4 a0 = Aq[k*32 + ty];
            float4 a1 = Aq[k*32 + ty + 16];
            float4 b0 = Bq[k*32 + tx];
            float4 b1 = Bq[k*32 + tx + 16];
            u64 da[8] = {pack2(a0.x,a0.x), pack2(a0.y,a0.y), pack2(a0.z,a0.z), pack2(a0.w,a0.w),
                         pack2(a1.x,a1.x), pack2(a1.y,a1.y), pack2(a1.z,a1.z), pack2(a1.w,a1.w)};
            u64 xd[4] = {pack2(b0.x,b0.y), pack2(b0.z,b0.w), pack2(b1.x,b1.y), pack2(b1.z,b1.w)};
            #pragma unroll
            for (int r = 0; r < 8; r++)
                #pragma unroll
                for (int j = 0; j < 4; j++)
                    ffma2(acc2[r][j], da[r], xd[j]);
        }
        __syncthreads();
    }
    float* pp = g_Pp + ((which*64 + pair)*4 + ks)*16384;
    #pragma unroll
    for (int r = 0; r < 8; r++){
        int row = ty*4 + (r & 3) + (r >= 4 ? 64 : 0);
        float2 p0 = unpack2(acc2[r][0]), p1 = unpack2(acc2[r][1]);
        float2 p2 = unpack2(acc2[r][2]), p3 = unpack2(acc2[r][3]);
        float4 v0 = {p0.x, p0.y, p1.x, p1.y};
        float4 v1 = {p2.x, p2.y, p3.x, p3.y};
        *(float4*)(pp + row*128 + tx*4)      = v0;
        *(float4*)(pp + row*128 + tx*4 + 64) = v1;
    }
}

// ---------------- o = scale * k @ (sum of P partials) (f32x2) --------------
__global__ __launch_bounds__(256) void gemm_o_kernel()
{
    __shared__ __align__(16) float As[16*132];
    __shared__ __align__(16) float Bs[16*128];
    int jt = blockIdx.x, pair = blockIdx.y, which = blockIdx.z;
    int b = pair >> 3, nh = pair & 7;
    const float* Kt = which ? g_hqkv : g_wqkv;
    float* out = which ? g_ho : g_wo;
    int tid = threadIdx.x, ty = tid >> 4, tx = tid & 15;
    const float* kb = Kt + (b*192 + nh*24 + 8 + jt)*HW;
    const float* pb = g_Pp + (which*64 + pair)*4*16384;
    u64 acc2[8][4];
    #pragma unroll
    for (int r = 0; r < 8; r++)
        #pragma unroll
        for (int j = 0; j < 4; j++) acc2[r][j] = 0ull;

    #pragma unroll 1
    for (int k0 = 0; k0 < 128; k0 += 16){
        #pragma unroll
        for (int i = 0; i < 8; i++){
            int idx = tid + i*256;
            int j = idx >> 4, k = idx & 15;
            As[k*132 + j] = kb[j*128 + k0 + k];
        }
        #pragma unroll
        for (int i = 0; i < 2; i++){
            int idx4 = tid + i*256;
            float4 p0 = ((const float4*)(pb           ))[k0*32 + idx4];
            float4 p1 = ((const float4*)(pb + 16384   ))[k0*32 + idx4];
            float4 p2 = ((const float4*)(pb + 2*16384 ))[k0*32 + idx4];
            float4 p3 = ((const float4*)(pb + 3*16384 ))[k0*32 + idx4];
            float4 s = {p0.x+p1.x+p2.x+p3.x, p0.y+p1.y+p2.y+p3.y,
                        p0.z+p1.z+p2.z+p3.z, p0.w+p1.w+p2.w+p3.w};
            ((float4*)Bs)[idx4] = s;
        }
        __syncthreads();
        const float4* Bq = (const float4*)Bs;
        #pragma unroll
        for (int k = 0; k < 16; k++){
            float4 a0 = *(const float4*)(As + k*132 + ty*4);
            float4 a1 = *(const float4*)(As + k*132 + ty*4 + 64);
            float4 b0 = Bq[k*32 + tx];
            float4 b1 = Bq[k*32 + tx + 16];
            u64 da[8] = {pack2(a0.x,a0.x), pack2(a0.y,a0.y), pack2(a0.z,a0.z), pack2(a0.w,a0.w),
                         pack2(a1.x,a1.x), pack2(a1.y,a1.y), pack2(a1.z,a1.z), pack2(a1.w,a1.w)};
            u64 xd[4] = {pack2(b0.x,b0.y), pack2(b0.z,b0.w), pack2(b1.x,b1.y), pack2(b1.z,b1.w)};
            #pragma unroll
            for (int r = 0; r < 8; r++)
                #pragma unroll
                for (int j = 0; j < 4; j++)
                    ffma2(acc2[r][j], da[r], xd[j]);
        }
        __syncthreads();
    }
    const float scale = 0.707106781186547524f;
    float* ob = out + (b*NC + nh*8 + jt)*HW;
    #pragma unroll
    for (int r = 0; r < 8; r++){
        int row = ty*4 + (r & 3) + (r >= 4 ? 64 : 0);
        float2 p0 = unpack2(acc2[r][0]), p1 = unpack2(acc2[r][1]);
        float2 p2 = unpack2(acc2[r][2]), p3 = unpack2(acc2[r][3]);
        float4 v0 = {p0.x*scale, p0.y*scale, p1.x*scale, p1.y*scale};
        float4 v1 = {p2.x*scale, p2.y*scale, p3.x*scale, p3.y*scale};
        *(float4*)(ob + row*SW + tx*4)      = v0;
        *(float4*)(ob + row*SW + tx*4 + 64) = v1;
    }
}

// ---------------- epilogue: out-projections + sigmoid gate (f32x2) ---------
__global__ __launch_bounds__(128) void epi_kernel(const float* __restrict__ x,
    const float* __restrict__ wow, const float* __restrict__ wob,
    const float* __restrict__ how, const float* __restrict__ hob,
    float* __restrict__ out)
{
    extern __shared__ float sm[];
    float* Ws = sm;              // [ci][o pad 68]
    float* Hs = sm + 4352;
    float* Xw = sm + 8704;       // [16][128]
    float* Xh = sm + 8704 + 2048;
    int pt = blockIdx.x, b = blockIdx.y;
    int px0 = pt * 128;
    int tid = threadIdx.x, ty = tid >> 4, tx = tid & 15;

    #pragma unroll
    for (int i = 0; i < 32; i++){
        int idx = tid + i*128;
        int o = idx >> 6, ci = idx & 63;
        Ws[ci*68 + o] = wow[idx];
        Hs[ci*68 + o] = how[idx];
    }
    u64 acc2[8][4];
    #pragma unroll
    for (int r = 0; r < 8; r++)
        #pragma unroll
        for (int j = 0; j < 4; j++) acc2[r][j] = 0ull;

    #pragma unroll 1
    for (int kc = 0; kc < 4; kc++){
        if (kc) __syncthreads();
        #pragma unroll
        for (int i = 0; i < 4; i++){
            int idx4 = tid + i*128;
            int ci = idx4 >> 5, p4 = idx4 & 31;
            ((float4*)Xw)[idx4] = *(const float4*)(g_wo + (b*NC + kc*16 + ci)*HW + px0 + p4*4);
            ((float4*)Xh)[idx4] = *(const float4*)(g_ho + (b*NC + kc*16 + ci)*HW + px0 + p4*4);
        }
        __syncthreads();
        const float4* Xwq = (const float4*)Xw;
        const float4* Xhq = (const float4*)Xh;
        #pragma unroll 2
        for (int c16 = 0; c16 < 16; c16++){
            int ci = kc*16 + c16;
            float4 aw0 = *(const float4*)(Ws + ci*68 + ty*8);
            float4 aw1 = *(const float4*)(Ws + ci*68 + ty*8 + 4);
            float4 ah0 = *(const float4*)(Hs + ci*68 + ty*8);
            float4 ah1 = *(const float4*)(Hs + ci*68 + ty*8 + 4);
            float4 xw0 = Xwq[c16*32 + tx];
            float4 xw1 = Xwq[c16*32 + tx + 16];
            float4 xh0 = Xhq[c16*32 + tx];
            float4 xh1 = Xhq[c16*32 + tx + 16];
            u64 dw[8] = {pack2(aw0.x,aw0.x), pack2(aw0.y,aw0.y), pack2(aw0.z,aw0.z), pack2(aw0.w,aw0.w),
                         pack2(aw1.x,aw1.x), pack2(aw1.y,aw1.y), pack2(aw1.z,aw1.z), pack2(aw1.w,aw1.w)};
            u64 dh[8] = {pack2(ah0.x,ah0.x), pack2(ah0.y,ah0.y), pack2(ah0.z,ah0.z), pack2(ah0.w,ah0.w),
                         pack2(ah1.x,ah1.x), pack2(ah1.y,ah1.y), pack2(ah1.z,ah1.z), pack2(ah1.w,ah1.w)};
            u64 xwd[4] = {pack2(xw0.x,xw0.y), pack2(xw0.z,xw0.w), pack2(xw1.x,xw1.y), pack2(xw1.z,xw1.w)};
            u64 xhd[4] = {pack2(xh0.x,xh0.y), pack2(xh0.z,xh0.w), pack2(xh1.x,xh1.y), pack2(xh1.z,xh1.w)};
            #pragma unroll
            for (int r = 0; r < 8; r++)
                #pragma unroll
                for (int j = 0; j < 4; j++){
                    ffma2(acc2[r][j], dw[r], xwd[j]);
                    ffma2(acc2[r][j], dh[r], xhd[j]);
                }
        }
    }
    #pragma unroll
    for (int r = 0; r < 8; r++){
        int c = ty*8 + r;
        float bv = wob[c] + hob[c];
        const float* xb = x + (b*NC + c)*HW + px0;
        float* ob = out + (b*NC + c)*HW + px0;
        float av[8];
        float2 p0 = unpack2(acc2[r][0]), p1 = unpack2(acc2[r][1]);
        float2 p2 = unpack2(acc2[r][2]), p3 = unpack2(acc2[r][3]);
        av[0]=p0.x; av[1]=p0.y; av[2]=p1.x; av[3]=p1.y;
        av[4]=p2.x; av[5]=p2.y; av[6]=p3.x; av[7]=p3.y;
        #pragma unroll
        for (int half = 0; half < 2; half++){
            float4 xv = *(const float4*)(xb + tx*4 + half*64);
            float vs[4];
            #pragma unroll
            for (int j = 0; j < 4; j++){
                float s = av[half*4 + j] + bv;
                vs[j] = (&xv.x)[j] * (1.f / (1.f + expf(-s)));
            }
            float4 v = {vs[0], vs[1], vs[2], vs[3]};
            *(float4*)(ob + tx*4 + half*64) = v;
        }
    }
}

// ---------------- launch ---------------------------------------------------
extern "C" void kernel_launch(void* const* d_in, const int* in_sizes, int n_in,
                              void* d_out, int out_size)
{
    const float* x = (const float*)d_in[0];
    int i1w[3], i1b[3], i2w[3], i2b[3];
    if (in_sizes[11] == 45056){ // reference-signature order
        i1w[0]=9;  i1w[1]=11; i1w[2]=13;  i1b[0]=10; i1b[1]=12; i1b[2]=14;
        i2w[0]=15; i2w[1]=17; i2w[2]=19;  i2b[0]=16; i2b[1]=18; i2b[2]=20;
    } else {                    // setup_inputs dict order
        i1w[0]=9;  i1w[1]=13; i1w[2]=17;  i1b[0]=10; i1b[1]=14; i1b[2]=18;
        i2w[0]=11; i2w[1]=15; i2w[2]=19;  i2b[0]=12; i2b[1]=16; i2b[2]=20;
    }
    const float* bn1g=(const float*)d_in[1]; const float* bn1b=(const float*)d_in[2];
    const float* bn1m=(const float*)d_in[3]; const float* bn1v=(const float*)d_in[4];
    const float* bn2g=(const float*)d_in[5]; const float* bn2b=(const float*)d_in[6];
    const float* bn2m=(const float*)d_in[7]; const float* bn2v=(const float*)d_in[8];
    const float* hqkvw=(const float*)d_in[21]; const float* hqkvb=(const float*)d_in[22];
    const float* wqkvw=(const float*)d_in[23]; const float* wqkvb=(const float*)d_in[24];
    const float* houtw=(const float*)d_in[25]; const float* houtb=(const float*)d_in[26];
    const float* woutw=(const float*)d_in[27]; const float* woutb=(const float*)d_in[28];

    int sm_h = (2*XH_SLOT + AS_SLAB) * 4;     // 88064 B
    int sm_w = (NC*XW_CI + AS_SLAB) * 4;      // 102400 B
    cudaFuncSetAttribute(conv_h_kernel, cudaFuncAttributeMaxDynamicSharedMemorySize, sm_h);
    cudaFuncSetAttribute(conv_w_kernel, cudaFuncAttributeMaxDynamicSharedMemorySize, sm_w);
    cudaFuncSetAttribute(pw_kernel,     cudaFuncAttributeMaxDynamicSharedMemorySize, 64*1024);
    cudaFuncSetAttribute(epi_kernel,    cudaFuncAttributeMaxDynamicSharedMemorySize, 64*1024);

    prep_kernel<<<NC, 128>>>(0,
        (const float*)d_in[i1w[0]], (const float*)d_in[i1b[0]],
        (const float*)d_in[i1w[1]], (const float*)d_in[i1b[1]],
        (const float*)d_in[i1w[2]], (const float*)d_in[i1b[2]],
        bn1g, bn1b, bn1m, bn1v);
    prep_kernel<<<NC, 128>>>(1,
        (const float*)d_in[i2w[0]], (const float*)d_in[i2b[0]],
        (const float*)d_in[i2w[1]], (const float*)d_in[i2b[1]],
        (const float*)d_in[i2w[2]], (const float*)d_in[i2b[2]],
        bn2g, bn2b, bn2m, bn2v);

    conv_h_kernel<<<dim3(64, NB), 256, sm_h>>>(x);
    conv_w_kernel<<<dim3(64, NB), 256, sm_w>>>(x);

    pw_kernel<<<dim3(128, NB, 3), 128, (4352 + 8192)*4>>>(0, hqkvw, hqkvb);
    pw_kernel<<<dim3(128, NB, 3), 128, (4352 + 8192)*4>>>(1, wqkvw, wqkvb);

    gemm_p_kernel<<<dim3(64, 4, 2), 256>>>();
    gemm_o_kernel<<<dim3(8, 64, 2), 256>>>();

    epi_kernel<<<dim3(128, NB), 128, (8704 + 4096)*4>>>(x, woutw, woutb, houtw, houtb,
                                                        (float*)d_out);
}

// round 7
// speedup vs baseline: 3.2535x; 1.1631x over previous
#include <cuda_runtime.h>
#include <cuda_fp16.h>

#define NB 8
#define NC 64
#define SH 128
#define SW 128
#define HW (SH*SW)
#define KT 21

typedef unsigned long long u64;
typedef unsigned int u32;

// ---------------- scratch (device globals; no allocations) ----------------
__device__ __align__(16) __half g_Whh[KT*4096];    // fp16 folded W [t][co][ci]
__device__ __align__(16) __half g_Wwh[KT*4096];
__device__ __align__(16) __half g_xt[(u64)NB*SH*SW*NC]; // NHWC fp16 input
__device__ __align__(16) float g_rbh[NC*SH];
__device__ __align__(16) float g_rbw[NC*SW];
__device__ __align__(16) float g_sch[NB*NC*HW];
__device__ __align__(16) float g_scw[NB*NC*HW];
__device__ __align__(16) float g_hqkv[NB*192*HW];
__device__ __align__(16) float g_wqkv[NB*192*HW];
__device__ __align__(16) float g_Pp[2*64*4*SW*SW];
__device__ __align__(16) float g_wo[NB*NC*HW];
__device__ __align__(16) float g_ho[NB*NC*HW];

// ---------------- fp16 mma helper ------------------------------------------
__device__ __forceinline__ void mma_f16(float* d, const u32* a, const u32* b){
    asm volatile("mma.sync.aligned.m16n8k16.row.col.f32.f16.f16.f32 "
        "{%0,%1,%2,%3}, {%4,%5,%6,%7}, {%8,%9}, {%0,%1,%2,%3};\n"
        : "+f"(d[0]), "+f"(d[1]), "+f"(d[2]), "+f"(d[3])
        : "r"(a[0]), "r"(a[1]), "r"(a[2]), "r"(a[3]), "r"(b[0]), "r"(b[1]));
}

// ---------------- f32x2 packed fma helpers (exact fp32 math) ---------------
__device__ __forceinline__ u64 pack2(float x, float y){
    u64 r; asm("mov.b64 %0, {%1,%2};" : "=l"(r) : "f"(x), "f"(y)); return r;
}
__device__ __forceinline__ void ffma2(u64& d, u64 a, u64 b){
    asm("fma.rn.f32x2 %0, %1, %2, %0;" : "+l"(d) : "l"(a), "l"(b));
}
__device__ __forceinline__ float2 unpack2(u64 d){
    float2 f; asm("mov.b64 {%0,%1}, %2;" : "=f"(f.x), "=f"(f.y) : "l"(d)); return f;
}

// ---------------- x -> NHWC fp16 transpose ---------------------------------
__global__ __launch_bounds__(256) void xt_kernel(const float* __restrict__ x)
{
    __shared__ __half T[NC*132];
    int h = blockIdx.x, b = blockIdx.y;
    int tid = threadIdx.x;
    #pragma unroll
    for (int i = 0; i < 8; i++){
        int idx4 = tid + i*256;
        int ci = idx4 >> 5, w4 = idx4 & 31;
        float4 v = *(const float4*)(x + (u64)(b*NC + ci)*HW + h*SW + w4*4);
        T[ci*132 + w4*4 + 0] = __float2half_rn(v.x);
        T[ci*132 + w4*4 + 1] = __float2half_rn(v.y);
        T[ci*132 + w4*4 + 2] = __float2half_rn(v.z);
        T[ci*132 + w4*4 + 3] = __float2half_rn(v.w);
    }
    __syncthreads();
    #pragma unroll
    for (int i = 0; i < 4; i++){
        int oct = tid + i*256;
        int w = oct >> 3, c8 = oct & 7;
        u32 rr[4];
        #pragma unroll
        for (int j = 0; j < 4; j++){
            __half2 hv;
            hv.x = T[(c8*8 + 2*j)*132 + w];
            hv.y = T[(c8*8 + 2*j + 1)*132 + w];
            rr[j] = *(u32*)&hv;
        }
        *(uint4*)(g_xt + ((u64)((b*SH + h)*SW + w))*NC + c8*8) =
            make_uint4(rr[0], rr[1], rr[2], rr[3]);
    }
}

// ---------------- prep: combine strip kernels, fold BN, fp16 W, biases -----
__global__ void prep_kernel(int side,
    const float* __restrict__ w7,  const float* __restrict__ b7,
    const float* __restrict__ w11, const float* __restrict__ b11,
    const float* __restrict__ w21, const float* __restrict__ b21,
    const float* __restrict__ bng, const float* __restrict__ bnb,
    const float* __restrict__ bnm, const float* __restrict__ bnv)
{
    __half* Wout = side ? g_Wwh : g_Whh;
    float* rbout = side ? g_rbw : g_rbh;
    int co = blockIdx.x;
    int tid = threadIdx.x;
    __shared__ float Wraw[NC*KT];
    __shared__ float Pfx[NC*(KT+1)];

    for (int idx = tid; idx < NC*KT; idx += blockDim.x){
        int ci = idx / KT, t = idx % KT;
        float v = w21[(co*NC+ci)*21 + t];
        if (t >= 5 && t < 16) v += w11[(co*NC+ci)*11 + (t-5)];
        if (t >= 7 && t < 14) v += w7 [(co*NC+ci)*7  + (t-7)];
        Wraw[idx] = v;
        float a = bng[ci] * rsqrtf(bnv[ci] + 1e-5f);
        Wout[t*4096 + co*64 + ci] = __float2half_rn(v * a);
    }
    __syncthreads();
    if (tid < NC){
        int ci = tid;
        float a = bng[ci] * rsqrtf(bnv[ci] + 1e-5f);
        float c = bnb[ci] - bnm[ci] * a;
        float s = 0.f;
        Pfx[ci*(KT+1)] = 0.f;
        for (int t = 0; t < KT; t++){
            s += Wraw[ci*KT + t] * c;
            Pfx[ci*(KT+1) + t + 1] = s;
        }
    }
    __syncthreads();
    float cb = b7[co] + b11[co] + b21[co];
    for (int h = tid; h < SH; h += blockDim.x){
        int t0 = 10 - h;  if (t0 < 0) t0 = 0;
        int t1 = 137 - h; if (t1 > KT-1) t1 = KT-1;
        float s = cb;
        for (int ci = 0; ci < NC; ci++)
            s += Pfx[ci*(KT+1) + t1 + 1] - Pfx[ci*(KT+1) + t0];
        rbout[co*SH + h] = s;
    }
}

// ======================= fp16 mma convs ====================================
// Block = (b, output rows h0,h0+1). D[64co][128px] per row.
// 8 warps: r = wid>>2 (row), pxq = (wid&3)*32. Warp tile 64co x 32px:
// m-tiles i=0..3 (16 co), n-tiles j=0..3 (8 px), K = 64ci in 4 chunks of 16.
// smem rows padded to 72 halves (144B) -> conflict-free fragment LDS.
// conv_w: X resident [2r][148 w'][72]; conv_h: 2 rolling h-row slots [128 w][72].
#define SROW 72
__global__ __launch_bounds__(256) void conv_h_kernel();
__global__ __launch_bounds__(256) void conv_w_kernel();

template<int SIDE>   // 0 = conv_h, 1 = conv_w
__device__ __forceinline__ void conv_body()
{
    extern __shared__ char smem_raw[];
    __half* Xs = (__half*)smem_raw;
    const int XROWS = SIDE ? 296 : 256;
    __half* Ws = Xs + XROWS*SROW;
    int h0 = blockIdx.x * 2, b = blockIdx.y;
    int tid = threadIdx.x;
    int wid = tid >> 5, lid = tid & 31;
    int gid = lid >> 2, tig = lid & 3;
    int r = wid >> 2, pxq = (wid & 3) * 32;

    const __half* Wsrc = SIDE ? g_Wwh : g_Whh;
    // ---- initial X staging ----
    if (SIDE){
        for (int i = tid; i < 296*8; i += 256){
            int row = i >> 3, c16 = i & 7;
            int rr = (row >= 148), wp = row - rr*148 - 10;
            uint4 v = make_uint4(0,0,0,0);
            if ((unsigned)wp < 128u)
                v = *(const uint4*)(g_xt + ((u64)((b*SH + h0 + rr)*SW + wp))*NC + c16*8);
            *(uint4*)(Xs + row*SROW + c16*8) = v;
        }
    } else {
        #pragma unroll
        for (int s = 0; s < 2; s++){
            int hp = h0 - 10 + s;
            for (int i = tid; i < 128*8; i += 256){
                int w = i >> 3, c16 = i & 7;
                uint4 v = make_uint4(0,0,0,0);
                if ((unsigned)hp < 128u)
                    v = *(const uint4*)(g_xt + ((u64)((b*SH + hp)*SW + w))*NC + c16*8);
                *(uint4*)(Xs + (s*128 + w)*SROW + c16*8) = v;
            }
        }
    }
    // ---- W tap 0 ----
    for (int i = tid; i < 512; i += 256){
        int row = i >> 3, c16 = i & 7;
        *(uint4*)(Ws + row*SROW + c16*8) = *(const uint4*)(Wsrc + row*64 + c16*8);
    }
    __syncthreads();

    float d[4][4][4];
    #pragma unroll
    for (int i = 0; i < 4; i++)
        #pragma unroll
        for (int j = 0; j < 4; j++)
            #pragma unroll
            for (int k = 0; k < 4; k++) d[i][j][k] = 0.f;

    #pragma unroll 1
    for (int t = 0; t < KT; t++){
        const __half* xbase = SIDE
            ? Xs + (r*148 + pxq + t)*SROW
            : Xs + (((t + r) & 1)*128 + pxq)*SROW;
        #pragma unroll
        for (int kc = 0; kc < 4; kc++){
            u32 bf[4][2];
            #pragma unroll
            for (int j = 0; j < 4; j++){
                const u32* bp = (const u32*)(xbase + (j*8 + gid)*SROW + kc*16 + tig*2);
                bf[j][0] = bp[0]; bf[j][1] = bp[4];
            }
            u32 af[4][4];
            #pragma unroll
            for (int i = 0; i < 4; i++){
                const u32* ap0 = (const u32*)(Ws + (i*16 + gid)*SROW + kc*16 + tig*2);
                const u32* ap1 = (const u32*)(Ws + (i*16 + gid + 8)*SROW + kc*16 + tig*2);
                af[i][0] = ap0[0]; af[i][1] = ap1[0];
                af[i][2] = ap0[4]; af[i][3] = ap1[4];
            }
            #pragma unroll
            for (int i = 0; i < 4; i++)
                #pragma unroll
                for (int j = 0; j < 4; j++)
                    mma_f16(d[i][j], af[i], bf[j]);
        }
        if (t < KT-1){
            __syncthreads();
            if (!SIDE){
                int hp = h0 + t - 8;
                __half* ds = Xs + ((t & 1)*128)*SROW;
                for (int i = tid; i < 128*8; i += 256){
                    int w = i >> 3, c16 = i & 7;
                    uint4 v = make_uint4(0,0,0,0);
                    if ((unsigned)hp < 128u)
                        v = *(const uint4*)(g_xt + ((u64)((b*SH + hp)*SW + w))*NC + c16*8);
                    *(uint4*)(ds + w*SROW + c16*8) = v;
                }
            }
            const __half* wsrc = Wsrc + (t+1)*4096;
            for (int i = tid; i < 512; i += 256){
                int row = i >> 3, c16 = i & 7;
                *(uint4*)(Ws + row*SROW + c16*8) = *(const uint4*)(wsrc + row*64 + c16*8);
            }
            __syncthreads();
        }
    }

    // ---- epilogue: direct float2 global stores ----
    float* outg = SIDE ? g_scw : g_sch;
    int hrow = h0 + r;
    #pragma unroll
    for (int i = 0; i < 4; i++){
        #pragma unroll
        for (int half = 0; half < 2; half++){
            int co = i*16 + gid + half*8;
            float* ob = outg + (u64)(b*NC + co)*HW + hrow*SW;
            float rbh = SIDE ? 0.f : g_rbh[co*SH + hrow];
            #pragma unroll
            for (int j = 0; j < 4; j++){
                int px = pxq + j*8 + tig*2;
                float2 v;
                v.x = d[i][j][half*2 + 0];
                v.y = d[i][j][half*2 + 1];
                if (SIDE){
                    float2 bb = *(const float2*)(g_rbw + co*SW + px);
                    v.x += bb.x; v.y += bb.y;
                } else {
                    v.x += rbh; v.y += rbh;
                }
                *(float2*)(ob + px) = v;
            }
        }
    }
}

__global__ __launch_bounds__(256, 2) void conv_h_kernel(){ conv_body<0>(); }
__global__ __launch_bounds__(256, 2) void conv_w_kernel(){ conv_body<1>(); }

// ---------------- 1x1 qkv projection 64 -> 192 (f32x2) ---------------------
__global__ __launch_bounds__(128) void pw_kernel(int which, const float* __restrict__ w,
                          const float* __restrict__ bias)
{
    extern __shared__ float sm[];
    float* Ws = sm;            // [ci][o pad 68]
    float* Xs = sm + 4352;     // [ci][128]
    const float* sc = which ? g_scw : g_sch;
    float* out = which ? g_wqkv : g_hqkv;
    int pt = blockIdx.x, b = blockIdx.y, og = blockIdx.z;
    int px0 = pt * 128;
    int tid = threadIdx.x, ty = tid >> 4, tx = tid & 15;

    #pragma unroll
    for (int i = 0; i < 32; i++){
        int idx = tid + i*128;
        int o = idx >> 6, ci = idx & 63;
        Ws[ci*68 + o] = w[og*4096 + idx];
    }
    #pragma unroll
    for (int i = 0; i < 16; i++){
        int idx4 = tid + i*128;
        int ci = idx4 >> 5, p4 = idx4 & 31;
        ((float4*)Xs)[idx4] = *(const float4*)(sc + (u64)(b*NC + ci)*HW + px0 + p4*4);
    }
    __syncthreads();
    u64 acc2[8][4];
    #pragma unroll
    for (int r = 0; r < 8; r++)
        #pragma unroll
        for (int j = 0; j < 4; j++) acc2[r][j] = 0ull;
    const float4* Xq = (const float4*)Xs;
    #pragma unroll 4
    for (int ci = 0; ci < NC; ci++){
        float4 a0 = *(const float4*)(Ws + ci*68 + ty*8);
        float4 a1 = *(const float4*)(Ws + ci*68 + ty*8 + 4);
        float4 x0 = Xq[ci*32 + tx];
        float4 x1 = Xq[ci*32 + tx + 16];
        u64 da[8] = {pack2(a0.x,a0.x), pack2(a0.y,a0.y), pack2(a0.z,a0.z), pack2(a0.w,a0.w),
                     pack2(a1.x,a1.x), pack2(a1.y,a1.y), pack2(a1.z,a1.z), pack2(a1.w,a1.w)};
        u64 xd[4] = {pack2(x0.x,x0.y), pack2(x0.z,x0.w), pack2(x1.x,x1.y), pack2(x1.z,x1.w)};
        #pragma unroll
        for (int r = 0; r < 8; r++)
            #pragma unroll
            for (int j = 0; j < 4; j++)
                ffma2(acc2[r][j], da[r], xd[j]);
    }
    #pragma unroll
    for (int r = 0; r < 8; r++){
        int o = og*64 + ty*8 + r;
        float bv = bias[o];
        float* ob = out + (u64)(b*192 + o)*HW + px0;
        float2 p0 = unpack2(acc2[r][0]), p1 = unpack2(acc2[r][1]);
        float2 p2 = unpack2(acc2[r][2]), p3 = unpack2(acc2[r][3]);
        float4 v0 = {p0.x+bv, p0.y+bv, p1.x+bv, p1.y+bv};
        float4 v1 = {p2.x+bv, p2.y+bv, p3.x+bv, p3.y+bv};
        *(float4*)(ob + tx*4)      = v0;
        *(float4*)(ob + tx*4 + 64) = v1;
    }
}

// ---------------- P partials: both branches, K split 4 (f32x2) -------------
__global__ __launch_bounds__(256) void gemm_p_kernel()
{
    __shared__ __align__(16) float As[16*128];
    __shared__ __align__(16) float Bs[16*128];
    int pair = blockIdx.x, ks = blockIdx.y, which = blockIdx.z;
    int b = pair >> 3, nh = pair & 7;
    const float* A  = which ? g_wqkv : g_hqkv;
    const float* Bm = which ? g_hqkv : g_wqkv;
    int tid = threadIdx.x, ty = tid >> 4, tx = tid & 15;
    u64 acc2[8][4];
    #pragma unroll
    for (int r = 0; r < 8; r++)
        #pragma unroll
        for (int j = 0; j < 4; j++) acc2[r][j] = 0ull;
    const float* abase = A  + (u64)(b*192 + nh*24 + 0 )*HW + ks*256*SW;
    const float* bbase = Bm + (u64)(b*192 + nh*24 + 16)*HW + ks*256*SW;

    #pragma unroll 1
    for (int k0 = 0; k0 < 256; k0 += 16){
        const float4* ap = (const float4*)(abase + k0*SW);
        const float4* bp = (const float4*)(bbase + k0*SW);
        #pragma unroll
        for (int i = 0; i < 2; i++){
            ((float4*)As)[tid + i*256] = ap[tid + i*256];
            ((float4*)Bs)[tid + i*256] = bp[tid + i*256];
        }
        __syncthreads();
        const float4* Aq = (const float4*)As;
        const float4* Bq = (const float4*)Bs;
        #pragma unroll
        for (int k = 0; k < 16; k++){
            float4 a0 = Aq[k*32 + ty];
            float4 a1 = Aq[k*32 + ty + 16];
            float4 b0 = Bq[k*32 + tx];
            float4 b1 = Bq[k*32 + tx + 16];
            u64 da[8] = {pack2(a0.x,a0.x), pack2(a0.y,a0.y), pack2(a0.z,a0.z), pack2(a0.w,a0.w),
                         pack2(a1.x,a1.x), pack2(a1.y,a1.y), pack2(a1.z,a1.z), pack2(a1.w,a1.w)};
            u64 xd[4] = {pack2(b0.x,b0.y), pack2(b0.z,b0.w), pack2(b1.x,b1.y), pack2(b1.z,b1.w)};
            #pragma unroll
            for (int r = 0; r < 8; r++)
                #pragma unroll
                for (int j = 0; j < 4; j++)
                    ffma2(acc2[r][j], da[r], xd[j]);
        }
        __syncthreads();
    }
    float* pp = g_Pp + (u64)((which*64 + pair)*4 + ks)*16384;
    #pragma unroll
    for (int r = 0; r < 8; r++){
        int row = ty*4 + (r & 3) + (r >= 4 ? 64 : 0);
        float2 p0 = unpack2(acc2[r][0]), p1 = unpack2(acc2[r][1]);
        float2 p2 = unpack2(acc2[r][2]), p3 = unpack2(acc2[r][3]);
        float4 v0 = {p0.x, p0.y, p1.x, p1.y};
        float4 v1 = {p2.x, p2.y, p3.x, p3.y};
        *(float4*)(pp + row*128 + tx*4)      = v0;
        *(float4*)(pp + row*128 + tx*4 + 64) = v1;
    }
}

// ---------------- o = scale * k @ (sum of P partials) (f32x2) --------------
__global__ __launch_bounds__(256) void gemm_o_kernel()
{
    __shared__ __align__(16) float As[16*132];
    __shared__ __align__(16) float Bs[16*128];
    int jt = blockIdx.x, pair = blockIdx.y, which = blockIdx.z;
    int b = pair >> 3, nh = pair & 7;
    const float* Kt = which ? g_hqkv : g_wqkv;
    float* out = which ? g_ho : g_wo;
    int tid = threadIdx.x, ty = tid >> 4, tx = tid & 15;
    const float* kb = Kt + (u64)(b*192 + nh*24 + 8 + jt)*HW;
    const float* pb = g_Pp + (u64)(which*64 + pair)*4*16384;
    u64 acc2[8][4];
    #pragma unroll
    for (int r = 0; r < 8; r++)
        #pragma unroll
        for (int j = 0; j < 4; j++) acc2[r][j] = 0ull;

    #pragma unroll 1
    for (int k0 = 0; k0 < 128; k0 += 16){
        #pragma unroll
        for (int i = 0; i < 8; i++){
            int idx = tid + i*256;
            int j = idx >> 4, k = idx & 15;
            As[k*132 + j] = kb[j*128 + k0 + k];
        }
        #pragma unroll
        for (int i = 0; i < 2; i++){
            int idx4 = tid + i*256;
            float4 p0 = ((const float4*)(pb           ))[k0*32 + idx4];
            float4 p1 = ((const float4*)(pb + 16384   ))[k0*32 + idx4];
            float4 p2 = ((const float4*)(pb + 2*16384 ))[k0*32 + idx4];
            float4 p3 = ((const float4*)(pb + 3*16384 ))[k0*32 + idx4];
            float4 s = {p0.x+p1.x+p2.x+p3.x, p0.y+p1.y+p2.y+p3.y,
                        p0.z+p1.z+p2.z+p3.z, p0.w+p1.w+p2.w+p3.w};
            ((float4*)Bs)[idx4] = s;
        }
        __syncthreads();
        const float4* Bq = (const float4*)Bs;
        #pragma unroll
        for (int k = 0; k < 16; k++){
            float4 a0 = *(const float4*)(As + k*132 + ty*4);
            float4 a1 = *(const float4*)(As + k*132 + ty*4 + 64);
            float4 b0 = Bq[k*32 + tx];
            float4 b1 = Bq[k*32 + tx + 16];
            u64 da[8] = {pack2(a0.x,a0.x), pack2(a0.y,a0.y), pack2(a0.z,a0.z), pack2(a0.w,a0.w),
                         pack2(a1.x,a1.x), pack2(a1.y,a1.y), pack2(a1.z,a1.z), pack2(a1.w,a1.w)};
            u64 xd[4] = {pack2(b0.x,b0.y), pack2(b0.z,b0.w), pack2(b1.x,b1.y), pack2(b1.z,b1.w)};
            #pragma unroll
            for (int r = 0; r < 8; r++)
                #pragma unroll
                for (int j = 0; j < 4; j++)
                    ffma2(acc2[r][j], da[r], xd[j]);
        }
        __syncthreads();
    }
    const float scale = 0.707106781186547524f;
    float* ob = out + (u64)(b*NC + nh*8 + jt)*HW;
    #pragma unroll
    for (int r = 0; r < 8; r++){
        int row = ty*4 + (r & 3) + (r >= 4 ? 64 : 0);
        float2 p0 = unpack2(acc2[r][0]), p1 = unpack2(acc2[r][1]);
        float2 p2 = unpack2(acc2[r][2]), p3 = unpack2(acc2[r][3]);
        float4 v0 = {p0.x*scale, p0.y*scale, p1.x*scale, p1.y*scale};
        float4 v1 = {p2.x*scale, p2.y*scale, p3.x*scale, p3.y*scale};
        *(float4*)(ob + row*SW + tx*4)      = v0;
        *(float4*)(ob + row*SW + tx*4 + 64) = v1;
    }
}

// ---------------- epilogue: out-projections + sigmoid gate (f32x2) ---------
__global__ __launch_bounds__(128) void epi_kernel(const float* __restrict__ x,
    const float* __restrict__ wow, const float* __restrict__ wob,
    const float* __restrict__ how, const float* __restrict__ hob,
    float* __restrict__ out)
{
    extern __shared__ float sm[];
    float* Ws = sm;
    float* Hs = sm + 4352;
    float* Xw = sm + 8704;
    float* Xh = sm + 8704 + 2048;
    int pt = blockIdx.x, b = blockIdx.y;
    int px0 = pt * 128;
    int tid = threadIdx.x, ty = tid >> 4, tx = tid & 15;

    #pragma unroll
    for (int i = 0; i < 32; i++){
        int idx = tid + i*128;
        int o = idx >> 6, ci = idx & 63;
        Ws[ci*68 + o] = wow[idx];
        Hs[ci*68 + o] = how[idx];
    }
    u64 acc2[8][4];
    #pragma unroll
    for (int r = 0; r < 8; r++)
        #pragma unroll
        for (int j = 0; j < 4; j++) acc2[r][j] = 0ull;

    #pragma unroll 1
    for (int kc = 0; kc < 4; kc++){
        if (kc) __syncthreads();
        #pragma unroll
        for (int i = 0; i < 4; i++){
            int idx4 = tid + i*128;
            int ci = idx4 >> 5, p4 = idx4 & 31;
            ((float4*)Xw)[idx4] = *(const float4*)(g_wo + (u64)(b*NC + kc*16 + ci)*HW + px0 + p4*4);
            ((float4*)Xh)[idx4] = *(const float4*)(g_ho + (u64)(b*NC + kc*16 + ci)*HW + px0 + p4*4);
        }
        __syncthreads();
        const float4* Xwq = (const float4*)Xw;
        const float4* Xhq = (const float4*)Xh;
        #pragma unroll 2
        for (int c16 = 0; c16 < 16; c16++){
            int ci = kc*16 + c16;
            float4 aw0 = *(const float4*)(Ws + ci*68 + ty*8);
            float4 aw1 = *(const float4*)(Ws + ci*68 + ty*8 + 4);
            float4 ah0 = *(const float4*)(Hs + ci*68 + ty*8);
            float4 ah1 = *(const float4*)(Hs + ci*68 + ty*8 + 4);
            float4 xw0 = Xwq[c16*32 + tx];
            float4 xw1 = Xwq[c16*32 + tx + 16];
            float4 xh0 = Xhq[c16*32 + tx];
            float4 xh1 = Xhq[c16*32 + tx + 16];
            u64 dw[8] = {pack2(aw0.x,aw0.x), pack2(aw0.y,aw0.y), pack2(aw0.z,aw0.z), pack2(aw0.w,aw0.w),
                         pack2(aw1.x,aw1.x), pack2(aw1.y,aw1.y), pack2(aw1.z,aw1.z), pack2(aw1.w,aw1.w)};
            u64 dh[8] = {pack2(ah0.x,ah0.x), pack2(ah0.y,ah0.y), pack2(ah0.z,ah0.z), pack2(ah0.w,ah0.w),
                         pack2(ah1.x,ah1.x), pack2(ah1.y,ah1.y), pack2(ah1.z,ah1.z), pack2(ah1.w,ah1.w)};
            u64 xwd[4] = {pack2(xw0.x,xw0.y), pack2(xw0.z,xw0.w), pack2(xw1.x,xw1.y), pack2(xw1.z,xw1.w)};
            u64 xhd[4] = {pack2(xh0.x,xh0.y), pack2(xh0.z,xh0.w), pack2(xh1.x,xh1.y), pack2(xh1.z,xh1.w)};
            #pragma unroll
            for (int r = 0; r < 8; r++)
                #pragma unroll
                for (int j = 0; j < 4; j++){
                    ffma2(acc2[r][j], dw[r], xwd[j]);
                    ffma2(acc2[r][j], dh[r], xhd[j]);
                }
        }
    }
    #pragma unroll
    for (int r = 0; r < 8; r++){
        int c = ty*8 + r;
        float bv = wob[c] + hob[c];
        const float* xb = x + (u64)(b*NC + c)*HW + px0;
        float* ob = out + (u64)(b*NC + c)*HW + px0;
        float av[8];
        float2 p0 = unpack2(acc2[r][0]), p1 = unpack2(acc2[r][1]);
        float2 p2 = unpack2(acc2[r][2]), p3 = unpack2(acc2[r][3]);
        av[0]=p0.x; av[1]=p0.y; av[2]=p1.x; av[3]=p1.y;
        av[4]=p2.x; av[5]=p2.y; av[6]=p3.x; av[7]=p3.y;
        #pragma unroll
        for (int half = 0; half < 2; half++){
            float4 xv = *(const float4*)(xb + tx*4 + half*64);
            float vs[4];
            #pragma unroll
            for (int j = 0; j < 4; j++){
                float s = av[half*4 + j] + bv;
                vs[j] = (&xv.x)[j] * (1.f / (1.f + expf(-s)));
            }
            float4 v = {vs[0], vs[1], vs[2], vs[3]};
            *(float4*)(ob + tx*4 + half*64) = v;
        }
    }
}

// ---------------- launch ---------------------------------------------------
extern "C" void kernel_launch(void* const* d_in, const int* in_sizes, int n_in,
                              void* d_out, int out_size)
{
    const float* x = (const float*)d_in[0];
    int i1w[3], i1b[3], i2w[3], i2b[3];
    if (in_sizes[11] == 45056){ // reference-signature order
        i1w[0]=9;  i1w[1]=11; i1w[2]=13;  i1b[0]=10; i1b[1]=12; i1b[2]=14;
        i2w[0]=15; i2w[1]=17; i2w[2]=19;  i2b[0]=16; i2b[1]=18; i2b[2]=20;
    } else {                    // setup_inputs dict order
        i1w[0]=9;  i1w[1]=13; i1w[2]=17;  i1b[0]=10; i1b[1]=14; i1b[2]=18;
        i2w[0]=11; i2w[1]=15; i2w[2]=19;  i2b[0]=12; i2b[1]=16; i2b[2]=20;
    }
    const float* bn1g=(const float*)d_in[1]; const float* bn1b=(const float*)d_in[2];
    const float* bn1m=(const float*)d_in[3]; const float* bn1v=(const float*)d_in[4];
    const float* bn2g=(const float*)d_in[5]; const float* bn2b=(const float*)d_in[6];
    const float* bn2m=(const float*)d_in[7]; const float* bn2v=(const float*)d_in[8];
    const float* hqkvw=(const float*)d_in[21]; const float* hqkvb=(const float*)d_in[22];
    const float* wqkvw=(const float*)d_in[23]; const float* wqkvb=(const float*)d_in[24];
    const float* houtw=(const float*)d_in[25]; const float* houtb=(const float*)d_in[26];
    const float* woutw=(const float*)d_in[27]; const float* woutb=(const float*)d_in[28];

    int sm_h = (256*SROW + 64*SROW) * 2;   // 46080 B
    int sm_w = (296*SROW + 64*SROW) * 2;   // 51840 B
    cudaFuncSetAttribute(conv_h_kernel, cudaFuncAttributeMaxDynamicSharedMemorySize, sm_h);
    cudaFuncSetAttribute(conv_w_kernel, cudaFuncAttributeMaxDynamicSharedMemorySize, sm_w);
    cudaFuncSetAttribute(pw_kernel,     cudaFuncAttributeMaxDynamicSharedMemorySize, 64*1024);
    cudaFuncSetAttribute(epi_kernel,    cudaFuncAttributeMaxDynamicSharedMemorySize, 64*1024);

    xt_kernel<<<dim3(SH, NB), 256>>>(x);
    prep_kernel<<<NC, 128>>>(0,
        (const float*)d_in[i1w[0]], (const float*)d_in[i1b[0]],
        (const float*)d_in[i1w[1]], (const float*)d_in[i1b[1]],
        (const float*)d_in[i1w[2]], (const float*)d_in[i1b[2]],
        bn1g, bn1b, bn1m, bn1v);
    prep_kernel<<<NC, 128>>>(1,
        (const float*)d_in[i2w[0]], (const float*)d_in[i2b[0]],
        (const float*)d_in[i2w[1]], (const float*)d_in[i2b[1]],
        (const float*)d_in[i2w[2]], (const float*)d_in[i2b[2]],
        bn2g, bn2b, bn2m, bn2v);

    conv_h_kernel<<<dim3(64, NB), 256, sm_h>>>();
    conv_w_kernel<<<dim3(64, NB), 256, sm_w>>>();

    pw_kernel<<<dim3(128, NB, 3), 128, (4352 + 8192)*4>>>(0, hqkvw, hqkvb);
    pw_kernel<<<dim3(128, NB, 3), 128, (4352 + 8192)*4>>>(1, wqkvw, wqkvb);

    gemm_p_kernel<<<dim3(64, 4, 2), 256>>>();
    gemm_o_kernel<<<dim3(8, 64, 2), 256>>>();

    epi_kernel<<<dim3(128, NB), 128, (8704 + 4096)*4>>>(x, woutw, woutb, houtw, houtb,
                                                        (float*)d_out);
}

// round 8
// speedup vs baseline: 3.3849x; 1.0404x over previous
#include <cuda_runtime.h>
#include <cuda_fp16.h>

#define NB 8
#define NC 64
#define SH 128
#define SW 128
#define HW (SH*SW)
#define KT 21

typedef unsigned long long u64;
typedef unsigned int u32;

// ---------------- scratch (device globals; no allocations) ----------------
__device__ __align__(16) __half g_Whh[KT*4096];    // fp16 folded W [t][co][ci]
__device__ __align__(16) __half g_Wwh[KT*4096];
__device__ __align__(16) __half g_xt[(u64)NB*SH*SW*NC]; // NHWC fp16 input
__device__ __align__(16) float g_rbh[NC*SH];
__device__ __align__(16) float g_rbw[NC*SW];
__device__ __align__(16) float g_sch[NB*NC*HW];
__device__ __align__(16) float g_scw[NB*NC*HW];
__device__ __align__(16) float g_hqkv[NB*192*HW];
__device__ __align__(16) float g_wqkv[NB*192*HW];
__device__ __align__(16) float g_Pp[2*64*4*SW*SW];
__device__ __align__(16) float g_wo[NB*NC*HW];
__device__ __align__(16) float g_ho[NB*NC*HW];

// ---------------- fp16 mma helper ------------------------------------------
__device__ __forceinline__ void mma_f16(float* d, const u32* a, const u32* b){
    asm volatile("mma.sync.aligned.m16n8k16.row.col.f32.f16.f16.f32 "
        "{%0,%1,%2,%3}, {%4,%5,%6,%7}, {%8,%9}, {%0,%1,%2,%3};\n"
        : "+f"(d[0]), "+f"(d[1]), "+f"(d[2]), "+f"(d[3])
        : "r"(a[0]), "r"(a[1]), "r"(a[2]), "r"(a[3]), "r"(b[0]), "r"(b[1]));
}

// ---------------- cp.async helpers -----------------------------------------
__device__ __forceinline__ u32 smem_u32(const void* p){
    u32 a; asm("{ .reg .u64 t; cvta.to.shared.u64 t, %1; cvt.u32.u64 %0, t; }"
               : "=r"(a) : "l"(p));
    return a;
}
__device__ __forceinline__ void cpa16(u32 dst, const void* src, u32 srcsize){
    asm volatile("cp.async.cg.shared.global [%0], [%1], 16, %2;"
                 :: "r"(dst), "l"(src), "r"(srcsize) : "memory");
}
#define CPA_COMMIT() asm volatile("cp.async.commit_group;" ::: "memory")
#define CPA_WAIT0()  asm volatile("cp.async.wait_group 0;" ::: "memory")

// ---------------- f32x2 packed fma helpers (exact fp32 math) ---------------
__device__ __forceinline__ u64 pack2(float x, float y){
    u64 r; asm("mov.b64 %0, {%1,%2};" : "=l"(r) : "f"(x), "f"(y)); return r;
}
__device__ __forceinline__ void ffma2(u64& d, u64 a, u64 b){
    asm("fma.rn.f32x2 %0, %1, %2, %0;" : "+l"(d) : "l"(a), "l"(b));
}
__device__ __forceinline__ float2 unpack2(u64 d){
    float2 f; asm("mov.b64 {%0,%1}, %2;" : "=f"(f.x), "=f"(f.y) : "l"(d)); return f;
}

// ---------------- x -> NHWC fp16 transpose ---------------------------------
__global__ __launch_bounds__(256) void xt_kernel(const float* __restrict__ x)
{
    __shared__ __half T[NC*132];
    int h = blockIdx.x, b = blockIdx.y;
    int tid = threadIdx.x;
    #pragma unroll
    for (int i = 0; i < 8; i++){
        int idx4 = tid + i*256;
        int ci = idx4 >> 5, w4 = idx4 & 31;
        float4 v = *(const float4*)(x + (u64)(b*NC + ci)*HW + h*SW + w4*4);
        T[ci*132 + w4*4 + 0] = __float2half_rn(v.x);
        T[ci*132 + w4*4 + 1] = __float2half_rn(v.y);
        T[ci*132 + w4*4 + 2] = __float2half_rn(v.z);
        T[ci*132 + w4*4 + 3] = __float2half_rn(v.w);
    }
    __syncthreads();
    #pragma unroll
    for (int i = 0; i < 4; i++){
        int oct = tid + i*256;
        int w = oct >> 3, c8 = oct & 7;
        u32 rr[4];
        #pragma unroll
        for (int j = 0; j < 4; j++){
            __half2 hv;
            hv.x = T[(c8*8 + 2*j)*132 + w];
            hv.y = T[(c8*8 + 2*j + 1)*132 + w];
            rr[j] = *(u32*)&hv;
        }
        *(uint4*)(g_xt + ((u64)((b*SH + h)*SW + w))*NC + c8*8) =
            make_uint4(rr[0], rr[1], rr[2], rr[3]);
    }
}

// ---------------- prep: combine strip kernels, fold BN, fp16 W, biases -----
__global__ void prep_kernel(int side,
    const float* __restrict__ w7,  const float* __restrict__ b7,
    const float* __restrict__ w11, const float* __restrict__ b11,
    const float* __restrict__ w21, const float* __restrict__ b21,
    const float* __restrict__ bng, const float* __restrict__ bnb,
    const float* __restrict__ bnm, const float* __restrict__ bnv)
{
    __half* Wout = side ? g_Wwh : g_Whh;
    float* rbout = side ? g_rbw : g_rbh;
    int co = blockIdx.x;
    int tid = threadIdx.x;
    __shared__ float Wraw[NC*KT];
    __shared__ float Pfx[NC*(KT+1)];

    for (int idx = tid; idx < NC*KT; idx += blockDim.x){
        int ci = idx / KT, t = idx % KT;
        float v = w21[(co*NC+ci)*21 + t];
        if (t >= 5 && t < 16) v += w11[(co*NC+ci)*11 + (t-5)];
        if (t >= 7 && t < 14) v += w7 [(co*NC+ci)*7  + (t-7)];
        Wraw[idx] = v;
        float a = bng[ci] * rsqrtf(bnv[ci] + 1e-5f);
        Wout[t*4096 + co*64 + ci] = __float2half_rn(v * a);
    }
    __syncthreads();
    if (tid < NC){
        int ci = tid;
        float a = bng[ci] * rsqrtf(bnv[ci] + 1e-5f);
        float c = bnb[ci] - bnm[ci] * a;
        float s = 0.f;
        Pfx[ci*(KT+1)] = 0.f;
        for (int t = 0; t < KT; t++){
            s += Wraw[ci*KT + t] * c;
            Pfx[ci*(KT+1) + t + 1] = s;
        }
    }
    __syncthreads();
    float cb = b7[co] + b11[co] + b21[co];
    for (int h = tid; h < SH; h += blockDim.x){
        int t0 = 10 - h;  if (t0 < 0) t0 = 0;
        int t1 = 137 - h; if (t1 > KT-1) t1 = KT-1;
        float s = cb;
        for (int ci = 0; ci < NC; ci++)
            s += Pfx[ci*(KT+1) + t1 + 1] - Pfx[ci*(KT+1) + t0];
        rbout[co*SH + h] = s;
    }
}

// ======================= fp16 mma convs (async staging) =====================
// Block = (b, output rows h0,h0+1). 8 warps: r = wid>>2, pxq = (wid&3)*32.
// Warp tile 64co x 32px; K = 64ci in 4 chunks of 16; taps accumulated.
// smem rows padded to 72 halves (144B) -> conflict-free fragment LDS.
// conv_w: X resident [2r][148 w'][72]. conv_h: 3 rolling row slots (row%3).
// W double-buffered (slab t&1). One __syncthreads per tap; cp.async staging.
#define SROW 72
#define WSLAB (64*SROW)          // halves per W slab

template<int SIDE>   // 0 = conv_h, 1 = conv_w
__device__ __forceinline__ void conv_body()
{
    extern __shared__ char smem_raw[];
    __half* Xs = (__half*)smem_raw;
    const int XROWS = SIDE ? 296 : 384;
    __half* Ws = Xs + XROWS*SROW;          // 2 slabs
    int h0 = blockIdx.x * 2, b = blockIdx.y;
    int tid = threadIdx.x;
    int wid = tid >> 5, lid = tid & 31;
    int gid = lid >> 2, tig = lid & 3;
    int r = wid >> 2, pxq = (wid & 3) * 32;
    u32 xs_b = smem_u32(Xs);
    u32 ws_b = smem_u32(Ws);

    const __half* Wsrc = SIDE ? g_Wwh : g_Whh;
    // ---- initial X staging (plain stores; one-time) ----
    if (SIDE){
        for (int i = tid; i < 296*8; i += 256){
            int row = i >> 3, c16 = i & 7;
            int rr = (row >= 148), wp = row - rr*148 - 10;
            uint4 v = make_uint4(0,0,0,0);
            if ((unsigned)wp < 128u)
                v = *(const uint4*)(g_xt + ((u64)((b*SH + h0 + rr)*SW + wp))*NC + c16*8);
            *(uint4*)(Xs + row*SROW + c16*8) = v;
        }
    } else {
        #pragma unroll
        for (int s = 0; s < 2; s++){
            int hp = h0 - 10 + s;            // rows for tap 0
            int slot = (hp + 12) % 3;
            for (int i = tid; i < 128*8; i += 256){
                int w = i >> 3, c16 = i & 7;
                uint4 v = make_uint4(0,0,0,0);
                if ((unsigned)hp < 128u)
                    v = *(const uint4*)(g_xt + ((u64)((b*SH + hp)*SW + w))*NC + c16*8);
                *(uint4*)(Xs + (slot*128 + w)*SROW + c16*8) = v;
            }
        }
    }
    // ---- W tap 0 -> slab 0 ----
    for (int i = tid; i < 512; i += 256){
        int row = i >> 3, c16 = i & 7;
        *(uint4*)(Ws + row*SROW + c16*8) = *(const uint4*)(Wsrc + row*64 + c16*8);
    }
    __syncthreads();

    float d[4][4][4];
    #pragma unroll
    for (int i = 0; i < 4; i++)
        #pragma unroll
        for (int j = 0; j < 4; j++)
            #pragma unroll
            for (int k = 0; k < 4; k++) d[i][j][k] = 0.f;

    #pragma unroll 1
    for (int t = 0; t < KT; t++){
        // ---- async prefetch for tap t+1 (lands before end-of-tap sync) ----
        if (t < KT-1){
            if (!SIDE){
                int nrow = h0 + t - 8;               // needed at tap t+1 (r=1)
                int slot = (nrow + 12) % 3;          // distinct from both read slots
                u32 ok = ((unsigned)nrow < 128u) ? 16u : 0u;
                int crow = nrow < 0 ? 0 : (nrow > 127 ? 127 : nrow);
                const __half* src = g_xt + ((u64)((b*SH + crow)*SW))*NC;
                #pragma unroll
                for (int i = 0; i < 4; i++){
                    int idx = tid + i*256;
                    int w = idx >> 3, c16 = idx & 7;
                    cpa16(xs_b + ((slot*128 + w)*SROW + c16*8)*2,
                          src + (u64)w*NC + c16*8, ok);
                }
            }
            {
                const __half* wsrc = Wsrc + (t+1)*4096;
                u32 wdst = ws_b + (((t+1) & 1)*WSLAB)*2;
                #pragma unroll
                for (int i = 0; i < 2; i++){
                    int idx = tid + i*256;
                    int row = idx >> 3, c16 = idx & 7;
                    cpa16(wdst + (row*SROW + c16*8)*2, wsrc + row*64 + c16*8, 16);
                }
            }
            CPA_COMMIT();
        }
        // ---- compute tap t ----
        const __half* Wt = Ws + (t & 1)*WSLAB;
        const __half* xbase = SIDE
            ? Xs + (r*148 + pxq + t)*SROW
            : Xs + (((h0 + t + r + 2) % 3)*128 + pxq)*SROW;
        #pragma unroll
        for (int kc = 0; kc < 4; kc++){
            u32 bf[4][2];
            #pragma unroll
            for (int j = 0; j < 4; j++){
                const u32* bp = (const u32*)(xbase + (j*8 + gid)*SROW + kc*16 + tig*2);
                bf[j][0] = bp[0]; bf[j][1] = bp[4];
            }
            u32 af[4][4];
            #pragma unroll
            for (int i = 0; i < 4; i++){
                const u32* ap0 = (const u32*)(Wt + (i*16 + gid)*SROW + kc*16 + tig*2);
                const u32* ap1 = (const u32*)(Wt + (i*16 + gid + 8)*SROW + kc*16 + tig*2);
                af[i][0] = ap0[0]; af[i][1] = ap1[0];
                af[i][2] = ap0[4]; af[i][3] = ap1[4];
            }
            #pragma unroll
            for (int i = 0; i < 4; i++)
                #pragma unroll
                for (int j = 0; j < 4; j++)
                    mma_f16(d[i][j], af[i], bf[j]);
        }
        if (t < KT-1){
            CPA_WAIT0();
            __syncthreads();
        }
    }

    // ---- epilogue: direct float2 global stores ----
    float* outg = SIDE ? g_scw : g_sch;
    int hrow = h0 + r;
    #pragma unroll
    for (int i = 0; i < 4; i++){
        #pragma unroll
        for (int half = 0; half < 2; half++){
            int co = i*16 + gid + half*8;
            float* ob = outg + (u64)(b*NC + co)*HW + hrow*SW;
            float rbh = SIDE ? 0.f : g_rbh[co*SH + hrow];
            #pragma unroll
            for (int j = 0; j < 4; j++){
                int px = pxq + j*8 + tig*2;
                float2 v;
                v.x = d[i][j][half*2 + 0];
                v.y = d[i][j][half*2 + 1];
                if (SIDE){
                    float2 bb = *(const float2*)(g_rbw + co*SW + px);
                    v.x += bb.x; v.y += bb.y;
                } else {
                    v.x += rbh; v.y += rbh;
                }
                *(float2*)(ob + px) = v;
            }
        }
    }
}

__global__ __launch_bounds__(256, 2) void conv_h_kernel(){ conv_body<0>(); }
__global__ __launch_bounds__(256, 2) void conv_w_kernel(){ conv_body<1>(); }

// ---------------- 1x1 qkv projection 64 -> 192 (f32x2) ---------------------
__global__ __launch_bounds__(128) void pw_kernel(int which, const float* __restrict__ w,
                          const float* __restrict__ bias)
{
    extern __shared__ float sm[];
    float* Ws = sm;            // [ci][o pad 68]
    float* Xs = sm + 4352;     // [ci][128]
    const float* sc = which ? g_scw : g_sch;
    float* out = which ? g_wqkv : g_hqkv;
    int pt = blockIdx.x, b = blockIdx.y, og = blockIdx.z;
    int px0 = pt * 128;
    int tid = threadIdx.x, ty = tid >> 4, tx = tid & 15;

    #pragma unroll
    for (int i = 0; i < 32; i++){
        int idx = tid + i*128;
        int o = idx >> 6, ci = idx & 63;
        Ws[ci*68 + o] = w[og*4096 + idx];
    }
    #pragma unroll
    for (int i = 0; i < 16; i++){
        int idx4 = tid + i*128;
        int ci = idx4 >> 5, p4 = idx4 & 31;
        ((float4*)Xs)[idx4] = *(const float4*)(sc + (u64)(b*NC + ci)*HW + px0 + p4*4);
    }
    __syncthreads();
    u64 acc2[8][4];
    #pragma unroll
    for (int r = 0; r < 8; r++)
        #pragma unroll
        for (int j = 0; j < 4; j++) acc2[r][j] = 0ull;
    const float4* Xq = (const float4*)Xs;
    #pragma unroll 4
    for (int ci = 0; ci < NC; ci++){
        float4 a0 = *(const float4*)(Ws + ci*68 + ty*8);
        float4 a1 = *(const float4*)(Ws + ci*68 + ty*8 + 4);
        float4 x0 = Xq[ci*32 + tx];
        float4 x1 = Xq[ci*32 + tx + 16];
        u64 da[8] = {pack2(a0.x,a0.x), pack2(a0.y,a0.y), pack2(a0.z,a0.z), pack2(a0.w,a0.w),
                     pack2(a1.x,a1.x), pack2(a1.y,a1.y), pack2(a1.z,a1.z), pack2(a1.w,a1.w)};
        u64 xd[4] = {pack2(x0.x,x0.y), pack2(x0.z,x0.w), pack2(x1.x,x1.y), pack2(x1.z,x1.w)};
        #pragma unroll
        for (int r = 0; r < 8; r++)
            #pragma unroll
            for (int j = 0; j < 4; j++)
                ffma2(acc2[r][j], da[r], xd[j]);
    }
    #pragma unroll
    for (int r = 0; r < 8; r++){
        int o = og*64 + ty*8 + r;
        float bv = bias[o];
        float* ob = out + (u64)(b*192 + o)*HW + px0;
        float2 p0 = unpack2(acc2[r][0]), p1 = unpack2(acc2[r][1]);
        float2 p2 = unpack2(acc2[r][2]), p3 = unpack2(acc2[r][3]);
        float4 v0 = {p0.x+bv, p0.y+bv, p1.x+bv, p1.y+bv};
        float4 v1 = {p2.x+bv, p2.y+bv, p3.x+bv, p3.y+bv};
        *(float4*)(ob + tx*4)      = v0;
        *(float4*)(ob + tx*4 + 64) = v1;
    }
}

// ---------------- P partials: both branches, K split 4 (f32x2) -------------
__global__ __launch_bounds__(256) void gemm_p_kernel()
{
    __shared__ __align__(16) float As[16*128];
    __shared__ __align__(16) float Bs[16*128];
    int pair = blockIdx.x, ks = blockIdx.y, which = blockIdx.z;
    int b = pair >> 3, nh = pair & 7;
    const float* A  = which ? g_wqkv : g_hqkv;
    const float* Bm = which ? g_hqkv : g_wqkv;
    int tid = threadIdx.x, ty = tid >> 4, tx = tid & 15;
    u64 acc2[8][4];
    #pragma unroll
    for (int r = 0; r < 8; r++)
        #pragma unroll
        for (int j = 0; j < 4; j++) acc2[r][j] = 0ull;
    const float* abase = A  + (u64)(b*192 + nh*24 + 0 )*HW + ks*256*SW;
    const float* bbase = Bm + (u64)(b*192 + nh*24 + 16)*HW + ks*256*SW;

    #pragma unroll 1
    for (int k0 = 0; k0 < 256; k0 += 16){
        const float4* ap = (const float4*)(abase + k0*SW);
        const float4* bp = (const float4*)(bbase + k0*SW);
        #pragma unroll
        for (int i = 0; i < 2; i++){
            ((float4*)As)[tid + i*256] = ap[tid + i*256];
            ((float4*)Bs)[tid + i*256] = bp[tid + i*256];
        }
        __syncthreads();
        const float4* Aq = (const float4*)As;
        const float4* Bq = (const float4*)Bs;
        #pragma unroll
        for (int k = 0; k < 16; k++){
            float4 a0 = Aq[k*32 + ty];
            float4 a1 = Aq[k*32 + ty + 16];
            float4 b0 = Bq[k*32 + tx];
            float4 b1 = Bq[k*32 + tx + 16];
            u64 da[8] = {pack2(a0.x,a0.x), pack2(a0.y,a0.y), pack2(a0.z,a0.z), pack2(a0.w,a0.w),
                         pack2(a1.x,a1.x), pack2(a1.y,a1.y), pack2(a1.z,a1.z), pack2(a1.w,a1.w)};
            u64 xd[4] = {pack2(b0.x,b0.y), pack2(b0.z,b0.w), pack2(b1.x,b1.y), pack2(b1.z,b1.w)};
            #pragma unroll
            for (int r = 0; r < 8; r++)
                #pragma unroll
                for (int j = 0; j < 4; j++)
                    ffma2(acc2[r][j], da[r], xd[j]);
        }
        __syncthreads();
    }
    float* pp = g_Pp + (u64)((which*64 + pair)*4 + ks)*16384;
    #pragma unroll
    for (int r = 0; r < 8; r++){
        int row = ty*4 + (r & 3) + (r >= 4 ? 64 : 0);
        float2 p0 = unpack2(acc2[r][0]), p1 = unpack2(acc2[r][1]);
        float2 p2 = unpack2(acc2[r][2]), p3 = unpack2(acc2[r][3]);
        float4 v0 = {p0.x, p0.y, p1.x, p1.y};
        float4 v1 = {p2.x, p2.y, p3.x, p3.y};
        *(float4*)(pp + row*128 + tx*4)      = v0;
        *(float4*)(pp + row*128 + tx*4 + 64) = v1;
    }
}

// ---------------- o = scale * k @ (sum of P partials) (f32x2) --------------
__global__ __launch_bounds__(256) void gemm_o_kernel()
{
    __shared__ __align__(16) float As[16*132];
    __shared__ __align__(16) float Bs[16*128];
    int jt = blockIdx.x, pair = blockIdx.y, which = blockIdx.z;
    int b = pair >> 3, nh = pair & 7;
    const float* Kt = which ? g_hqkv : g_wqkv;
    float* out = which ? g_ho : g_wo;
    int tid = threadIdx.x, ty = tid >> 4, tx = tid & 15;
    const float* kb = Kt + (u64)(b*192 + nh*24 + 8 + jt)*HW;
    const float* pb = g_Pp + (u64)(which*64 + pair)*4*16384;
    u64 acc2[8][4];
    #pragma unroll
    for (int r = 0; r < 8; r++)
        #pragma unroll
        for (int j = 0; j < 4; j++) acc2[r][j] = 0ull;

    #pragma unroll 1
    for (int k0 = 0; k0 < 128; k0 += 16){
        #pragma unroll
        for (int i = 0; i < 8; i++){
            int idx = tid + i*256;
            int j = idx >> 4, k = idx & 15;
            As[k*132 + j] = kb[j*128 + k0 + k];
        }
        #pragma unroll
        for (int i = 0; i < 2; i++){
            int idx4 = tid + i*256;
            float4 p0 = ((const float4*)(pb           ))[k0*32 + idx4];
            float4 p1 = ((const float4*)(pb + 16384   ))[k0*32 + idx4];
            float4 p2 = ((const float4*)(pb + 2*16384 ))[k0*32 + idx4];
            float4 p3 = ((const float4*)(pb + 3*16384 ))[k0*32 + idx4];
            float4 s = {p0.x+p1.x+p2.x+p3.x, p0.y+p1.y+p2.y+p3.y,
                        p0.z+p1.z+p2.z+p3.z, p0.w+p1.w+p2.w+p3.w};
            ((float4*)Bs)[idx4] = s;
        }
        __syncthreads();
        const float4* Bq = (const float4*)Bs;
        #pragma unroll
        for (int k = 0; k < 16; k++){
            float4 a0 = *(const float4*)(As + k*132 + ty*4);
            float4 a1 = *(const float4*)(As + k*132 + ty*4 + 64);
            float4 b0 = Bq[k*32 + tx];
            float4 b1 = Bq[k*32 + tx + 16];
            u64 da[8] = {pack2(a0.x,a0.x), pack2(a0.y,a0.y), pack2(a0.z,a0.z), pack2(a0.w,a0.w),
                         pack2(a1.x,a1.x), pack2(a1.y,a1.y), pack2(a1.z,a1.z), pack2(a1.w,a1.w)};
            u64 xd[4] = {pack2(b0.x,b0.y), pack2(b0.z,b0.w), pack2(b1.x,b1.y), pack2(b1.z,b1.w)};
            #pragma unroll
            for (int r = 0; r < 8; r++)
                #pragma unroll
                for (int j = 0; j < 4; j++)
                    ffma2(acc2[r][j], da[r], xd[j]);
        }
        __syncthreads();
    }
    const float scale = 0.707106781186547524f;
    float* ob = out + (u64)(b*NC + nh*8 + jt)*HW;
    #pragma unroll
    for (int r = 0; r < 8; r++){
        int row = ty*4 + (r & 3) + (r >= 4 ? 64 : 0);
        float2 p0 = unpack2(acc2[r][0]), p1 = unpack2(acc2[r][1]);
        float2 p2 = unpack2(acc2[r][2]), p3 = unpack2(acc2[r][3]);
        float4 v0 = {p0.x*scale, p0.y*scale, p1.x*scale, p1.y*scale};
        float4 v1 = {p2.x*scale, p2.y*scale, p3.x*scale, p3.y*scale};
        *(float4*)(ob + row*SW + tx*4)      = v0;
        *(float4*)(ob + row*SW + tx*4 + 64) = v1;
    }
}

// ---------------- epilogue: out-projections + sigmoid gate (f32x2) ---------
__global__ __launch_bounds__(128) void epi_kernel(const float* __restrict__ x,
    const float* __restrict__ wow, const float* __restrict__ wob,
    const float* __restrict__ how, const float* __restrict__ hob,
    float* __restrict__ out)
{
    extern __shared__ float sm[];
    float* Ws = sm;
    float* Hs = sm + 4352;
    float* Xw = sm + 8704;
    float* Xh = sm + 8704 + 2048;
    int pt = blockIdx.x, b = blockIdx.y;
    int px0 = pt * 128;
    int tid = threadIdx.x, ty = tid >> 4, tx = tid & 15;

    #pragma unroll
    for (int i = 0; i < 32; i++){
        int idx = tid + i*128;
        int o = idx >> 6, ci = idx & 63;
        Ws[ci*68 + o] = wow[idx];
        Hs[ci*68 + o] = how[idx];
    }
    u64 acc2[8][4];
    #pragma unroll
    for (int r = 0; r < 8; r++)
        #pragma unroll
        for (int j = 0; j < 4; j++) acc2[r][j] = 0ull;

    #pragma unroll 1
    for (int kc = 0; kc < 4; kc++){
        if (kc) __syncthreads();
        #pragma unroll
        for (int i = 0; i < 4; i++){
            int idx4 = tid + i*128;
            int ci = idx4 >> 5, p4 = idx4 & 31;
            ((float4*)Xw)[idx4] = *(const float4*)(g_wo + (u64)(b*NC + kc*16 + ci)*HW + px0 + p4*4);
            ((float4*)Xh)[idx4] = *(const float4*)(g_ho + (u64)(b*NC + kc*16 + ci)*HW + px0 + p4*4);
        }
        __syncthreads();
        const float4* Xwq = (const float4*)Xw;
        const float4* Xhq = (const float4*)Xh;
        #pragma unroll 2
        for (int c16 = 0; c16 < 16; c16++){
            int ci = kc*16 + c16;
            float4 aw0 = *(const float4*)(Ws + ci*68 + ty*8);
            float4 aw1 = *(const float4*)(Ws + ci*68 + ty*8 + 4);
            float4 ah0 = *(const float4*)(Hs + ci*68 + ty*8);
            float4 ah1 = *(const float4*)(Hs + ci*68 + ty*8 + 4);
            float4 xw0 = Xwq[c16*32 + tx];
            float4 xw1 = Xwq[c16*32 + tx + 16];
            float4 xh0 = Xhq[c16*32 + tx];
            float4 xh1 = Xhq[c16*32 + tx + 16];
            u64 dw[8] = {pack2(aw0.x,aw0.x), pack2(aw0.y,aw0.y), pack2(aw0.z,aw0.z), pack2(aw0.w,aw0.w),
                         pack2(aw1.x,aw1.x), pack2(aw1.y,aw1.y), pack2(aw1.z,aw1.z), pack2(aw1.w,aw1.w)};
            u64 dh[8] = {pack2(ah0.x,ah0.x), pack2(ah0.y,ah0.y), pack2(ah0.z,ah0.z), pack2(ah0.w,ah0.w),
                         pack2(ah1.x,ah1.x), pack2(ah1.y,ah1.y), pack2(ah1.z,ah1.z), pack2(ah1.w,ah1.w)};
            u64 xwd[4] = {pack2(xw0.x,xw0.y), pack2(xw0.z,xw0.w), pack2(xw1.x,xw1.y), pack2(xw1.z,xw1.w)};
            u64 xhd[4] = {pack2(xh0.x,xh0.y), pack2(xh0.z,xh0.w), pack2(xh1.x,xh1.y), pack2(xh1.z,xh1.w)};
            #pragma unroll
            for (int r = 0; r < 8; r++)
                #pragma unroll
                for (int j = 0; j < 4; j++){
                    ffma2(acc2[r][j], dw[r], xwd[j]);
                    ffma2(acc2[r][j], dh[r], xhd[j]);
                }
        }
    }
    #pragma unroll
    for (int r = 0; r < 8; r++){
        int c = ty*8 + r;
        float bv = wob[c] + hob[c];
        const float* xb = x + (u64)(b*NC + c)*HW + px0;
        float* ob = out + (u64)(b*NC + c)*HW + px0;
        float av[8];
        float2 p0 = unpack2(acc2[r][0]), p1 = unpack2(acc2[r][1]);
        float2 p2 = unpack2(acc2[r][2]), p3 = unpack2(acc2[r][3]);
        av[0]=p0.x; av[1]=p0.y; av[2]=p1.x; av[3]=p1.y;
        av[4]=p2.x; av[5]=p2.y; av[6]=p3.x; av[7]=p3.y;
        #pragma unroll
        for (int half = 0; half < 2; half++){
            float4 xv = *(const float4*)(xb + tx*4 + half*64);
            float vs[4];
            #pragma unroll
            for (int j = 0; j < 4; j++){
                float s = av[half*4 + j] + bv;
                vs[j] = (&xv.x)[j] * (1.f / (1.f + expf(-s)));
            }
            float4 v = {vs[0], vs[1], vs[2], vs[3]};
            *(float4*)(ob + tx*4 + half*64) = v;
        }
    }
}

// ---------------- launch ---------------------------------------------------
extern "C" void kernel_launch(void* const* d_in, const int* in_sizes, int n_in,
                              void* d_out, int out_size)
{
    const float* x = (const float*)d_in[0];
    int i1w[3], i1b[3], i2w[3], i2b[3];
    if (in_sizes[11] == 45056){ // reference-signature order
        i1w[0]=9;  i1w[1]=11; i1w[2]=13;  i1b[0]=10; i1b[1]=12; i1b[2]=14;
        i2w[0]=15; i2w[1]=17; i2w[2]=19;  i2b[0]=16; i2b[1]=18; i2b[2]=20;
    } else {                    // setup_inputs dict order
        i1w[0]=9;  i1w[1]=13; i1w[2]=17;  i1b[0]=10; i1b[1]=14; i1b[2]=18;
        i2w[0]=11; i2w[1]=15; i2w[2]=19;  i2b[0]=12; i2b[1]=16; i2b[2]=20;
    }
    const float* bn1g=(const float*)d_in[1]; const float* bn1b=(const float*)d_in[2];
    const float* bn1m=(const float*)d_in[3]; const float* bn1v=(const float*)d_in[4];
    const float* bn2g=(const float*)d_in[5]; const float* bn2b=(const float*)d_in[6];
    const float* bn2m=(const float*)d_in[7]; const float* bn2v=(const float*)d_in[8];
    const float* hqkvw=(const float*)d_in[21]; const float* hqkvb=(const float*)d_in[22];
    const float* wqkvw=(const float*)d_in[23]; const float* wqkvb=(const float*)d_in[24];
    const float* houtw=(const float*)d_in[25]; const float* houtb=(const float*)d_in[26];
    const float* woutw=(const float*)d_in[27]; const float* woutb=(const float*)d_in[28];

    int sm_h = (384*SROW + 2*WSLAB) * 2;   // 73728 B
    int sm_w = (296*SROW + 2*WSLAB) * 2;   // 61056 B
    cudaFuncSetAttribute(conv_h_kernel, cudaFuncAttributeMaxDynamicSharedMemorySize, sm_h);
    cudaFuncSetAttribute(conv_w_kernel, cudaFuncAttributeMaxDynamicSharedMemorySize, sm_w);
    cudaFuncSetAttribute(pw_kernel,     cudaFuncAttributeMaxDynamicSharedMemorySize, 64*1024);
    cudaFuncSetAttribute(epi_kernel,    cudaFuncAttributeMaxDynamicSharedMemorySize, 64*1024);

    xt_kernel<<<dim3(SH, NB), 256>>>(x);
    prep_kernel<<<NC, 128>>>(0,
        (const float*)d_in[i1w[0]], (const float*)d_in[i1b[0]],
        (const float*)d_in[i1w[1]], (const float*)d_in[i1b[1]],
        (const float*)d_in[i1w[2]], (const float*)d_in[i1b[2]],
        bn1g, bn1b, bn1m, bn1v);
    prep_kernel<<<NC, 128>>>(1,
        (const float*)d_in[i2w[0]], (const float*)d_in[i2b[0]],
        (const float*)d_in[i2w[1]], (const float*)d_in[i2b[1]],
        (const float*)d_in[i2w[2]], (const float*)d_in[i2b[2]],
        bn2g, bn2b, bn2m, bn2v);

    conv_h_kernel<<<dim3(64, NB), 256, sm_h>>>();
    conv_w_kernel<<<dim3(64, NB), 256, sm_w>>>();

    pw_kernel<<<dim3(128, NB, 3), 128, (4352 + 8192)*4>>>(0, hqkvw, hqkvb);
    pw_kernel<<<dim3(128, NB, 3), 128, (4352 + 8192)*4>>>(1, wqkvw, wqkvb);

    gemm_p_kernel<<<dim3(64, 4, 2), 256>>>();
    gemm_o_kernel<<<dim3(8, 64, 2), 256>>>();

    epi_kernel<<<dim3(128, NB), 128, (8704 + 4096)*4>>>(x, woutw, woutb, houtw, houtb,
                                                        (float*)d_out);
}

// round 9
// speedup vs baseline: 3.5655x; 1.0533x over previous
#include <cuda_runtime.h>
#include <cuda_fp16.h>

#define NB 8
#define NC 64
#define SH 128
#define SW 128
#define HW (SH*SW)
#define KT 21

typedef unsigned long long u64;
typedef unsigned int u32;

// ---------------- scratch (device globals; no allocations) ----------------
__device__ __align__(16) __half g_Whh[KT*4096];    // fp16 folded W [t][co][ci]
__device__ __align__(16) __half g_Wwh[KT*4096];
__device__ __align__(16) __half g_xt[(u64)NB*SH*SW*NC]; // NHWC fp16 input
__device__ __align__(16) float g_rbh[NC*SH];
__device__ __align__(16) float g_rbw[NC*SW];
__device__ __align__(16) float g_hqkv[NB*192*HW];
__device__ __align__(16) float g_wqkv[NB*192*HW];
__device__ __align__(16) float g_Pp[2*64*4*SW*SW];
__device__ __align__(16) float g_wo[NB*NC*HW];
__device__ __align__(16) float g_ho[NB*NC*HW];

// ---------------- fp16 mma helper ------------------------------------------
__device__ __forceinline__ void mma_f16(float* d, const u32* a, const u32* b){
    asm volatile("mma.sync.aligned.m16n8k16.row.col.f32.f16.f16.f32 "
        "{%0,%1,%2,%3}, {%4,%5,%6,%7}, {%8,%9}, {%0,%1,%2,%3};\n"
        : "+f"(d[0]), "+f"(d[1]), "+f"(d[2]), "+f"(d[3])
        : "r"(a[0]), "r"(a[1]), "r"(a[2]), "r"(a[3]), "r"(b[0]), "r"(b[1]));
}

// ---------------- cp.async helpers -----------------------------------------
__device__ __forceinline__ u32 smem_u32(const void* p){
    u32 a; asm("{ .reg .u64 t; cvta.to.shared.u64 t, %1; cvt.u32.u64 %0, t; }"
               : "=r"(a) : "l"(p));
    return a;
}
__device__ __forceinline__ void cpa16(u32 dst, const void* src, u32 srcsize){
    asm volatile("cp.async.cg.shared.global [%0], [%1], 16, %2;"
                 :: "r"(dst), "l"(src), "r"(srcsize) : "memory");
}
#define CPA_COMMIT() asm volatile("cp.async.commit_group;" ::: "memory")
#define CPA_WAIT0()  asm volatile("cp.async.wait_group 0;" ::: "memory")

// ---------------- f32x2 packed fma helpers (exact fp32 math) ---------------
__device__ __forceinline__ u64 pack2(float x, float y){
    u64 r; asm("mov.b64 %0, {%1,%2};" : "=l"(r) : "f"(x), "f"(y)); return r;
}
__device__ __forceinline__ void ffma2(u64& d, u64 a, u64 b){
    asm("fma.rn.f32x2 %0, %1, %2, %0;" : "+l"(d) : "l"(a), "l"(b));
}
__device__ __forceinline__ float2 unpack2(u64 d){
    float2 f; asm("mov.b64 {%0,%1}, %2;" : "=f"(f.x), "=f"(f.y) : "l"(d)); return f;
}

// ---------------- x -> NHWC fp16 transpose ---------------------------------
__global__ __launch_bounds__(256) void xt_kernel(const float* __restrict__ x)
{
    __shared__ __half T[NC*132];
    int h = blockIdx.x, b = blockIdx.y;
    int tid = threadIdx.x;
    #pragma unroll
    for (int i = 0; i < 8; i++){
        int idx4 = tid + i*256;
        int ci = idx4 >> 5, w4 = idx4 & 31;
        float4 v = *(const float4*)(x + (u64)(b*NC + ci)*HW + h*SW + w4*4);
        T[ci*132 + w4*4 + 0] = __float2half_rn(v.x);
        T[ci*132 + w4*4 + 1] = __float2half_rn(v.y);
        T[ci*132 + w4*4 + 2] = __float2half_rn(v.z);
        T[ci*132 + w4*4 + 3] = __float2half_rn(v.w);
    }
    __syncthreads();
    #pragma unroll
    for (int i = 0; i < 4; i++){
        int oct = tid + i*256;
        int w = oct >> 3, c8 = oct & 7;
        u32 rr[4];
        #pragma unroll
        for (int j = 0; j < 4; j++){
            __half2 hv;
            hv.x = T[(c8*8 + 2*j)*132 + w];
            hv.y = T[(c8*8 + 2*j + 1)*132 + w];
            rr[j] = *(u32*)&hv;
        }
        *(uint4*)(g_xt + ((u64)((b*SH + h)*SW + w))*NC + c8*8) =
            make_uint4(rr[0], rr[1], rr[2], rr[3]);
    }
}

// ---------------- prep: combine strip kernels, fold BN, fp16 W, biases -----
__global__ void prep_kernel(int side,
    const float* __restrict__ w7,  const float* __restrict__ b7,
    const float* __restrict__ w11, const float* __restrict__ b11,
    const float* __restrict__ w21, const float* __restrict__ b21,
    const float* __restrict__ bng, const float* __restrict__ bnb,
    const float* __restrict__ bnm, const float* __restrict__ bnv)
{
    __half* Wout = side ? g_Wwh : g_Whh;
    float* rbout = side ? g_rbw : g_rbh;
    int co = blockIdx.x;
    int tid = threadIdx.x;
    __shared__ float Wraw[NC*KT];
    __shared__ float Pfx[NC*(KT+1)];

    for (int idx = tid; idx < NC*KT; idx += blockDim.x){
        int ci = idx / KT, t = idx % KT;
        float v = w21[(co*NC+ci)*21 + t];
        if (t >= 5 && t < 16) v += w11[(co*NC+ci)*11 + (t-5)];
        if (t >= 7 && t < 14) v += w7 [(co*NC+ci)*7  + (t-7)];
        Wraw[idx] = v;
        float a = bng[ci] * rsqrtf(bnv[ci] + 1e-5f);
        Wout[t*4096 + co*64 + ci] = __float2half_rn(v * a);
    }
    __syncthreads();
    if (tid < NC){
        int ci = tid;
        float a = bng[ci] * rsqrtf(bnv[ci] + 1e-5f);
        float c = bnb[ci] - bnm[ci] * a;
        float s = 0.f;
        Pfx[ci*(KT+1)] = 0.f;
        for (int t = 0; t < KT; t++){
            s += Wraw[ci*KT + t] * c;
            Pfx[ci*(KT+1) + t + 1] = s;
        }
    }
    __syncthreads();
    float cb = b7[co] + b11[co] + b21[co];
    for (int h = tid; h < SH; h += blockDim.x){
        int t0 = 10 - h;  if (t0 < 0) t0 = 0;
        int t1 = 137 - h; if (t1 > KT-1) t1 = KT-1;
        float s = cb;
        for (int ci = 0; ci < NC; ci++)
            s += Pfx[ci*(KT+1) + t1 + 1] - Pfx[ci*(KT+1) + t0];
        rbout[co*SH + h] = s;
    }
}

// ======== fused conv (fp16 mma) + qkv projection (exact f32x2) ==============
// grid (64 hpair, NB, 2 side). Block = (b, rows h0,h0+1, side).
// Phase 1: 21-tap conv via m16n8k16, async staging (as R8).
// Phase 2: stage D+rb fp32 -> Ds[64ci][260], then 3 og-slabs of the 192x64
//          projection in f32x2 (bit-identical to old pw), store qkv fp32.
#define SROW 72
#define WSLAB (64*SROW)          // halves per W slab
#define DS_STR 260
#define W2_STR 68

__global__ __launch_bounds__(256, 2) void conv_fused_kernel(
    const float* __restrict__ hqkv_w, const float* __restrict__ hqkv_b,
    const float* __restrict__ wqkv_w, const float* __restrict__ wqkv_b)
{
    extern __shared__ char smem_raw[];
    __half* Xs = (__half*)smem_raw;            // 384 rows x 72 halves
    __half* Ws = Xs + 384*SROW;                // 2 W slabs
    int h0 = blockIdx.x * 2, b = blockIdx.y;
    int side = blockIdx.z;                     // 0 = h-branch, 1 = w-branch
    int tid = threadIdx.x;
    int wid = tid >> 5, lid = tid & 31;
    int gid = lid >> 2, tig = lid & 3;
    int r = wid >> 2, pxq = (wid & 3) * 32;
    u32 xs_b = smem_u32(Xs);
    u32 ws_b = smem_u32(Ws);

    const __half* Wsrc = side ? g_Wwh : g_Whh;
    // ---- initial X staging ----
    if (side){
        for (int i = tid; i < 296*8; i += 256){
            int row = i >> 3, c16 = i & 7;
            int rr = (row >= 148), wp = row - rr*148 - 10;
            uint4 v = make_uint4(0,0,0,0);
            if ((unsigned)wp < 128u)
                v = *(const uint4*)(g_xt + ((u64)((b*SH + h0 + rr)*SW + wp))*NC + c16*8);
            *(uint4*)(Xs + row*SROW + c16*8) = v;
        }
    } else {
        #pragma unroll
        for (int s = 0; s < 2; s++){
            int hp = h0 - 10 + s;
            int slot = (hp + 12) % 3;
            for (int i = tid; i < 128*8; i += 256){
                int w = i >> 3, c16 = i & 7;
                uint4 v = make_uint4(0,0,0,0);
                if ((unsigned)hp < 128u)
                    v = *(const uint4*)(g_xt + ((u64)((b*SH + hp)*SW + w))*NC + c16*8);
                *(uint4*)(Xs + (slot*128 + w)*SROW + c16*8) = v;
            }
        }
    }
    // ---- W tap 0 -> slab 0 ----
    for (int i = tid; i < 512; i += 256){
        int row = i >> 3, c16 = i & 7;
        *(uint4*)(Ws + row*SROW + c16*8) = *(const uint4*)(Wsrc + row*64 + c16*8);
    }
    __syncthreads();

    float d[4][4][4];
    #pragma unroll
    for (int i = 0; i < 4; i++)
        #pragma unroll
        for (int j = 0; j < 4; j++)
            #pragma unroll
            for (int k = 0; k < 4; k++) d[i][j][k] = 0.f;

    #pragma unroll 1
    for (int t = 0; t < KT; t++){
        if (t < KT-1){
            if (!side){
                int nrow = h0 + t - 8;
                int slot = (nrow + 12) % 3;
                u32 ok = ((unsigned)nrow < 128u) ? 16u : 0u;
                int crow = nrow < 0 ? 0 : (nrow > 127 ? 127 : nrow);
                const __half* src = g_xt + ((u64)((b*SH + crow)*SW))*NC;
                #pragma unroll
                for (int i = 0; i < 4; i++){
                    int idx = tid + i*256;
                    int w = idx >> 3, c16 = idx & 7;
                    cpa16(xs_b + ((slot*128 + w)*SROW + c16*8)*2,
                          src + (u64)w*NC + c16*8, ok);
                }
            }
            {
                const __half* wsrc = Wsrc + (t+1)*4096;
                u32 wdst = ws_b + (((t+1) & 1)*WSLAB)*2;
                #pragma unroll
                for (int i = 0; i < 2; i++){
                    int idx = tid + i*256;
                    int row = idx >> 3, c16 = idx & 7;
                    cpa16(wdst + (row*SROW + c16*8)*2, wsrc + row*64 + c16*8, 16);
                }
            }
            CPA_COMMIT();
        }
        // ---- compute tap t ----
        const __half* Wt = Ws + (t & 1)*WSLAB;
        const __half* xbase = side
            ? Xs + (r*148 + pxq + t)*SROW
            : Xs + (((h0 + t + r + 2) % 3)*128 + pxq)*SROW;
        #pragma unroll
        for (int kc = 0; kc < 4; kc++){
            u32 bf[4][2];
            #pragma unroll
            for (int j = 0; j < 4; j++){
                const u32* bp = (const u32*)(xbase + (j*8 + gid)*SROW + kc*16 + tig*2);
                bf[j][0] = bp[0]; bf[j][1] = bp[4];
            }
            u32 af[4][4];
            #pragma unroll
            for (int i = 0; i < 4; i++){
                const u32* ap0 = (const u32*)(Wt + (i*16 + gid)*SROW + kc*16 + tig*2);
                const u32* ap1 = (const u32*)(Wt + (i*16 + gid + 8)*SROW + kc*16 + tig*2);
                af[i][0] = ap0[0]; af[i][1] = ap1[0];
                af[i][2] = ap0[4]; af[i][3] = ap1[4];
            }
            #pragma unroll
            for (int i = 0; i < 4; i++)
                #pragma unroll
                for (int j = 0; j < 4; j++)
                    mma_f16(d[i][j], af[i], bf[j]);
        }
        if (t < KT-1){
            CPA_WAIT0();
            __syncthreads();
        }
    }

    // ================= Phase 2: fused qkv projection ========================
    float* Ds  = (float*)smem_raw;                 // [64ci][260]
    float* W2s = (float*)(smem_raw + 64*DS_STR*4); // [64ci][68]
    const float* w2   = side ? wqkv_w : hqkv_w;
    const float* bias = side ? wqkv_b : hqkv_b;
    float* qkv = side ? g_wqkv : g_hqkv;

    __syncthreads();   // mainloop smem reads done
    // stage D + rb (fp32, exact)
    #pragma unroll
    for (int i = 0; i < 4; i++){
        #pragma unroll
        for (int half = 0; half < 2; half++){
            int co = i*16 + gid + half*8;
            float rbv = side ? 0.f : g_rbh[co*SH + h0 + r];
            #pragma unroll
            for (int j = 0; j < 4; j++){
                int px = pxq + j*8 + tig*2;
                float vx = d[i][j][half*2 + 0];
                float vy = d[i][j][half*2 + 1];
                if (side){
                    float2 bb = *(const float2*)(g_rbw + co*SW + px);
                    vx += bb.x; vy += bb.y;
                } else { vx += rbv; vy += rbv; }
                *(float2*)&Ds[co*DS_STR + r*128 + px] = make_float2(vx, vy);
            }
        }
    }
    __syncthreads();

    #pragma unroll 1
    for (int og = 0; og < 3; og++){
        if (og) __syncthreads();           // prior og's readers done
        for (int it = tid; it < 4096; it += 256){
            int o = it >> 6, ci = it & 63;
            W2s[ci*W2_STR + o] = w2[og*4096 + it];
        }
        __syncthreads();
        u64 acc2[8][4];
        #pragma unroll
        for (int rr = 0; rr < 8; rr++)
            #pragma unroll
            for (int j = 0; j < 4; j++) acc2[rr][j] = 0ull;
        int tx = lid;                      // 0..31
        #pragma unroll 4
        for (int ci = 0; ci < NC; ci++){
            float4 a0 = *(const float4*)(W2s + ci*W2_STR + wid*8);
            float4 a1 = *(const float4*)(W2s + ci*W2_STR + wid*8 + 4);
            float4 x0 = *(const float4*)(Ds + ci*DS_STR + tx*4);
            float4 x1 = *(const float4*)(Ds + ci*DS_STR + tx*4 + 128);
            u64 da[8] = {pack2(a0.x,a0.x), pack2(a0.y,a0.y), pack2(a0.z,a0.z), pack2(a0.w,a0.w),
                         pack2(a1.x,a1.x), pack2(a1.y,a1.y), pack2(a1.z,a1.z), pack2(a1.w,a1.w)};
            u64 xd[4] = {pack2(x0.x,x0.y), pack2(x0.z,x0.w), pack2(x1.x,x1.y), pack2(x1.z,x1.w)};
            #pragma unroll
            for (int rr = 0; rr < 8; rr++)
                #pragma unroll
                for (int j = 0; j < 4; j++)
                    ffma2(acc2[rr][j], da[rr], xd[j]);
        }
        #pragma unroll
        for (int rr = 0; rr < 8; rr++){
            int o = og*64 + wid*8 + rr;
            float bv = bias[o];
            float* ob = qkv + (u64)(b*192 + o)*HW + h0*SW;
            float2 p0 = unpack2(acc2[rr][0]), p1 = unpack2(acc2[rr][1]);
            float2 p2 = unpack2(acc2[rr][2]), p3 = unpack2(acc2[rr][3]);
            float4 v0 = {p0.x+bv, p0.y+bv, p1.x+bv, p1.y+bv};   // row h0
            float4 v1 = {p2.x+bv, p2.y+bv, p3.x+bv, p3.y+bv};   // row h0+1
            *(float4*)(ob + tx*4)      = v0;
            *(float4*)(ob + SW + tx*4) = v1;
        }
    }
}

// ---------------- P partials: both branches, K split 4 (f32x2) -------------
__global__ __launch_bounds__(256) void gemm_p_kernel()
{
    __shared__ __align__(16) float As[16*128];
    __shared__ __align__(16) float Bs[16*128];
    int pair = blockIdx.x, ks = blockIdx.y, which = blockIdx.z;
    int b = pair >> 3, nh = pair & 7;
    const float* A  = which ? g_wqkv : g_hqkv;
    const float* Bm = which ? g_hqkv : g_wqkv;
    int tid = threadIdx.x, ty = tid >> 4, tx = tid & 15;
    u64 acc2[8][4];
    #pragma unroll
    for (int r = 0; r < 8; r++)
        #pragma unroll
        for (int j = 0; j < 4; j++) acc2[r][j] = 0ull;
    const float* abase = A  + (u64)(b*192 + nh*24 + 0 )*HW + ks*256*SW;
    const float* bbase = Bm + (u64)(b*192 + nh*24 + 16)*HW + ks*256*SW;

    #pragma unroll 1
    for (int k0 = 0; k0 < 256; k0 += 16){
        const float4* ap = (const float4*)(abase + k0*SW);
        const float4* bp = (const float4*)(bbase + k0*SW);
        #pragma unroll
        for (int i = 0; i < 2; i++){
            ((float4*)As)[tid + i*256] = ap[tid + i*256];
            ((float4*)Bs)[tid + i*256] = bp[tid + i*256];
        }
        __syncthreads();
        const float4* Aq = (const float4*)As;
        const float4* Bq = (const float4*)Bs;
        #pragma unroll
        for (int k = 0; k < 16; k++){
            float4 a0 = Aq[k*32 + ty];
            float4 a1 = Aq[k*32 + ty + 16];
            float4 b0 = Bq[k*32 + tx];
            float4 b1 = Bq[k*32 + tx + 16];
            u64 da[8] = {pack2(a0.x,a0.x), pack2(a0.y,a0.y), pack2(a0.z,a0.z), pack2(a0.w,a0.w),
                         pack2(a1.x,a1.x), pack2(a1.y,a1.y), pack2(a1.z,a1.z), pack2(a1.w,a1.w)};
            u64 xd[4] = {pack2(b0.x,b0.y), pack2(b0.z,b0.w), pack2(b1.x,b1.y), pack2(b1.z,b1.w)};
            #pragma unroll
            for (int r = 0; r < 8; r++)
                #pragma unroll
                for (int j = 0; j < 4; j++)
                    ffma2(acc2[r][j], da[r], xd[j]);
        }
        __syncthreads();
    }
    float* pp = g_Pp + (u64)((which*64 + pair)*4 + ks)*16384;
    #pragma unroll
    for (int r = 0; r < 8; r++){
        int row = ty*4 + (r & 3) + (r >= 4 ? 64 : 0);
        float2 p0 = unpack2(acc2[r][0]), p1 = unpack2(acc2[r][1]);
        float2 p2 = unpack2(acc2[r][2]), p3 = unpack2(acc2[r][3]);
        float4 v0 = {p0.x, p0.y, p1.x, p1.y};
        float4 v1 = {p2.x, p2.y, p3.x, p3.y};
        *(float4*)(pp + row*128 + tx*4)      = v0;
        *(float4*)(pp + row*128 + tx*4 + 64) = v1;
    }
}

// ---------------- o = scale * k @ (sum of P partials) (f32x2) --------------
__global__ __launch_bounds__(256) void gemm_o_kernel()
{
    __shared__ __align__(16) float As[16*132];
    __shared__ __align__(16) float Bs[16*128];
    int jt = blockIdx.x, pair = blockIdx.y, which = blockIdx.z;
    int b = pair >> 3, nh = pair & 7;
    const float* Kt = which ? g_hqkv : g_wqkv;
    float* out = which ? g_ho : g_wo;
    int tid = threadIdx.x, ty = tid >> 4, tx = tid & 15;
    const float* kb = Kt + (u64)(b*192 + nh*24 + 8 + jt)*HW;
    const float* pb = g_Pp + (u64)(which*64 + pair)*4*16384;
    u64 acc2[8][4];
    #pragma unroll
    for (int r = 0; r < 8; r++)
        #pragma unroll
        for (int j = 0; j < 4; j++) acc2[r][j] = 0ull;

    #pragma unroll 1
    for (int k0 = 0; k0 < 128; k0 += 16){
        #pragma unroll
        for (int i = 0; i < 8; i++){
            int idx = tid + i*256;
            int j = idx >> 4, k = idx & 15;
            As[k*132 + j] = kb[j*128 + k0 + k];
        }
        #pragma unroll
        for (int i = 0; i < 2; i++){
            int idx4 = tid + i*256;
            float4 p0 = ((const float4*)(pb           ))[k0*32 + idx4];
            float4 p1 = ((const float4*)(pb + 16384   ))[k0*32 + idx4];
            float4 p2 = ((const float4*)(pb + 2*16384 ))[k0*32 + idx4];
            float4 p3 = ((const float4*)(pb + 3*16384 ))[k0*32 + idx4];
            float4 s = {p0.x+p1.x+p2.x+p3.x, p0.y+p1.y+p2.y+p3.y,
                        p0.z+p1.z+p2.z+p3.z, p0.w+p1.w+p2.w+p3.w};
            ((float4*)Bs)[idx4] = s;
        }
        __syncthreads();
        const float4* Bq = (const float4*)Bs;
        #pragma unroll
        for (int k = 0; k < 16; k++){
            float4 a0 = *(const float4*)(As + k*132 + ty*4);
            float4 a1 = *(const float4*)(As + k*132 + ty*4 + 64);
            float4 b0 = Bq[k*32 + tx];
            float4 b1 = Bq[k*32 + tx + 16];
            u64 da[8] = {pack2(a0.x,a0.x), pack2(a0.y,a0.y), pack2(a0.z,a0.z), pack2(a0.w,a0.w),
                         pack2(a1.x,a1.x), pack2(a1.y,a1.y), pack2(a1.z,a1.z), pack2(a1.w,a1.w)};
            u64 xd[4] = {pack2(b0.x,b0.y), pack2(b0.z,b0.w), pack2(b1.x,b1.y), pack2(b1.z,b1.w)};
            #pragma unroll
            for (int r = 0; r < 8; r++)
                #pragma unroll
                for (int j = 0; j < 4; j++)
                    ffma2(acc2[r][j], da[r], xd[j]);
        }
        __syncthreads();
    }
    const float scale = 0.707106781186547524f;
    float* ob = out + (u64)(b*NC + nh*8 + jt)*HW;
    #pragma unroll
    for (int r = 0; r < 8; r++){
        int row = ty*4 + (r & 3) + (r >= 4 ? 64 : 0);
        float2 p0 = unpack2(acc2[r][0]), p1 = unpack2(acc2[r][1]);
        float2 p2 = unpack2(acc2[r][2]), p3 = unpack2(acc2[r][3]);
        float4 v0 = {p0.x*scale, p0.y*scale, p1.x*scale, p1.y*scale};
        float4 v1 = {p2.x*scale, p2.y*scale, p3.x*scale, p3.y*scale};
        *(float4*)(ob + row*SW + tx*4)      = v0;
        *(float4*)(ob + row*SW + tx*4 + 64) = v1;
    }
}

// ---------------- epilogue: out-projections + sigmoid gate (f32x2) ---------
__global__ __launch_bounds__(128) void epi_kernel(const float* __restrict__ x,
    const float* __restrict__ wow, const float* __restrict__ wob,
    const float* __restrict__ how, const float* __restrict__ hob,
    float* __restrict__ out)
{
    extern __shared__ float sm[];
    float* Ws = sm;
    float* Hs = sm + 4352;
    float* Xw = sm + 8704;
    float* Xh = sm + 8704 + 2048;
    int pt = blockIdx.x, b = blockIdx.y;
    int px0 = pt * 128;
    int tid = threadIdx.x, ty = tid >> 4, tx = tid & 15;

    #pragma unroll
    for (int i = 0; i < 32; i++){
        int idx = tid + i*128;
        int o = idx >> 6, ci = idx & 63;
        Ws[ci*68 + o] = wow[idx];
        Hs[ci*68 + o] = how[idx];
    }
    u64 acc2[8][4];
    #pragma unroll
    for (int r = 0; r < 8; r++)
        #pragma unroll
        for (int j = 0; j < 4; j++) acc2[r][j] = 0ull;

    #pragma unroll 1
    for (int kc = 0; kc < 4; kc++){
        if (kc) __syncthreads();
        #pragma unroll
        for (int i = 0; i < 4; i++){
            int idx4 = tid + i*128;
            int ci = idx4 >> 5, p4 = idx4 & 31;
            ((float4*)Xw)[idx4] = *(const float4*)(g_wo + (u64)(b*NC + kc*16 + ci)*HW + px0 + p4*4);
            ((float4*)Xh)[idx4] = *(const float4*)(g_ho + (u64)(b*NC + kc*16 + ci)*HW + px0 + p4*4);
        }
        __syncthreads();
        const float4* Xwq = (const float4*)Xw;
        const float4* Xhq = (const float4*)Xh;
        #pragma unroll 2
        for (int c16 = 0; c16 < 16; c16++){
            int ci = kc*16 + c16;
            float4 aw0 = *(const float4*)(Ws + ci*68 + ty*8);
            float4 aw1 = *(const float4*)(Ws + ci*68 + ty*8 + 4);
            float4 ah0 = *(const float4*)(Hs + ci*68 + ty*8);
            float4 ah1 = *(const float4*)(Hs + ci*68 + ty*8 + 4);
            float4 xw0 = Xwq[c16*32 + tx];
            float4 xw1 = Xwq[c16*32 + tx + 16];
            float4 xh0 = Xhq[c16*32 + tx];
            float4 xh1 = Xhq[c16*32 + tx + 16];
            u64 dw[8] = {pack2(aw0.x,aw0.x), pack2(aw0.y,aw0.y), pack2(aw0.z,aw0.z), pack2(aw0.w,aw0.w),
                         pack2(aw1.x,aw1.x), pack2(aw1.y,aw1.y), pack2(aw1.z,aw1.z), pack2(aw1.w,aw1.w)};
            u64 dh[8] = {pack2(ah0.x,ah0.x), pack2(ah0.y,ah0.y), pack2(ah0.z,ah0.z), pack2(ah0.w,ah0.w),
                         pack2(ah1.x,ah1.x), pack2(ah1.y,ah1.y), pack2(ah1.z,ah1.z), pack2(ah1.w,ah1.w)};
            u64 xwd[4] = {pack2(xw0.x,xw0.y), pack2(xw0.z,xw0.w), pack2(xw1.x,xw1.y), pack2(xw1.z,xw1.w)};
            u64 xhd[4] = {pack2(xh0.x,xh0.y), pack2(xh0.z,xh0.w), pack2(xh1.x,xh1.y), pack2(xh1.z,xh1.w)};
            #pragma unroll
            for (int r = 0; r < 8; r++)
                #pragma unroll
                for (int j = 0; j < 4; j++){
                    ffma2(acc2[r][j], dw[r], xwd[j]);
                    ffma2(acc2[r][j], dh[r], xhd[j]);
                }
        }
    }
    #pragma unroll
    for (int r = 0; r < 8; r++){
        int c = ty*8 + r;
        float bv = wob[c] + hob[c];
        const float* xb = x + (u64)(b*NC + c)*HW + px0;
        float* ob = out + (u64)(b*NC + c)*HW + px0;
        float av[8];
        float2 p0 = unpack2(acc2[r][0]), p1 = unpack2(acc2[r][1]);
        float2 p2 = unpack2(acc2[r][2]), p3 = unpack2(acc2[r][3]);
        av[0]=p0.x; av[1]=p0.y; av[2]=p1.x; av[3]=p1.y;
        av[4]=p2.x; av[5]=p2.y; av[6]=p3.x; av[7]=p3.y;
        #pragma unroll
        for (int half = 0; half < 2; half++){
            float4 xv = *(const float4*)(xb + tx*4 + half*64);
            float vs[4];
            #pragma unroll
            for (int j = 0; j < 4; j++){
                float s = av[half*4 + j] + bv;
                vs[j] = (&xv.x)[j] * (1.f / (1.f + expf(-s)));
            }
            float4 v = {vs[0], vs[1], vs[2], vs[3]};
            *(float4*)(ob + tx*4 + half*64) = v;
        }
    }
}

// ---------------- launch ---------------------------------------------------
extern "C" void kernel_launch(void* const* d_in, const int* in_sizes, int n_in,
                              void* d_out, int out_size)
{
    const float* x = (const float*)d_in[0];
    int i1w[3], i1b[3], i2w[3], i2b[3];
    if (in_sizes[11] == 45056){ // reference-signature order
        i1w[0]=9;  i1w[1]=11; i1w[2]=13;  i1b[0]=10; i1b[1]=12; i1b[2]=14;
        i2w[0]=15; i2w[1]=17; i2w[2]=19;  i2b[0]=16; i2b[1]=18; i2b[2]=20;
    } else {                    // setup_inputs dict order
        i1w[0]=9;  i1w[1]=13; i1w[2]=17;  i1b[0]=10; i1b[1]=14; i1b[2]=18;
        i2w[0]=11; i2w[1]=15; i2w[2]=19;  i2b[0]=12; i2b[1]=16; i2b[2]=20;
    }
    const float* bn1g=(const float*)d_in[1]; const float* bn1b=(const float*)d_in[2];
    const float* bn1m=(const float*)d_in[3]; const float* bn1v=(const float*)d_in[4];
    const float* bn2g=(const float*)d_in[5]; const float* bn2b=(const float*)d_in[6];
    const float* bn2m=(const float*)d_in[7]; const float* bn2v=(const float*)d_in[8];
    const float* hqkvw=(const float*)d_in[21]; const float* hqkvb=(const float*)d_in[22];
    const float* wqkvw=(const float*)d_in[23]; const float* wqkvb=(const float*)d_in[24];
    const float* houtw=(const float*)d_in[25]; const float* houtb=(const float*)d_in[26];
    const float* woutw=(const float*)d_in[27]; const float* woutb=(const float*)d_in[28];

    // smem: max(mainloop 384*72*2 + 2*4608*2 = 73728, proj 64*260*4 + 64*68*4 = 83968)
    int sm_conv = 64*260*4 + 64*68*4;   // 83968 B
    cudaFuncSetAttribute(conv_fused_kernel, cudaFuncAttributeMaxDynamicSharedMemorySize, sm_conv);
    cudaFuncSetAttribute(epi_kernel, cudaFuncAttributeMaxDynamicSharedMemorySize, 64*1024);

    xt_kernel<<<dim3(SH, NB), 256>>>(x);
    prep_kernel<<<NC, 128>>>(0,
        (const float*)d_in[i1w[0]], (const float*)d_in[i1b[0]],
        (const float*)d_in[i1w[1]], (const float*)d_in[i1b[1]],
        (const float*)d_in[i1w[2]], (const float*)d_in[i1b[2]],
        bn1g, bn1b, bn1m, bn1v);
    prep_kernel<<<NC, 128>>>(1,
        (const float*)d_in[i2w[0]], (const float*)d_in[i2b[0]],
        (const float*)d_in[i2w[1]], (const float*)d_in[i2b[1]],
        (const float*)d_in[i2w[2]], (const float*)d_in[i2b[2]],
        bn2g, bn2b, bn2m, bn2v);

    conv_fused_kernel<<<dim3(64, NB, 2), 256, sm_conv>>>(hqkvw, hqkvb, wqkvw, wqkvb);

    gemm_p_kernel<<<dim3(64, 4, 2), 256>>>();
    gemm_o_kernel<<<dim3(8, 64, 2), 256>>>();

    epi_kernel<<<dim3(128, NB), 128, (8704 + 4096)*4>>>(x, woutw, woutb, houtw, houtb,
                                                        (float*)d_out);
}

// round 12
// speedup vs baseline: 4.4300x; 1.2425x over previous
#include <cuda_runtime.h>
#include <cuda_fp16.h>

#define NB 8
#define NC 64
#define SH 128
#define SW 128
#define HW (SH*SW)
#define KT 21

typedef unsigned long long u64;
typedef unsigned int u32;

// ---------------- scratch (device globals; no allocations) ----------------
__device__ __align__(16) __half g_Whh[KT*4096];    // fp16 folded W [t][co][ci]
__device__ __align__(16) __half g_Wwh[KT*4096];
__device__ __align__(16) __half g_xt[(u64)NB*SH*SW*NC]; // NHWC fp16 input
__device__ __align__(16) float g_rbh[NC*SH];
__device__ __align__(16) float g_rbw[NC*SW];
__device__ __align__(16) __half g_hqh[(u64)NB*192*HW];  // h-branch qkv hi
__device__ __align__(16) __half g_hql[(u64)NB*192*HW];  // h-branch qkv lo
__device__ __align__(16) __half g_wqh[(u64)NB*192*HW];
__device__ __align__(16) __half g_wql[(u64)NB*192*HW];
__device__ __align__(16) float g_Pp[2*64*4*SW*SW];      // P partials fp32
__device__ __align__(16) __half g_Ph[2*64*SW*SW];       // summed P hi
__device__ __align__(16) __half g_Pl[2*64*SW*SW];       // summed P lo
__device__ __align__(16) float g_wo[NB*NC*HW];
__device__ __align__(16) float g_ho[NB*NC*HW];

// ---------------- fp16 mma / ldmatrix helpers -------------------------------
__device__ __forceinline__ void mma_f16(float* d, const u32* a, const u32* b){
    asm volatile("mma.sync.aligned.m16n8k16.row.col.f32.f16.f16.f32 "
        "{%0,%1,%2,%3}, {%4,%5,%6,%7}, {%8,%9}, {%0,%1,%2,%3};\n"
        : "+f"(d[0]), "+f"(d[1]), "+f"(d[2]), "+f"(d[3])
        : "r"(a[0]), "r"(a[1]), "r"(a[2]), "r"(a[3]), "r"(b[0]), "r"(b[1]));
}
__device__ __forceinline__ void ldsm_x4(u32& r0,u32& r1,u32& r2,u32& r3, u32 addr){
    asm volatile("ldmatrix.sync.aligned.m8n8.x4.shared.b16 {%0,%1,%2,%3}, [%4];"
        : "=r"(r0),"=r"(r1),"=r"(r2),"=r"(r3) : "r"(addr));
}
__device__ __forceinline__ void ldsm_x4t(u32& r0,u32& r1,u32& r2,u32& r3, u32 addr){
    asm volatile("ldmatrix.sync.aligned.m8n8.x4.trans.shared.b16 {%0,%1,%2,%3}, [%4];"
        : "=r"(r0),"=r"(r1),"=r"(r2),"=r"(r3) : "r"(addr));
}

// ---------------- cp.async helpers -----------------------------------------
__device__ __forceinline__ u32 smem_u32(const void* p){
    u32 a; asm("{ .reg .u64 t; cvta.to.shared.u64 t, %1; cvt.u32.u64 %0, t; }"
               : "=r"(a) : "l"(p));
    return a;
}
__device__ __forceinline__ void cpa16(u32 dst, const void* src, u32 srcsize){
    asm volatile("cp.async.cg.shared.global [%0], [%1], 16, %2;"
                 :: "r"(dst), "l"(src), "r"(srcsize) : "memory");
}
#define CPA_COMMIT() asm volatile("cp.async.commit_group;" ::: "memory")
#define CPA_WAIT0()  asm volatile("cp.async.wait_group 0;" ::: "memory")
#define CPA_WAIT1()  asm volatile("cp.async.wait_group 1;" ::: "memory")

// ---------------- f32x2 packed fma helpers (exact fp32 math) ---------------
__device__ __forceinline__ u64 pack2(float x, float y){
    u64 r; asm("mov.b64 %0, {%1,%2};" : "=l"(r) : "f"(x), "f"(y)); return r;
}
__device__ __forceinline__ void ffma2(u64& d, u64 a, u64 b){
    asm("fma.rn.f32x2 %0, %1, %2, %0;" : "+l"(d) : "l"(a), "l"(b));
}
__device__ __forceinline__ float2 unpack2(u64 d){
    float2 f; asm("mov.b64 {%0,%1}, %2;" : "=f"(f.x), "=f"(f.y) : "l"(d)); return f;
}

// split 4 floats into hi/lo half4 (packed as uint2)
__device__ __forceinline__ void split4(const float* v, uint2& hi, uint2& lo){
    __half h[4], l[4];
    #pragma unroll
    for (int i = 0; i < 4; i++){
        h[i] = __float2half_rn(v[i]);
        l[i] = __float2half_rn(v[i] - __half2float(h[i]));
    }
    __half2 a0 = {h[0],h[1]}, a1 = {h[2],h[3]};
    __half2 b0 = {l[0],l[1]}, b1 = {l[2],l[3]};
    hi.x = *(u32*)&a0; hi.y = *(u32*)&a1;
    lo.x = *(u32*)&b0; lo.y = *(u32*)&b1;
}

// ---------------- x -> NHWC fp16 transpose ---------------------------------
__global__ __launch_bounds__(256) void xt_kernel(const float* __restrict__ x)
{
    __shared__ __half T[NC*132];
    int h = blockIdx.x, b = blockIdx.y;
    int tid = threadIdx.x;
    #pragma unroll
    for (int i = 0; i < 8; i++){
        int idx4 = tid + i*256;
        int ci = idx4 >> 5, w4 = idx4 & 31;
        float4 v = *(const float4*)(x + (u64)(b*NC + ci)*HW + h*SW + w4*4);
        T[ci*132 + w4*4 + 0] = __float2half_rn(v.x);
        T[ci*132 + w4*4 + 1] = __float2half_rn(v.y);
        T[ci*132 + w4*4 + 2] = __float2half_rn(v.z);
        T[ci*132 + w4*4 + 3] = __float2half_rn(v.w);
    }
    __syncthreads();
    #pragma unroll
    for (int i = 0; i < 4; i++){
        int oct = tid + i*256;
        int w = oct >> 3, c8 = oct & 7;
        u32 rr[4];
        #pragma unroll
        for (int j = 0; j < 4; j++){
            __half2 hv;
            hv.x = T[(c8*8 + 2*j)*132 + w];
            hv.y = T[(c8*8 + 2*j + 1)*132 + w];
            rr[j] = *(u32*)&hv;
        }
        *(uint4*)(g_xt + ((u64)((b*SH + h)*SW + w))*NC + c8*8) =
            make_uint4(rr[0], rr[1], rr[2], rr[3]);
    }
}

// ---------------- prep: combine strip kernels, fold BN, fp16 W, biases -----
__global__ void prep_kernel(int side,
    const float* __restrict__ w7,  const float* __restrict__ b7,
    const float* __restrict__ w11, const float* __restrict__ b11,
    const float* __restrict__ w21, const float* __restrict__ b21,
    const float* __restrict__ bng, const float* __restrict__ bnb,
    const float* __restrict__ bnm, const float* __restrict__ bnv)
{
    __half* Wout = side ? g_Wwh : g_Whh;
    float* rbout = side ? g_rbw : g_rbh;
    int co = blockIdx.x;
    int tid = threadIdx.x;
    __shared__ float Wraw[NC*KT];
    __shared__ float Pfx[NC*(KT+1)];

    for (int idx = tid; idx < NC*KT; idx += blockDim.x){
        int ci = idx / KT, t = idx % KT;
        float v = w21[(co*NC+ci)*21 + t];
        if (t >= 5 && t < 16) v += w11[(co*NC+ci)*11 + (t-5)];
        if (t >= 7 && t < 14) v += w7 [(co*NC+ci)*7  + (t-7)];
        Wraw[idx] = v;
        float a = bng[ci] * rsqrtf(bnv[ci] + 1e-5f);
        Wout[t*4096 + co*64 + ci] = __float2half_rn(v * a);
    }
    __syncthreads();
    if (tid < NC){
        int ci = tid;
        float a = bng[ci] * rsqrtf(bnv[ci] + 1e-5f);
        float c = bnb[ci] - bnm[ci] * a;
        float s = 0.f;
        Pfx[ci*(KT+1)] = 0.f;
        for (int t = 0; t < KT; t++){
            s += Wraw[ci*KT + t] * c;
            Pfx[ci*(KT+1) + t + 1] = s;
        }
    }
    __syncthreads();
    float cb = b7[co] + b11[co] + b21[co];
    for (int h = tid; h < SH; h += blockDim.x){
        int t0 = 10 - h;  if (t0 < 0) t0 = 0;
        int t1 = 137 - h; if (t1 > KT-1) t1 = KT-1;
        float s = cb;
        for (int ci = 0; ci < NC; ci++)
            s += Pfx[ci*(KT+1) + t1 + 1] - Pfx[ci*(KT+1) + t0];
        rbout[co*SH + h] = s;
    }
}

// ======== fused conv (fp16 mma) + qkv projection (exact f32x2) ==============
#define SROW 72
#define WSLAB (64*SROW)
#define DS_STR 260
#define W2_STR 68

__global__ __launch_bounds__(256, 2) void conv_fused_kernel(
    const float* __restrict__ hqkv_w, const float* __restrict__ hqkv_b,
    const float* __restrict__ wqkv_w, const float* __restrict__ wqkv_b)
{
    extern __shared__ char smem_raw[];
    __half* Xs = (__half*)smem_raw;            // 384 rows x 72 halves
    __half* Ws = Xs + 384*SROW;                // 2 W slabs
    int h0 = blockIdx.x * 2, b = blockIdx.y;
    int side = blockIdx.z;
    int tid = threadIdx.x;
    int wid = tid >> 5, lid = tid & 31;
    int gid = lid >> 2, tig = lid & 3;
    int r = wid >> 2, pxq = (wid & 3) * 32;
    u32 xs_b = smem_u32(Xs);
    u32 ws_b = smem_u32(Ws);

    const __half* Wsrc = side ? g_Wwh : g_Whh;
    if (side){
        for (int i = tid; i < 296*8; i += 256){
            int row = i >> 3, c16 = i & 7;
            int rr = (row >= 148), wp = row - rr*148 - 10;
            uint4 v = make_uint4(0,0,0,0);
            if ((unsigned)wp < 128u)
                v = *(const uint4*)(g_xt + ((u64)((b*SH + h0 + rr)*SW + wp))*NC + c16*8);
            *(uint4*)(Xs + row*SROW + c16*8) = v;
        }
    } else {
        #pragma unroll
        for (int s = 0; s < 2; s++){
            int hp = h0 - 10 + s;
            int slot = (hp + 12) % 3;
            for (int i = tid; i < 128*8; i += 256){
                int w = i >> 3, c16 = i & 7;
                uint4 v = make_uint4(0,0,0,0);
                if ((unsigned)hp < 128u)
                    v = *(const uint4*)(g_xt + ((u64)((b*SH + hp)*SW + w))*NC + c16*8);
                *(uint4*)(Xs + (slot*128 + w)*SROW + c16*8) = v;
            }
        }
    }
    for (int i = tid; i < 512; i += 256){
        int row = i >> 3, c16 = i & 7;
        *(uint4*)(Ws + row*SROW + c16*8) = *(const uint4*)(Wsrc + row*64 + c16*8);
    }
    __syncthreads();

    float d[4][4][4];
    #pragma unroll
    for (int i = 0; i < 4; i++)
        #pragma unroll
        for (int j = 0; j < 4; j++)
            #pragma unroll
            for (int k = 0; k < 4; k++) d[i][j][k] = 0.f;

    #pragma unroll 1
    for (int t = 0; t < KT; t++){
        if (t < KT-1){
            if (!side){
                int nrow = h0 + t - 8;
                int slot = (nrow + 12) % 3;
                u32 ok = ((unsigned)nrow < 128u) ? 16u : 0u;
                int crow = nrow < 0 ? 0 : (nrow > 127 ? 127 : nrow);
                const __half* src = g_xt + ((u64)((b*SH + crow)*SW))*NC;
                #pragma unroll
                for (int i = 0; i < 4; i++){
                    int idx = tid + i*256;
                    int w = idx >> 3, c16 = idx & 7;
                    cpa16(xs_b + ((slot*128 + w)*SROW + c16*8)*2,
                          src + (u64)w*NC + c16*8, ok);
                }
            }
            {
                const __half* wsrc = Wsrc + (t+1)*4096;
                u32 wdst = ws_b + (((t+1) & 1)*WSLAB)*2;
                #pragma unroll
                for (int i = 0; i < 2; i++){
                    int idx = tid + i*256;
                    int row = idx >> 3, c16 = idx & 7;
                    cpa16(wdst + (row*SROW + c16*8)*2, wsrc + row*64 + c16*8, 16);
                }
            }
            CPA_COMMIT();
        }
        const __half* Wt = Ws + (t & 1)*WSLAB;
        const __half* xbase = side
            ? Xs + (r*148 + pxq + t)*SROW
            : Xs + (((h0 + t + r + 2) % 3)*128 + pxq)*SROW;
        #pragma unroll
        for (int kc = 0; kc < 4; kc++){
            u32 bf[4][2];
            #pragma unroll
            for (int j = 0; j < 4; j++){
                const u32* bp = (const u32*)(xbase + (j*8 + gid)*SROW + kc*16 + tig*2);
                bf[j][0] = bp[0]; bf[j][1] = bp[4];
            }
            u32 af[4][4];
            #pragma unroll
            for (int i = 0; i < 4; i++){
                const u32* ap0 = (const u32*)(Wt + (i*16 + gid)*SROW + kc*16 + tig*2);
                const u32* ap1 = (const u32*)(Wt + (i*16 + gid + 8)*SROW + kc*16 + tig*2);
                af[i][0] = ap0[0]; af[i][1] = ap1[0];
                af[i][2] = ap0[4]; af[i][3] = ap1[4];
            }
            #pragma unroll
            for (int i = 0; i < 4; i++)
                #pragma unroll
                for (int j = 0; j < 4; j++)
                    mma_f16(d[i][j], af[i], bf[j]);
        }
        if (t < KT-1){
            CPA_WAIT0();
            __syncthreads();
        }
    }

    // ================= Phase 2: fused qkv projection ========================
    float* Ds  = (float*)smem_raw;                 // [64ci][260]
    float* W2s = (float*)(smem_raw + 64*DS_STR*4); // [64ci][68]
    const float* w2   = side ? wqkv_w : hqkv_w;
    const float* bias = side ? wqkv_b : hqkv_b;
    __half* qh = side ? g_wqh : g_hqh;
    __half* ql = side ? g_wql : g_hql;

    __syncthreads();
    #pragma unroll
    for (int i = 0; i < 4; i++){
        #pragma unroll
        for (int half = 0; half < 2; half++){
            int co = i*16 + gid + half*8;
            float rbv = side ? 0.f : g_rbh[co*SH + h0 + r];
            #pragma unroll
            for (int j = 0; j < 4; j++){
                int px = pxq + j*8 + tig*2;
                float vx = d[i][j][half*2 + 0];
                float vy = d[i][j][half*2 + 1];
                if (side){
                    float2 bb = *(const float2*)(g_rbw + co*SW + px);
                    vx += bb.x; vy += bb.y;
                } else { vx += rbv; vy += rbv; }
                *(float2*)&Ds[co*DS_STR + r*128 + px] = make_float2(vx, vy);
            }
        }
    }
    __syncthreads();

    #pragma unroll 1
    for (int og = 0; og < 3; og++){
        if (og) __syncthreads();
        for (int it = tid; it < 4096; it += 256){
            int o = it >> 6, ci = it & 63;
            W2s[ci*W2_STR + o] = w2[og*4096 + it];
        }
        __syncthreads();
        u64 acc2[8][4];
        #pragma unroll
        for (int rr = 0; rr < 8; rr++)
            #pragma unroll
            for (int j = 0; j < 4; j++) acc2[rr][j] = 0ull;
        int tx = lid;
        #pragma unroll 4
        for (int ci = 0; ci < NC; ci++){
            float4 a0 = *(const float4*)(W2s + ci*W2_STR + wid*8);
            float4 a1 = *(const float4*)(W2s + ci*W2_STR + wid*8 + 4);
            float4 x0 = *(const float4*)(Ds + ci*DS_STR + tx*4);
            float4 x1 = *(const float4*)(Ds + ci*DS_STR + tx*4 + 128);
            u64 da[8] = {pack2(a0.x,a0.x), pack2(a0.y,a0.y), pack2(a0.z,a0.z), pack2(a0.w,a0.w),
                         pack2(a1.x,a1.x), pack2(a1.y,a1.y), pack2(a1.z,a1.z), pack2(a1.w,a1.w)};
            u64 xd[4] = {pack2(x0.x,x0.y), pack2(x0.z,x0.w), pack2(x1.x,x1.y), pack2(x1.z,x1.w)};
            #pragma unroll
            for (int rr = 0; rr < 8; rr++)
                #pragma unroll
                for (int j = 0; j < 4; j++)
                    ffma2(acc2[rr][j], da[rr], xd[j]);
        }
        #pragma unroll
        for (int rr = 0; rr < 8; rr++){
            int o = og*64 + wid*8 + rr;
            float bv = bias[o];
            u64 off = (u64)(b*192 + o)*HW + h0*SW + tx*4;
            float2 p0 = unpack2(acc2[rr][0]), p1 = unpack2(acc2[rr][1]);
            float2 p2 = unpack2(acc2[rr][2]), p3 = unpack2(acc2[rr][3]);
            float v0[4] = {p0.x+bv, p0.y+bv, p1.x+bv, p1.y+bv};   // row h0
            float v1[4] = {p2.x+bv, p2.y+bv, p3.x+bv, p3.y+bv};   // row h0+1
            uint2 hi, lo;
            split4(v0, hi, lo);
            *(uint2*)(qh + off) = hi;
            *(uint2*)(ql + off) = lo;
            split4(v1, hi, lo);
            *(uint2*)(qh + off + SW) = hi;
            *(uint2*)(ql + off + SW) = lo;
        }
    }
}

// ---------------- psum: fold 4 P partials -> Ph/Pl fp16 --------------------
__global__ __launch_bounds__(256) void psum_kernel()
{
    int which = blockIdx.y;
    int idx4 = blockIdx.x*256 + threadIdx.x;      // 0..262143
    int pr = idx4 >> 12;                          // pair
    int off = (idx4 & 4095) * 4;
    const float* pb = g_Pp + (u64)((which*64 + pr)*4)*16384;
    float4 p0 = *(const float4*)(pb + off);
    float4 p1 = *(const float4*)(pb + 16384 + off);
    float4 p2 = *(const float4*)(pb + 2*16384 + off);
    float4 p3 = *(const float4*)(pb + 3*16384 + off);
    float s[4] = {p0.x+p1.x+p2.x+p3.x, p0.y+p1.y+p2.y+p3.y,
                  p0.z+p1.z+p2.z+p3.z, p0.w+p1.w+p2.w+p3.w};
    uint2 hi, lo;
    split4(s, hi, lo);
    u64 o = (u64)(which*64 + pr)*16384 + off;
    *(uint2*)(g_Ph + o) = hi;
    *(uint2*)(g_Pl + o) = lo;
}

// ---------------- gemm_p: split-fp16 tensor, P partials --------------------
// C[128 m][128 n] = sum_k q[k][m] v[k][n], K = 256 per block (ks slice).
// Pipeline per iter: wait -> sync -> stage -> commit -> compute (WAR-safe).
#define GP_MAT 2176
#define GP_BUF (4*GP_MAT)
__global__ __launch_bounds__(256, 2) void gemm_p_kernel()
{
    extern __shared__ __half PS[];
    int pair = blockIdx.x, ks = blockIdx.y, which = blockIdx.z;
    int b = pair >> 3, nh = pair & 7;
    const __half* qh = which ? g_wqh : g_hqh;
    const __half* ql = which ? g_wql : g_hql;
    const __half* vh = which ? g_hqh : g_wqh;
    const __half* vl = which ? g_hql : g_wql;
    u64 aoff = (u64)(b*192 + nh*24 + 0 )*HW + (u64)ks*256*SW;
    u64 boff = (u64)(b*192 + nh*24 + 16)*HW + (u64)ks*256*SW;
    int tid = threadIdx.x, lid = tid & 31, wid = tid >> 5;
    int mw = wid >> 1, nw = wid & 1;
    int gid = lid >> 2, tig = lid & 3;

    float d[2][8][4];
    #pragma unroll
    for (int i = 0; i < 2; i++)
        #pragma unroll
        for (int j = 0; j < 8; j++)
            #pragma unroll
            for (int k = 0; k < 4; k++) d[i][j][k] = 0.f;

    int krA = (lid & 7) + ((lid >> 4) << 3);       // A trans: k row
    int mcA = ((lid >> 3) & 1) * 8;                // A trans: m col offset
    int krB = (lid & 7) + ((lid >> 3) & 1) * 8;    // B trans: k row
    int ncB = (lid >> 4) * 8;                      // B trans: n col offset

    #pragma unroll 1
    for (int c = 0; c < 18; c++){
        if (c >= 2){
            if (c <= 16) CPA_WAIT1(); else CPA_WAIT0();
            __syncthreads();
        }
        if (c < 16){
            __half* B0 = PS + (c % 3)*GP_BUF;
            int k0 = c*16;
            #pragma unroll
            for (int i = 0; i < 4; i++){
                int id = tid + i*256;
                int mat = id >> 8, rem = id & 255;
                int kk = rem >> 4, seg = rem & 15;
                const __half* src =
                    (mat == 0 ? qh + aoff : mat == 1 ? ql + aoff :
                     mat == 2 ? vh + boff : vl + boff)
                    + (u64)(k0 + kk)*SW + seg*8;
                cpa16(smem_u32(B0 + mat*GP_MAT + kk*136 + seg*8), src, 16);
            }
            CPA_COMMIT();
        }
        if (c < 2) continue;
        int cc = c - 2;
        u32 base = smem_u32(PS + (cc % 3)*GP_BUF);
        u32 ah[2][4], al[2][4];
        #pragma unroll
        for (int i = 0; i < 2; i++){
            int mb = mw*32 + i*16;
            ldsm_x4t(ah[i][0],ah[i][1],ah[i][2],ah[i][3],
                     base + (0*GP_MAT + krA*136 + mb + mcA)*2);
            ldsm_x4t(al[i][0],al[i][1],al[i][2],al[i][3],
                     base + (1*GP_MAT + krA*136 + mb + mcA)*2);
        }
        #pragma unroll
        for (int jp = 0; jp < 4; jp++){
            int jb = nw*64 + jp*16;
            u32 h0,h1,h2,h3, l0,l1,l2,l3;
            ldsm_x4t(h0,h1,h2,h3, base + (2*GP_MAT + krB*136 + jb + ncB)*2);
            ldsm_x4t(l0,l1,l2,l3, base + (3*GP_MAT + krB*136 + jb + ncB)*2);
            u32 BH[2][2] = {{h0,h1},{h2,h3}};
            u32 BL[2][2] = {{l0,l1},{l2,l3}};
            #pragma unroll
            for (int jj = 0; jj < 2; jj++){
                int j = jp*2 + jj;
                #pragma unroll
                for (int i = 0; i < 2; i++){
                    mma_f16(d[i][j], ah[i], BH[jj]);
                    mma_f16(d[i][j], ah[i], BL[jj]);
                    mma_f16(d[i][j], al[i], BH[jj]);
                }
            }
        }
    }
    float* pp = g_Pp + (u64)((which*64 + pair)*4 + ks)*16384;
    #pragma unroll
    for (int i = 0; i < 2; i++)
        #pragma unroll
        for (int j = 0; j < 8; j++)
            #pragma unroll
            for (int hf = 0; hf < 2; hf++){
                int m = mw*32 + i*16 + gid + hf*8;
                int n = nw*64 + j*8 + tig*2;
                *(float2*)&pp[m*128 + n] =
                    make_float2(d[i][j][hf*2], d[i][j][hf*2+1]);
            }
}

// ---------------- gemm_o: split-fp16 tensor ---------------------------------
// C[128 m(h)][128 n(w)] = sum_t k[m][t] P[t][n], K = 128.
#define GO_A 3072
#define GO_B 2176
#define GO_BUF (2*GO_A + 2*GO_B)
__global__ __launch_bounds__(256, 2) void gemm_o_kernel()
{
    extern __shared__ __half OS[];
    int jt = blockIdx.x, pair = blockIdx.y, which = blockIdx.z;
    int b = pair >> 3, nh = pair & 7;
    const __half* kh = (which ? g_hqh : g_wqh) + (u64)(b*192 + nh*24 + 8 + jt)*HW;
    const __half* kl = (which ? g_hql : g_wql) + (u64)(b*192 + nh*24 + 8 + jt)*HW;
    const __half* ph = g_Ph + (u64)(which*64 + pair)*16384;
    const __half* pl = g_Pl + (u64)(which*64 + pair)*16384;
    float* out = which ? g_ho : g_wo;
    int tid = threadIdx.x, lid = tid & 31, wid = tid >> 5;
    int mw = wid >> 1, nw = wid & 1;
    int gid = lid >> 2, tig = lid & 3;

    float d[2][8][4];
    #pragma unroll
    for (int i = 0; i < 2; i++)
        #pragma unroll
        for (int j = 0; j < 8; j++)
            #pragma unroll
            for (int k = 0; k < 4; k++) d[i][j][k] = 0.f;

    int mrA = (lid & 7) + ((lid >> 3) & 1) * 8;    // A non-trans: m row offset
    int ksA = (lid >> 4) * 8;                      // A non-trans: k col seg
    int krB = (lid & 7) + ((lid >> 3) & 1) * 8;
    int ncB = (lid >> 4) * 8;

    #pragma unroll 1
    for (int c = 0; c < 10; c++){
        if (c >= 2){
            if (c <= 8) CPA_WAIT1(); else CPA_WAIT0();
            __syncthreads();
        }
        if (c < 8){
            __half* B0 = OS + (c % 3)*GO_BUF;
            int t0 = c*16;
            #pragma unroll
            for (int i = 0; i < 4; i++){
                int id = tid + i*256;
                if (id < 512){                     // A: kh/kl
                    int mat = id >> 8, rem = id & 255;
                    int m = rem >> 1, seg = rem & 1;
                    const __half* src = (mat ? kl : kh) + m*128 + t0 + seg*8;
                    cpa16(smem_u32(B0 + mat*GO_A + m*24 + seg*8), src, 16);
                } else {                           // B: Ph/Pl
                    int id2 = id - 512;
                    int mat = id2 >> 8, rem = id2 & 255;
                    int kk = rem >> 4, seg = rem & 15;
                    const __half* src = (mat ? pl : ph) + (t0 + kk)*128 + seg*8;
                    cpa16(smem_u32(B0 + 2*GO_A + mat*GO_B + kk*136 + seg*8), src, 16);
                }
            }
            CPA_COMMIT();
        }
        if (c < 2) continue;
        int cc = c - 2;
        u32 base = smem_u32(OS + (cc % 3)*GO_BUF);
        u32 ah[2][4], al[2][4];
        #pragma unroll
        for (int i = 0; i < 2; i++){
            int mb = mw*32 + i*16;
            ldsm_x4(ah[i][0],ah[i][1],ah[i][2],ah[i][3],
                    base + (0*GO_A + (mb + mrA)*24 + ksA)*2);
            ldsm_x4(al[i][0],al[i][1],al[i][2],al[i][3],
                    base + (1*GO_A + (mb + mrA)*24 + ksA)*2);
        }
        #pragma unroll
        for (int jp = 0; jp < 4; jp++){
            int jb = nw*64 + jp*16;
            u32 h0,h1,h2,h3, l0,l1,l2,l3;
            ldsm_x4t(h0,h1,h2,h3, base + (2*GO_A + 0*GO_B + krB*136 + jb + ncB)*2);
            ldsm_x4t(l0,l1,l2,l3, base + (2*GO_A + 1*GO_B + krB*136 + jb + ncB)*2);
            u32 BH[2][2] = {{h0,h1},{h2,h3}};
            u32 BL[2][2] = {{l0,l1},{l2,l3}};
            #pragma unroll
            for (int jj = 0; jj < 2; jj++){
                int j = jp*2 + jj;
                #pragma unroll
                for (int i = 0; i < 2; i++){
                    mma_f16(d[i][j], ah[i], BH[jj]);
                    mma_f16(d[i][j], ah[i], BL[jj]);
                    mma_f16(d[i][j], al[i], BH[jj]);
                }
            }
        }
    }
    const float scale = 0.707106781186547524f;
    float* ob = out + (u64)(b*NC + nh*8 + jt)*HW;
    #pragma unroll
    for (int i = 0; i < 2; i++)
        #pragma unroll
        for (int j = 0; j < 8; j++)
            #pragma unroll
            for (int hf = 0; hf < 2; hf++){
                int m = mw*32 + i*16 + gid + hf*8;
                int n = nw*64 + j*8 + tig*2;
                *(float2*)&ob[m*SW + n] =
                    make_float2(d[i][j][hf*2]*scale, d[i][j][hf*2+1]*scale);
            }
}

// ---------------- epilogue: out-projections + sigmoid gate (f32x2) ---------
__global__ __launch_bounds__(128) void epi_kernel(const float* __restrict__ x,
    const float* __restrict__ wow, const float* __restrict__ wob,
    const float* __restrict__ how, const float* __restrict__ hob,
    float* __restrict__ out)
{
    extern __shared__ float sm[];
    float* Ws = sm;
    float* Hs = sm + 4352;
    float* Xw = sm + 8704;
    float* Xh = sm + 8704 + 2048;
    int pt = blockIdx.x, b = blockIdx.y;
    int px0 = pt * 128;
    int tid = threadIdx.x, ty = tid >> 4, tx = tid & 15;

    #pragma unroll
    for (int i = 0; i < 32; i++){
        int idx = tid + i*128;
        int o = idx >> 6, ci = idx & 63;
        Ws[ci*68 + o] = wow[idx];
        Hs[ci*68 + o] = how[idx];
    }
    u64 acc2[8][4];
    #pragma unroll
    for (int r = 0; r < 8; r++)
        #pragma unroll
        for (int j = 0; j < 4; j++) acc2[r][j] = 0ull;

    #pragma unroll 1
    for (int kc = 0; kc < 4; kc++){
        if (kc) __syncthreads();
        #pragma unroll
        for (int i = 0; i < 4; i++){
            int idx4 = tid + i*128;
            int ci = idx4 >> 5, p4 = idx4 & 31;
            ((float4*)Xw)[idx4] = *(const float4*)(g_wo + (u64)(b*NC + kc*16 + ci)*HW + px0 + p4*4);
            ((float4*)Xh)[idx4] = *(const float4*)(g_ho + (u64)(b*NC + kc*16 + ci)*HW + px0 + p4*4);
        }
        __syncthreads();
        const float4* Xwq = (const float4*)Xw;
        const float4* Xhq = (const float4*)Xh;
        #pragma unroll 2
        for (int c16 = 0; c16 < 16; c16++){
            int ci = kc*16 + c16;
            float4 aw0 = *(const float4*)(Ws + ci*68 + ty*8);
            float4 aw1 = *(const float4*)(Ws + ci*68 + ty*8 + 4);
            float4 ah0 = *(const float4*)(Hs + ci*68 + ty*8);
            float4 ah1 = *(const float4*)(Hs + ci*68 + ty*8 + 4);
            float4 xw0 = Xwq[c16*32 + tx];
            float4 xw1 = Xwq[c16*32 + tx + 16];
            float4 xh0 = Xhq[c16*32 + tx];
            float4 xh1 = Xhq[c16*32 + tx + 16];
            u64 dw[8] = {pack2(aw0.x,aw0.x), pack2(aw0.y,aw0.y), pack2(aw0.z,aw0.z), pack2(aw0.w,aw0.w),
                         pack2(aw1.x,aw1.x), pack2(aw1.y,aw1.y), pack2(aw1.z,aw1.z), pack2(aw1.w,aw1.w)};
            u64 dh[8] = {pack2(ah0.x,ah0.x), pack2(ah0.y,ah0.y), pack2(ah0.z,ah0.z), pack2(ah0.w,ah0.w),
                         pack2(ah1.x,ah1.x), pack2(ah1.y,ah1.y), pack2(ah1.z,ah1.z), pack2(ah1.w,ah1.w)};
            u64 xwd[4] = {pack2(xw0.x,xw0.y), pack2(xw0.z,xw0.w), pack2(xw1.x,xw1.y), pack2(xw1.z,xw1.w)};
            u64 xhd[4] = {pack2(xh0.x,xh0.y), pack2(xh0.z,xh0.w), pack2(xh1.x,xh1.y), pack2(xh1.z,xh1.w)};
            #pragma unroll
            for (int r = 0; r < 8; r++)
                #pragma unroll
                for (int j = 0; j < 4; j++){
                    ffma2(acc2[r][j], dw[r], xwd[j]);
                    ffma2(acc2[r][j], dh[r], xhd[j]);
                }
        }
    }
    #pragma unroll
    for (int r = 0; r < 8; r++){
        int c = ty*8 + r;
        float bv = wob[c] + hob[c];
        const float* xb = x + (u64)(b*NC + c)*HW + px0;
        float* ob = out + (u64)(b*NC + c)*HW + px0;
        float av[8];
        float2 p0 = unpack2(acc2[r][0]), p1 = unpack2(acc2[r][1]);
        float2 p2 = unpack2(acc2[r][2]), p3 = unpack2(acc2[r][3]);
        av[0]=p0.x; av[1]=p0.y; av[2]=p1.x; av[3]=p1.y;
        av[4]=p2.x; av[5]=p2.y; av[6]=p3.x; av[7]=p3.y;
        #pragma unroll
        for (int half = 0; half < 2; half++){
            float4 xv = *(const float4*)(xb + tx*4 + half*64);
            float vs[4];
            #pragma unroll
            for (int j = 0; j < 4; j++){
                float s = av[half*4 + j] + bv;
                vs[j] = (&xv.x)[j] * (1.f / (1.f + expf(-s)));
            }
            float4 v = {vs[0], vs[1], vs[2], vs[3]};
            *(float4*)(ob + tx*4 + half*64) = v;
        }
    }
}

// ---------------- launch ---------------------------------------------------
extern "C" void kernel_launch(void* const* d_in, const int* in_sizes, int n_in,
                              void* d_out, int out_size)
{
    const float* x = (const float*)d_in[0];
    int i1w[3], i1b[3], i2w[3], i2b[3];
    if (in_sizes[11] == 45056){ // reference-signature order
        i1w[0]=9;  i1w[1]=11; i1w[2]=13;  i1b[0]=10; i1b[1]=12; i1b[2]=14;
        i2w[0]=15; i2w[1]=17; i2w[2]=19;  i2b[0]=16; i2b[1]=18; i2b[2]=20;
    } else {                    // setup_inputs dict order
        i1w[0]=9;  i1w[1]=13; i1w[2]=17;  i1b[0]=10; i1b[1]=14; i1b[2]=18;
        i2w[0]=11; i2w[1]=15; i2w[2]=19;  i2b[0]=12; i2b[1]=16; i2b[2]=20;
    }
    const float* bn1g=(const float*)d_in[1]; const float* bn1b=(const float*)d_in[2];
    const float* bn1m=(const float*)d_in[3]; const float* bn1v=(const float*)d_in[4];
    const float* bn2g=(const float*)d_in[5]; const float* bn2b=(const float*)d_in[6];
    const float* bn2m=(const float*)d_in[7]; const float* bn2v=(const float*)d_in[8];
    const float* hqkvw=(const float*)d_in[21]; const float* hqkvb=(const float*)d_in[22];
    const float* wqkvw=(const float*)d_in[23]; const float* wqkvb=(const float*)d_in[24];
    const float* houtw=(const float*)d_in[25]; const float* houtb=(const float*)d_in[26];
    const float* woutw=(const float*)d_in[27]; const float* woutb=(const float*)d_in[28];

    int sm_conv = 64*DS_STR*4 + 64*W2_STR*4;   // 83968 B
    int sm_gp = 3*GP_BUF*2;                    // 52224 B
    int sm_go = 3*GO_BUF*2;                    // 62976 B
    cudaFuncSetAttribute(conv_fused_kernel, cudaFuncAttributeMaxDynamicSharedMemorySize, sm_conv);
    cudaFuncSetAttribute(gemm_p_kernel, cudaFuncAttributeMaxDynamicSharedMemorySize, sm_gp);
    cudaFuncSetAttribute(gemm_o_kernel, cudaFuncAttributeMaxDynamicSharedMemorySize, sm_go);
    cudaFuncSetAttribute(epi_kernel, cudaFuncAttributeMaxDynamicSharedMemorySize, 64*1024);

    xt_kernel<<<dim3(SH, NB), 256>>>(x);
    prep_kernel<<<NC, 128>>>(0,
        (const float*)d_in[i1w[0]], (const float*)d_in[i1b[0]],
        (const float*)d_in[i1w[1]], (const float*)d_in[i1b[1]],
        (const float*)d_in[i1w[2]], (const float*)d_in[i1b[2]],
        bn1g, bn1b, bn1m, bn1v);
    prep_kernel<<<NC, 128>>>(1,
        (const float*)d_in[i2w[0]], (const float*)d_in[i2b[0]],
        (const float*)d_in[i2w[1]], (const float*)d_in[i2b[1]],
        (const float*)d_in[i2w[2]], (const float*)d_in[i2b[2]],
        bn2g, bn2b, bn2m, bn2v);

    conv_fused_kernel<<<dim3(64, NB, 2), 256, sm_conv>>>(hqkvw, hqkvb, wqkvw, wqkvb);

    gemm_p_kernel<<<dim3(64, 4, 2), 256, sm_gp>>>();
    psum_kernel<<<dim3(1024, 2), 256>>>();
    gemm_o_kernel<<<dim3(8, 64, 2), 256, sm_go>>>();

    epi_kernel<<<dim3(128, NB), 128, (8704 + 4096)*4>>>(x, woutw, woutb, houtw, houtb,
                                                        (float*)d_out);
}

// round 14
// speedup vs baseline: 4.8414x; 1.0929x over previous
#include <cuda_runtime.h>
#include <cuda_fp16.h>

#define NB 8
#define NC 64
#define SH 128
#define SW 128
#define HW (SH*SW)
#define KT 21

typedef unsigned long long u64;
typedef unsigned int u32;

// ---------------- scratch (device globals; no allocations) ----------------
__device__ __align__(16) __half g_Whh[KT*4096];    // fp16 folded W [t][co][ci]
__device__ __align__(16) __half g_Wwh[KT*4096];
__device__ __align__(16) __half g_xt[(u64)NB*SH*SW*NC]; // NHWC fp16 input
__device__ __align__(16) float g_rbh[NC*SH];
__device__ __align__(16) float g_rbw[NC*SW];
__device__ __align__(16) __half g_hqh[(u64)NB*192*HW];  // h-branch qkv hi
__device__ __align__(16) __half g_hql[(u64)NB*192*HW];  // h-branch qkv lo
__device__ __align__(16) __half g_wqh[(u64)NB*192*HW];
__device__ __align__(16) __half g_wql[(u64)NB*192*HW];
__device__ __align__(16) float g_Pp[2*64*4*SW*SW];      // P partials fp32
__device__ __align__(16) __half g_Ph[2*64*SW*SW];       // summed P hi
__device__ __align__(16) __half g_Pl[2*64*SW*SW];       // summed P lo
__device__ __align__(16) float g_wo[NB*NC*HW];
__device__ __align__(16) float g_ho[NB*NC*HW];

// ---------------- fp16 mma / ldmatrix helpers -------------------------------
__device__ __forceinline__ void mma_f16(float* d, const u32* a, const u32* b){
    asm volatile("mma.sync.aligned.m16n8k16.row.col.f32.f16.f16.f32 "
        "{%0,%1,%2,%3}, {%4,%5,%6,%7}, {%8,%9}, {%0,%1,%2,%3};\n"
        : "+f"(d[0]), "+f"(d[1]), "+f"(d[2]), "+f"(d[3])
        : "r"(a[0]), "r"(a[1]), "r"(a[2]), "r"(a[3]), "r"(b[0]), "r"(b[1]));
}
__device__ __forceinline__ void ldsm_x4(u32& r0,u32& r1,u32& r2,u32& r3, u32 addr){
    asm volatile("ldmatrix.sync.aligned.m8n8.x4.shared.b16 {%0,%1,%2,%3}, [%4];"
        : "=r"(r0),"=r"(r1),"=r"(r2),"=r"(r3) : "r"(addr));
}
__device__ __forceinline__ void ldsm_x4t(u32& r0,u32& r1,u32& r2,u32& r3, u32 addr){
    asm volatile("ldmatrix.sync.aligned.m8n8.x4.trans.shared.b16 {%0,%1,%2,%3}, [%4];"
        : "=r"(r0),"=r"(r1),"=r"(r2),"=r"(r3) : "r"(addr));
}

// ---------------- cp.async helpers -----------------------------------------
__device__ __forceinline__ u32 smem_u32(const void* p){
    u32 a; asm("{ .reg .u64 t; cvta.to.shared.u64 t, %1; cvt.u32.u64 %0, t; }"
               : "=r"(a) : "l"(p));
    return a;
}
__device__ __forceinline__ void cpa16(u32 dst, const void* src, u32 srcsize){
    asm volatile("cp.async.cg.shared.global [%0], [%1], 16, %2;"
                 :: "r"(dst), "l"(src), "r"(srcsize) : "memory");
}
#define CPA_COMMIT() asm volatile("cp.async.commit_group;" ::: "memory")
#define CPA_WAIT0()  asm volatile("cp.async.wait_group 0;" ::: "memory")
#define CPA_WAIT1()  asm volatile("cp.async.wait_group 1;" ::: "memory")

// ---------------- f32x2 packed fma helpers (exact fp32 math) ---------------
__device__ __forceinline__ u64 pack2(float x, float y){
    u64 r; asm("mov.b64 %0, {%1,%2};" : "=l"(r) : "f"(x), "f"(y)); return r;
}
__device__ __forceinline__ void ffma2(u64& d, u64 a, u64 b){
    asm("fma.rn.f32x2 %0, %1, %2, %0;" : "+l"(d) : "l"(a), "l"(b));
}
__device__ __forceinline__ float2 unpack2(u64 d){
    float2 f; asm("mov.b64 {%0,%1}, %2;" : "=f"(f.x), "=f"(f.y) : "l"(d)); return f;
}

// split helpers: fp32 -> hi/lo fp16
__device__ __forceinline__ void split2(float x, float y, u32& hi, u32& lo){
    __half hx = __float2half_rn(x), hy = __float2half_rn(y);
    __half lx = __float2half_rn(x - __half2float(hx));
    __half ly = __float2half_rn(y - __half2float(hy));
    __half2 h = {hx, hy}, l = {lx, ly};
    hi = *(u32*)&h; lo = *(u32*)&l;
}
__device__ __forceinline__ void split4(const float* v, uint2& hi, uint2& lo){
    split2(v[0], v[1], hi.x, lo.x);
    split2(v[2], v[3], hi.y, lo.y);
}

// ---------------- x -> NHWC fp16 transpose ---------------------------------
__global__ __launch_bounds__(256) void xt_kernel(const float* __restrict__ x)
{
    __shared__ __half T[NC*132];
    int h = blockIdx.x, b = blockIdx.y;
    int tid = threadIdx.x;
    #pragma unroll
    for (int i = 0; i < 8; i++){
        int idx4 = tid + i*256;
        int ci = idx4 >> 5, w4 = idx4 & 31;
        float4 v = *(const float4*)(x + (u64)(b*NC + ci)*HW + h*SW + w4*4);
        T[ci*132 + w4*4 + 0] = __float2half_rn(v.x);
        T[ci*132 + w4*4 + 1] = __float2half_rn(v.y);
        T[ci*132 + w4*4 + 2] = __float2half_rn(v.z);
        T[ci*132 + w4*4 + 3] = __float2half_rn(v.w);
    }
    __syncthreads();
    #pragma unroll
    for (int i = 0; i < 4; i++){
        int oct = tid + i*256;
        int w = oct >> 3, c8 = oct & 7;
        u32 rr[4];
        #pragma unroll
        for (int j = 0; j < 4; j++){
            __half2 hv;
            hv.x = T[(c8*8 + 2*j)*132 + w];
            hv.y = T[(c8*8 + 2*j + 1)*132 + w];
            rr[j] = *(u32*)&hv;
        }
        *(uint4*)(g_xt + ((u64)((b*SH + h)*SW + w))*NC + c8*8) =
            make_uint4(rr[0], rr[1], rr[2], rr[3]);
    }
}

// ---------------- prep: combine strip kernels, fold BN, fp16 W, biases -----
__global__ void prep_kernel(int side,
    const float* __restrict__ w7,  const float* __restrict__ b7,
    const float* __restrict__ w11, const float* __restrict__ b11,
    const float* __restrict__ w21, const float* __restrict__ b21,
    const float* __restrict__ bng, const float* __restrict__ bnb,
    const float* __restrict__ bnm, const float* __restrict__ bnv)
{
    __half* Wout = side ? g_Wwh : g_Whh;
    float* rbout = side ? g_rbw : g_rbh;
    int co = blockIdx.x;
    int tid = threadIdx.x;
    __shared__ float Wraw[NC*KT];
    __shared__ float Pfx[NC*(KT+1)];

    for (int idx = tid; idx < NC*KT; idx += blockDim.x){
        int ci = idx / KT, t = idx % KT;
        float v = w21[(co*NC+ci)*21 + t];
        if (t >= 5 && t < 16) v += w11[(co*NC+ci)*11 + (t-5)];
        if (t >= 7 && t < 14) v += w7 [(co*NC+ci)*7  + (t-7)];
        Wraw[idx] = v;
        float a = bng[ci] * rsqrtf(bnv[ci] + 1e-5f);
        Wout[t*4096 + co*64 + ci] = __float2half_rn(v * a);
    }
    __syncthreads();
    if (tid < NC){
        int ci = tid;
        float a = bng[ci] * rsqrtf(bnv[ci] + 1e-5f);
        float c = bnb[ci] - bnm[ci] * a;
        float s = 0.f;
        Pfx[ci*(KT+1)] = 0.f;
        for (int t = 0; t < KT; t++){
            s += Wraw[ci*KT + t] * c;
            Pfx[ci*(KT+1) + t + 1] = s;
        }
    }
    __syncthreads();
    float cb = b7[co] + b11[co] + b21[co];
    for (int h = tid; h < SH; h += blockDim.x){
        int t0 = 10 - h;  if (t0 < 0) t0 = 0;
        int t1 = 137 - h; if (t1 > KT-1) t1 = KT-1;
        float s = cb;
        for (int ci = 0; ci < NC; ci++)
            s += Pfx[ci*(KT+1) + t1 + 1] - Pfx[ci*(KT+1) + t0];
        rbout[co*SH + h] = s;
    }
}

// ======== fused conv (fp16 mma) + qkv projection (split-fp16 mma) ===========
// Phase 2 smem: Dh/Dl [64ci][264] + W2h/W2l [64o][72]  (86016 B peak)
#define SROW 72
#define WSLAB (64*SROW)
#define DP_STR 264
#define WP_STR 72

__global__ __launch_bounds__(256, 2) void conv_fused_kernel(
    const float* __restrict__ hqkv_w, const float* __restrict__ hqkv_b,
    const float* __restrict__ wqkv_w, const float* __restrict__ wqkv_b)
{
    extern __shared__ char smem_raw[];
    __half* Xs = (__half*)smem_raw;            // 384 rows x 72 halves
    __half* Ws = Xs + 384*SROW;                // 2 W slabs
    int h0 = blockIdx.x * 2, b = blockIdx.y;
    int side = blockIdx.z;
    int tid = threadIdx.x;
    int wid = tid >> 5, lid = tid & 31;
    int gid = lid >> 2, tig = lid & 3;
    int r = wid >> 2, pxq = (wid & 3) * 32;
    u32 xs_b = smem_u32(Xs);
    u32 ws_b = smem_u32(Ws);

    const __half* Wsrc = side ? g_Wwh : g_Whh;
    if (side){
        for (int i = tid; i < 296*8; i += 256){
            int row = i >> 3, c16 = i & 7;
            int rr = (row >= 148), wp = row - rr*148 - 10;
            uint4 v = make_uint4(0,0,0,0);
            if ((unsigned)wp < 128u)
                v = *(const uint4*)(g_xt + ((u64)((b*SH + h0 + rr)*SW + wp))*NC + c16*8);
            *(uint4*)(Xs + row*SROW + c16*8) = v;
        }
    } else {
        #pragma unroll
        for (int s = 0; s < 2; s++){
            int hp = h0 - 10 + s;
            int slot = (hp + 12) % 3;
            for (int i = tid; i < 128*8; i += 256){
                int w = i >> 3, c16 = i & 7;
                uint4 v = make_uint4(0,0,0,0);
                if ((unsigned)hp < 128u)
                    v = *(const uint4*)(g_xt + ((u64)((b*SH + hp)*SW + w))*NC + c16*8);
                *(uint4*)(Xs + (slot*128 + w)*SROW + c16*8) = v;
            }
        }
    }
    for (int i = tid; i < 512; i += 256){
        int row = i >> 3, c16 = i & 7;
        *(uint4*)(Ws + row*SROW + c16*8) = *(const uint4*)(Wsrc + row*64 + c16*8);
    }
    __syncthreads();

    float d[4][4][4];
    #pragma unroll
    for (int i = 0; i < 4; i++)
        #pragma unroll
        for (int j = 0; j < 4; j++)
            #pragma unroll
            for (int k = 0; k < 4; k++) d[i][j][k] = 0.f;

    #pragma unroll 1
    for (int t = 0; t < KT; t++){
        if (t < KT-1){
            if (!side){
                int nrow = h0 + t - 8;
                int slot = (nrow + 12) % 3;
                u32 ok = ((unsigned)nrow < 128u) ? 16u : 0u;
                int crow = nrow < 0 ? 0 : (nrow > 127 ? 127 : nrow);
                const __half* src = g_xt + ((u64)((b*SH + crow)*SW))*NC;
                #pragma unroll
                for (int i = 0; i < 4; i++){
                    int idx = tid + i*256;
                    int w = idx >> 3, c16 = idx & 7;
                    cpa16(xs_b + ((slot*128 + w)*SROW + c16*8)*2,
                          src + (u64)w*NC + c16*8, ok);
                }
            }
            {
                const __half* wsrc = Wsrc + (t+1)*4096;
                u32 wdst = ws_b + (((t+1) & 1)*WSLAB)*2;
                #pragma unroll
                for (int i = 0; i < 2; i++){
                    int idx = tid + i*256;
                    int row = idx >> 3, c16 = idx & 7;
                    cpa16(wdst + (row*SROW + c16*8)*2, wsrc + row*64 + c16*8, 16);
                }
            }
            CPA_COMMIT();
        }
        const __half* Wt = Ws + (t & 1)*WSLAB;
        const __half* xbase = side
            ? Xs + (r*148 + pxq + t)*SROW
            : Xs + (((h0 + t + r + 2) % 3)*128 + pxq)*SROW;
        #pragma unroll
        for (int kc = 0; kc < 4; kc++){
            u32 bf[4][2];
            #pragma unroll
            for (int j = 0; j < 4; j++){
                const u32* bp = (const u32*)(xbase + (j*8 + gid)*SROW + kc*16 + tig*2);
                bf[j][0] = bp[0]; bf[j][1] = bp[4];
            }
            u32 af[4][4];
            #pragma unroll
            for (int i = 0; i < 4; i++){
                const u32* ap0 = (const u32*)(Wt + (i*16 + gid)*SROW + kc*16 + tig*2);
                const u32* ap1 = (const u32*)(Wt + (i*16 + gid + 8)*SROW + kc*16 + tig*2);
                af[i][0] = ap0[0]; af[i][1] = ap1[0];
                af[i][2] = ap0[4]; af[i][3] = ap1[4];
            }
            #pragma unroll
            for (int i = 0; i < 4; i++)
                #pragma unroll
                for (int j = 0; j < 4; j++)
                    mma_f16(d[i][j], af[i], bf[j]);
        }
        if (t < KT-1){
            CPA_WAIT0();
            __syncthreads();
        }
    }

    // ====== Phase 2: qkv projection via split-fp16 mma ======================
    __half* Dh  = (__half*)smem_raw;           // [64 ci][264]
    __half* Dl  = Dh + 64*DP_STR;
    __half* W2h = Dl + 64*DP_STR;              // [64 o][72]
    __half* W2l = W2h + 64*WP_STR;
    const float* w2   = side ? wqkv_w : hqkv_w;
    const float* bias = side ? wqkv_b : hqkv_b;
    __half* qh = side ? g_wqh : g_hqh;
    __half* ql = side ? g_wql : g_hql;

    __syncthreads();   // conv smem reads done
    // stage conv result D + rb as hi/lo fp16
    #pragma unroll
    for (int i = 0; i < 4; i++){
        #pragma unroll
        for (int half = 0; half < 2; half++){
            int co = i*16 + gid + half*8;
            float rbv = side ? 0.f : g_rbh[co*SH + h0 + r];
            #pragma unroll
            for (int j = 0; j < 4; j++){
                int px256 = r*128 + pxq + j*8 + tig*2;
                float vx = d[i][j][half*2 + 0];
                float vy = d[i][j][half*2 + 1];
                if (side){
                    float2 bb = *(const float2*)(g_rbw + co*SW + ((pxq + j*8 + tig*2)));
                    vx += bb.x; vy += bb.y;
                } else { vx += rbv; vy += rbv; }
                u32 hi, lo;
                split2(vx, vy, hi, lo);
                *(u32*)&Dh[co*DP_STR + px256] = hi;
                *(u32*)&Dl[co*DP_STR + px256] = lo;
            }
        }
    }
    __syncthreads();

    // projection warp layout: mw = o-half (32), nw = px-quarter (64)
    int mw = wid & 1, nw = wid >> 1;
    int mrA = (lid & 7) + ((lid >> 3) & 1) * 8;    // A non-trans row offset
    int ksA = (lid >> 4) * 8;                      // A non-trans k seg
    int krB = (lid & 7) + ((lid >> 3) & 1) * 8;    // B trans k row
    int ncB = (lid >> 4) * 8;                      // B trans n col offset
    u32 dh_b = smem_u32(Dh), dl_b = smem_u32(Dl);
    u32 w2h_b = smem_u32(W2h), w2l_b = smem_u32(W2l);

    #pragma unroll 1
    for (int og = 0; og < 3; og++){
        if (og) __syncthreads();          // prior og's W2 readers done
        for (int it = tid; it < 4096; it += 256){
            int o = it >> 6, ci = it & 63;
            float w = w2[og*4096 + it];
            __half hh = __float2half_rn(w);
            W2h[o*WP_STR + ci] = hh;
            W2l[o*WP_STR + ci] = __float2half_rn(w - __half2float(hh));
        }
        __syncthreads();
        float dd[2][8][4];
        #pragma unroll
        for (int i = 0; i < 2; i++)
            #pragma unroll
            for (int j = 0; j < 8; j++)
                #pragma unroll
                for (int k = 0; k < 4; k++) dd[i][j][k] = 0.f;
        #pragma unroll
        for (int kc = 0; kc < 4; kc++){
            u32 ah[2][4], al2[2][4];
            #pragma unroll
            for (int i = 0; i < 2; i++){
                int mb = mw*32 + i*16;
                ldsm_x4(ah[i][0],ah[i][1],ah[i][2],ah[i][3],
                        w2h_b + ((mb + mrA)*WP_STR + kc*16 + ksA)*2);
                ldsm_x4(al2[i][0],al2[i][1],al2[i][2],al2[i][3],
                        w2l_b + ((mb + mrA)*WP_STR + kc*16 + ksA)*2);
            }
            #pragma unroll
            for (int jp = 0; jp < 4; jp++){
                int jb = nw*64 + jp*16;
                u32 h0r,h1r,h2r,h3r, l0r,l1r,l2r,l3r;
                ldsm_x4t(h0r,h1r,h2r,h3r, dh_b + ((kc*16 + krB)*DP_STR + jb + ncB)*2);
                ldsm_x4t(l0r,l1r,l2r,l3r, dl_b + ((kc*16 + krB)*DP_STR + jb + ncB)*2);
                u32 BH[2][2] = {{h0r,h1r},{h2r,h3r}};
                u32 BL[2][2] = {{l0r,l1r},{l2r,l3r}};
                #pragma unroll
                for (int jj = 0; jj < 2; jj++){
                    int j = jp*2 + jj;
                    #pragma unroll
                    for (int i = 0; i < 2; i++){
                        mma_f16(dd[i][j], ah[i], BH[jj]);
                        mma_f16(dd[i][j], ah[i], BL[jj]);
                        mma_f16(dd[i][j], al2[i], BH[jj]);
                    }
                }
            }
        }
        // epilogue: bias + split -> global hi/lo
        #pragma unroll
        for (int i = 0; i < 2; i++){
            #pragma unroll
            for (int hf = 0; hf < 2; hf++){
                int o = og*64 + mw*32 + i*16 + gid + hf*8;
                float bv = bias[o];
                u64 obase = (u64)(b*192 + o)*HW;
                #pragma unroll
                for (int j = 0; j < 8; j++){
                    int px256 = nw*64 + j*8 + tig*2;
                    int r2 = px256 >> 7, px = px256 & 127;
                    float vx = dd[i][j][hf*2 + 0] + bv;
                    float vy = dd[i][j][hf*2 + 1] + bv;
                    u32 hi, lo;
                    split2(vx, vy, hi, lo);
                    u64 off = obase + (u64)(h0 + r2)*SW + px;
                    *(u32*)(qh + off) = hi;
                    *(u32*)(ql + off) = lo;
                }
            }
        }
    }
}

// ---------------- psum: fold 4 P partials -> Ph/Pl fp16 --------------------
__global__ __launch_bounds__(256) void psum_kernel()
{
    int which = blockIdx.y;
    int idx4 = blockIdx.x*256 + threadIdx.x;      // 0..262143
    int pr = idx4 >> 12;                          // pair
    int off = (idx4 & 4095) * 4;
    const float* pb = g_Pp + (u64)((which*64 + pr)*4)*16384;
    float4 p0 = *(const float4*)(pb + off);
    float4 p1 = *(const float4*)(pb + 16384 + off);
    float4 p2 = *(const float4*)(pb + 2*16384 + off);
    float4 p3 = *(const float4*)(pb + 3*16384 + off);
    float s[4] = {p0.x+p1.x+p2.x+p3.x, p0.y+p1.y+p2.y+p3.y,
                  p0.z+p1.z+p2.z+p3.z, p0.w+p1.w+p2.w+p3.w};
    uint2 hi, lo;
    split4(s, hi, lo);
    u64 o = (u64)(which*64 + pr)*16384 + off;
    *(uint2*)(g_Ph + o) = hi;
    *(uint2*)(g_Pl + o) = lo;
}

// ---------------- gemm_p: split-fp16 tensor, P partials --------------------
#define GP_MAT 2176
#define GP_BUF (4*GP_MAT)
__global__ __launch_bounds__(256, 2) void gemm_p_kernel()
{
    extern __shared__ __half PS[];
    int pair = blockIdx.x, ks = blockIdx.y, which = blockIdx.z;
    int b = pair >> 3, nh = pair & 7;
    const __half* qh = which ? g_wqh : g_hqh;
    const __half* ql = which ? g_wql : g_hql;
    const __half* vh = which ? g_hqh : g_wqh;
    const __half* vl = which ? g_hql : g_wql;
    u64 aoff = (u64)(b*192 + nh*24 + 0 )*HW + (u64)ks*256*SW;
    u64 boff = (u64)(b*192 + nh*24 + 16)*HW + (u64)ks*256*SW;
    int tid = threadIdx.x, lid = tid & 31, wid = tid >> 5;
    int mw = wid >> 1, nw = wid & 1;
    int gid = lid >> 2, tig = lid & 3;

    float d[2][8][4];
    #pragma unroll
    for (int i = 0; i < 2; i++)
        #pragma unroll
        for (int j = 0; j < 8; j++)
            #pragma unroll
            for (int k = 0; k < 4; k++) d[i][j][k] = 0.f;

    int krA = (lid & 7) + ((lid >> 4) << 3);
    int mcA = ((lid >> 3) & 1) * 8;
    int krB = (lid & 7) + ((lid >> 3) & 1) * 8;
    int ncB = (lid >> 4) * 8;

    #pragma unroll 1
    for (int c = 0; c < 18; c++){
        if (c >= 2){
            if (c <= 16) CPA_WAIT1(); else CPA_WAIT0();
            __syncthreads();
        }
        if (c < 16){
            __half* B0 = PS + (c % 3)*GP_BUF;
            int k0 = c*16;
            #pragma unroll
            for (int i = 0; i < 4; i++){
                int id = tid + i*256;
                int mat = id >> 8, rem = id & 255;
                int kk = rem >> 4, seg = rem & 15;
                const __half* src =
                    (mat == 0 ? qh + aoff : mat == 1 ? ql + aoff :
                     mat == 2 ? vh + boff : vl + boff)
                    + (u64)(k0 + kk)*SW + seg*8;
                cpa16(smem_u32(B0 + mat*GP_MAT + kk*136 + seg*8), src, 16);
            }
            CPA_COMMIT();
        }
        if (c < 2) continue;
        int cc = c - 2;
        u32 base = smem_u32(PS + (cc % 3)*GP_BUF);
        u32 ah[2][4], al[2][4];
        #pragma unroll
        for (int i = 0; i < 2; i++){
            int mb = mw*32 + i*16;
            ldsm_x4t(ah[i][0],ah[i][1],ah[i][2],ah[i][3],
                     base + (0*GP_MAT + krA*136 + mb + mcA)*2);
            ldsm_x4t(al[i][0],al[i][1],al[i][2],al[i][3],
                     base + (1*GP_MAT + krA*136 + mb + mcA)*2);
        }
        #pragma unroll
        for (int jp = 0; jp < 4; jp++){
            int jb = nw*64 + jp*16;
            u32 h0,h1,h2,h3, l0,l1,l2,l3;
            ldsm_x4t(h0,h1,h2,h3, base + (2*GP_MAT + krB*136 + jb + ncB)*2);
            ldsm_x4t(l0,l1,l2,l3, base + (3*GP_MAT + krB*136 + jb + ncB)*2);
            u32 BH[2][2] = {{h0,h1},{h2,h3}};
            u32 BL[2][2] = {{l0,l1},{l2,l3}};
            #pragma unroll
            for (int jj = 0; jj < 2; jj++){
                int j = jp*2 + jj;
                #pragma unroll
                for (int i = 0; i < 2; i++){
                    mma_f16(d[i][j], ah[i], BH[jj]);
                    mma_f16(d[i][j], ah[i], BL[jj]);
                    mma_f16(d[i][j], al[i], BH[jj]);
                }
            }
        }
    }
    float* pp = g_Pp + (u64)((which*64 + pair)*4 + ks)*16384;
    #pragma unroll
    for (int i = 0; i < 2; i++)
        #pragma unroll
        for (int j = 0; j < 8; j++)
            #pragma unroll
            for (int hf = 0; hf < 2; hf++){
                int m = mw*32 + i*16 + gid + hf*8;
                int n = nw*64 + j*8 + tig*2;
                *(float2*)&pp[m*128 + n] =
                    make_float2(d[i][j][hf*2], d[i][j][hf*2+1]);
            }
}

// ---------------- gemm_o: split-fp16 tensor ---------------------------------
#define GO_A 3072
#define GO_B 2176
#define GO_BUF (2*GO_A + 2*GO_B)
__global__ __launch_bounds__(256, 2) void gemm_o_kernel()
{
    extern __shared__ __half OS[];
    int jt = blockIdx.x, pair = blockIdx.y, which = blockIdx.z;
    int b = pair >> 3, nh = pair & 7;
    const __half* kh = (which ? g_hqh : g_wqh) + (u64)(b*192 + nh*24 + 8 + jt)*HW;
    const __half* kl = (which ? g_hql : g_wql) + (u64)(b*192 + nh*24 + 8 + jt)*HW;
    const __half* ph = g_Ph + (u64)(which*64 + pair)*16384;
    const __half* pl = g_Pl + (u64)(which*64 + pair)*16384;
    float* out = which ? g_ho : g_wo;
    int tid = threadIdx.x, lid = tid & 31, wid = tid >> 5;
    int mw = wid >> 1, nw = wid & 1;
    int gid = lid >> 2, tig = lid & 3;

    float d[2][8][4];
    #pragma unroll
    for (int i = 0; i < 2; i++)
        #pragma unroll
        for (int j = 0; j < 8; j++)
            #pragma unroll
            for (int k = 0; k < 4; k++) d[i][j][k] = 0.f;

    int mrA = (lid & 7) + ((lid >> 3) & 1) * 8;
    int ksA = (lid >> 4) * 8;
    int krB = (lid & 7) + ((lid >> 3) & 1) * 8;
    int ncB = (lid >> 4) * 8;

    #pragma unroll 1
    for (int c = 0; c < 10; c++){
        if (c >= 2){
            if (c <= 8) CPA_WAIT1(); else CPA_WAIT0();
            __syncthreads();
        }
        if (c < 8){
            __half* B0 = OS + (c % 3)*GO_BUF;
            int t0 = c*16;
            #pragma unroll
            for (int i = 0; i < 4; i++){
                int id = tid + i*256;
                if (id < 512){
                    int mat = id >> 8, rem = id & 255;
                    int m = rem >> 1, seg = rem & 1;
                    const __half* src = (mat ? kl : kh) + m*128 + t0 + seg*8;
                    cpa16(smem_u32(B0 + mat*GO_A + m*24 + seg*8), src, 16);
                } else {
                    int id2 = id - 512;
                    int mat = id2 >> 8, rem = id2 & 255;
                    int kk = rem >> 4, seg = rem & 15;
                    const __half* src = (mat ? pl : ph) + (t0 + kk)*128 + seg*8;
                    cpa16(smem_u32(B0 + 2*GO_A + mat*GO_B + kk*136 + seg*8), src, 16);
                }
            }
            CPA_COMMIT();
        }
        if (c < 2) continue;
        int cc = c - 2;
        u32 base = smem_u32(OS + (cc % 3)*GO_BUF);
        u32 ah[2][4], al[2][4];
        #pragma unroll
        for (int i = 0; i < 2; i++){
            int mb = mw*32 + i*16;
            ldsm_x4(ah[i][0],ah[i][1],ah[i][2],ah[i][3],
                    base + (0*GO_A + (mb + mrA)*24 + ksA)*2);
            ldsm_x4(al[i][0],al[i][1],al[i][2],al[i][3],
                    base + (1*GO_A + (mb + mrA)*24 + ksA)*2);
        }
        #pragma unroll
        for (int jp = 0; jp < 4; jp++){
            int jb = nw*64 + jp*16;
            u32 h0,h1,h2,h3, l0,l1,l2,l3;
            ldsm_x4t(h0,h1,h2,h3, base + (2*GO_A + 0*GO_B + krB*136 + jb + ncB)*2);
            ldsm_x4t(l0,l1,l2,l3, base + (2*GO_A + 1*GO_B + krB*136 + jb + ncB)*2);
            u32 BH[2][2] = {{h0,h1},{h2,h3}};
            u32 BL[2][2] = {{l0,l1},{l2,l3}};
            #pragma unroll
            for (int jj = 0; jj < 2; jj++){
                int j = jp*2 + jj;
                #pragma unroll
                for (int i = 0; i < 2; i++){
                    mma_f16(d[i][j], ah[i], BH[jj]);
                    mma_f16(d[i][j], ah[i], BL[jj]);
                    mma_f16(d[i][j], al[i], BH[jj]);
                }
            }
        }
    }
    const float scale = 0.707106781186547524f;
    float* ob = out + (u64)(b*NC + nh*8 + jt)*HW;
    #pragma unroll
    for (int i = 0; i < 2; i++)
        #pragma unroll
        for (int j = 0; j < 8; j++)
            #pragma unroll
            for (int hf = 0; hf < 2; hf++){
                int m = mw*32 + i*16 + gid + hf*8;
                int n = nw*64 + j*8 + tig*2;
                *(float2*)&ob[m*SW + n] =
                    make_float2(d[i][j][hf*2]*scale, d[i][j][hf*2+1]*scale);
            }
}

// ---------------- epilogue: out-projections + sigmoid gate (f32x2) ---------
__global__ __launch_bounds__(128) void epi_kernel(const float* __restrict__ x,
    const float* __restrict__ wow, const float* __restrict__ wob,
    const float* __restrict__ how, const float* __restrict__ hob,
    float* __restrict__ out)
{
    extern __shared__ float sm[];
    float* Ws = sm;
    float* Hs = sm + 4352;
    float* Xw = sm + 8704;
    float* Xh = sm + 8704 + 2048;
    int pt = blockIdx.x, b = blockIdx.y;
    int px0 = pt * 128;
    int tid = threadIdx.x, ty = tid >> 4, tx = tid & 15;

    #pragma unroll
    for (int i = 0; i < 32; i++){
        int idx = tid + i*128;
        int o = idx >> 6, ci = idx & 63;
        Ws[ci*68 + o] = wow[idx];
        Hs[ci*68 + o] = how[idx];
    }
    u64 acc2[8][4];
    #pragma unroll
    for (int r = 0; r < 8; r++)
        #pragma unroll
        for (int j = 0; j < 4; j++) acc2[r][j] = 0ull;

    #pragma unroll 1
    for (int kc = 0; kc < 4; kc++){
        if (kc) __syncthreads();
        #pragma unroll
        for (int i = 0; i < 4; i++){
            int idx4 = tid + i*128;
            int ci = idx4 >> 5, p4 = idx4 & 31;
            ((float4*)Xw)[idx4] = *(const float4*)(g_wo + (u64)(b*NC + kc*16 + ci)*HW + px0 + p4*4);
            ((float4*)Xh)[idx4] = *(const float4*)(g_ho + (u64)(b*NC + kc*16 + ci)*HW + px0 + p4*4);
        }
        __syncthreads();
        const float4* Xwq = (const float4*)Xw;
        const float4* Xhq = (const float4*)Xh;
        #pragma unroll 2
        for (int c16 = 0; c16 < 16; c16++){
            int ci = kc*16 + c16;
            float4 aw0 = *(const float4*)(Ws + ci*68 + ty*8);
            float4 aw1 = *(const float4*)(Ws + ci*68 + ty*8 + 4);
            float4 ah0 = *(const float4*)(Hs + ci*68 + ty*8);
            float4 ah1 = *(const float4*)(Hs + ci*68 + ty*8 + 4);
            float4 xw0 = Xwq[c16*32 + tx];
            float4 xw1 = Xwq[c16*32 + tx + 16];
            float4 xh0 = Xhq[c16*32 + tx];
            float4 xh1 = Xhq[c16*32 + tx + 16];
            u64 dw[8] = {pack2(aw0.x,aw0.x), pack2(aw0.y,aw0.y), pack2(aw0.z,aw0.z), pack2(aw0.w,aw0.w),
                         pack2(aw1.x,aw1.x), pack2(aw1.y,aw1.y), pack2(aw1.z,aw1.z), pack2(aw1.w,aw1.w)};
            u64 dh[8] = {pack2(ah0.x,ah0.x), pack2(ah0.y,ah0.y), pack2(ah0.z,ah0.z), pack2(ah0.w,ah0.w),
                         pack2(ah1.x,ah1.x), pack2(ah1.y,ah1.y), pack2(ah1.z,ah1.z), pack2(ah1.w,ah1.w)};
            u64 xwd[4] = {pack2(xw0.x,xw0.y), pack2(xw0.z,xw0.w), pack2(xw1.x,xw1.y), pack2(xw1.z,xw1.w)};
            u64 xhd[4] = {pack2(xh0.x,xh0.y), pack2(xh0.z,xh0.w), pack2(xh1.x,xh1.y), pack2(xh1.z,xh1.w)};
            #pragma unroll
            for (int r = 0; r < 8; r++)
                #pragma unroll
                for (int j = 0; j < 4; j++){
                    ffma2(acc2[r][j], dw[r], xwd[j]);
                    ffma2(acc2[r][j], dh[r], xhd[j]);
                }
        }
    }
    #pragma unroll
    for (int r = 0; r < 8; r++){
        int c = ty*8 + r;
        float bv = wob[c] + hob[c];
        const float* xb = x + (u64)(b*NC + c)*HW + px0;
        float* ob = out + (u64)(b*NC + c)*HW + px0;
        float av[8];
        float2 p0 = unpack2(acc2[r][0]), p1 = unpack2(acc2[r][1]);
        float2 p2 = unpack2(acc2[r][2]), p3 = unpack2(acc2[r][3]);
        av[0]=p0.x; av[1]=p0.y; av[2]=p1.x; av[3]=p1.y;
        av[4]=p2.x; av[5]=p2.y; av[6]=p3.x; av[7]=p3.y;
        #pragma unroll
        for (int half = 0; half < 2; half++){
            float4 xv = *(const float4*)(xb + tx*4 + half*64);
            float vs[4];
            #pragma unroll
            for (int j = 0; j < 4; j++){
                float s = av[half*4 + j] + bv;
                vs[j] = (&xv.x)[j] * (1.f / (1.f + expf(-s)));
            }
            float4 v = {vs[0], vs[1], vs[2], vs[3]};
            *(float4*)(ob + tx*4 + half*64) = v;
        }
    }
}

// ---------------- launch ---------------------------------------------------
extern "C" void kernel_launch(void* const* d_in, const int* in_sizes, int n_in,
                              void* d_out, int out_size)
{
    const float* x = (const float*)d_in[0];
    int i1w[3], i1b[3], i2w[3], i2b[3];
    if (in_sizes[11] == 45056){ // reference-signature order
        i1w[0]=9;  i1w[1]=11; i1w[2]=13;  i1b[0]=10; i1b[1]=12; i1b[2]=14;
        i2w[0]=15; i2w[1]=17; i2w[2]=19;  i2b[0]=16; i2b[1]=18; i2b[2]=20;
    } else {                    // setup_inputs dict order
        i1w[0]=9;  i1w[1]=13; i1w[2]=17;  i1b[0]=10; i1b[1]=14; i1b[2]=18;
        i2w[0]=11; i2w[1]=15; i2w[2]=19;  i2b[0]=12; i2b[1]=16; i2b[2]=20;
    }
    const float* bn1g=(const float*)d_in[1]; const float* bn1b=(const float*)d_in[2];
    const float* bn1m=(const float*)d_in[3]; const float* bn1v=(const float*)d_in[4];
    const float* bn2g=(const float*)d_in[5]; const float* bn2b=(const float*)d_in[6];
    const float* bn2m=(const float*)d_in[7]; const float* bn2v=(const float*)d_in[8];
    const float* hqkvw=(const float*)d_in[21]; const float* hqkvb=(const float*)d_in[22];
    const float* wqkvw=(const float*)d_in[23]; const float* wqkvb=(const float*)d_in[24];
    const float* houtw=(const float*)d_in[25]; const float* houtb=(const float*)d_in[26];
    const float* woutw=(const float*)d_in[27]; const float* woutb=(const float*)d_in[28];

    int sm_conv = (2*64*DP_STR + 2*64*WP_STR) * 2;   // 86016 B (covers phase1's 73728)
    int sm_gp = 3*GP_BUF*2;                    // 52224 B
    int sm_go = 3*GO_BUF*2;                    // 62976 B
    cudaFuncSetAttribute(conv_fused_kernel, cudaFuncAttributeMaxDynamicSharedMemorySize, sm_conv);
    cudaFuncSetAttribute(gemm_p_kernel, cudaFuncAttributeMaxDynamicSharedMemorySize, sm_gp);
    cudaFuncSetAttribute(gemm_o_kernel, cudaFuncAttributeMaxDynamicSharedMemorySize, sm_go);
    cudaFuncSetAttribute(epi_kernel, cudaFuncAttributeMaxDynamicSharedMemorySize, 64*1024);

    xt_kernel<<<dim3(SH, NB), 256>>>(x);
    prep_kernel<<<NC, 128>>>(0,
        (const float*)d_in[i1w[0]], (const float*)d_in[i1b[0]],
        (const float*)d_in[i1w[1]], (const float*)d_in[i1b[1]],
        (const float*)d_in[i1w[2]], (const float*)d_in[i1b[2]],
        bn1g, bn1b, bn1m, bn1v);
    prep_kernel<<<NC, 128>>>(1,
        (const float*)d_in[i2w[0]], (const float*)d_in[i2b[0]],
        (const float*)d_in[i2w[1]], (const float*)d_in[i2b[1]],
        (const float*)d_in[i2w[2]], (const float*)d_in[i2b[2]],
        bn2g, bn2b, bn2m, bn2v);

    conv_fused_kernel<<<dim3(64, NB, 2), 256, sm_conv>>>(hqkvw, hqkvb, wqkvw, wqkvb);

    gemm_p_kernel<<<dim3(64, 4, 2), 256, sm_gp>>>();
    psum_kernel<<<dim3(1024, 2), 256>>>();
    gemm_o_kernel<<<dim3(8, 64, 2), 256, sm_go>>>();

    epi_kernel<<<dim3(128, NB), 128, (8704 + 4096)*4>>>(x, woutw, woutb, houtw, houtb,
                                                        (float*)d_out);
}